// round 3
// baseline (speedup 1.0000x reference)
#include <cuda_runtime.h>
#include <math.h>

// ---------------------------------------------------------------------------
// Problem constants
// ---------------------------------------------------------------------------
constexpr int    Nn = 1024;
constexpr int    Bb = 16;
constexpr int    Tt = 12;
constexpr int    Ff = 8;
constexpr int    Hh = 64;
constexpr int    Ee = 32768;
constexpr size_t NS = (size_t)Nn * (Bb * Hh);   // 1M floats per plane

// ---------------------------------------------------------------------------
// Scratch arena: 80 planes + small vectors (static device memory, no allocs)
// ---------------------------------------------------------------------------
constexpr size_t O_ADJF  = 0;
constexpr size_t O_ADJB  = 1 * NS;
constexpr size_t O_XENC  = 2 * NS;    // 12 planes
constexpr size_t O_XF1   = 14 * NS;   // 12
constexpr size_t O_XF2   = 26 * NS;   // 12
constexpr size_t O_XB1   = 38 * NS;   // 12
constexpr size_t O_XB2   = 50 * NS;   // 12
constexpr size_t O_H     = 62 * NS;
constexpr size_t O_HHOP  = 63 * NS;   // 4: [HF1, HF2, HB1, HB2]
constexpr size_t O_RH    = 67 * NS;
constexpr size_t O_RHHOP = 68 * NS;   // 4
constexpr size_t O_R     = 72 * NS;
constexpr size_t O_U     = 73 * NS;
constexpr size_t O_C     = 74 * NS;
constexpr size_t O_F1    = 75 * NS;
constexpr size_t O_F2    = 76 * NS;
constexpr size_t O_B1    = 77 * NS;
constexpr size_t O_B2    = 78 * NS;
constexpr size_t O_Z     = 79 * NS;
constexpr size_t O_RSUM  = 80 * NS;          // 1024
constexpr size_t O_CSUM  = 80 * NS + 1024;   // 1024
constexpr size_t O_INVF  = 80 * NS + 2048;   // 1024
constexpr size_t O_INVB  = 80 * NS + 3072;   // 1024
constexpr size_t F_TOT   = 80 * NS + 4096;

__device__ float g_f[F_TOT];

// ---------------------------------------------------------------------------
// Adjacency normalization
// ---------------------------------------------------------------------------
__global__ void k_rowsum(const float* __restrict__ adj) {
    const int i = blockIdx.x;
    __shared__ float sm[256];
    float a = 0.f;
    for (int j = threadIdx.x; j < 1024; j += 256) a += adj[(size_t)i * 1024 + j];
    sm[threadIdx.x] = a; __syncthreads();
    for (int s = 128; s > 0; s >>= 1) {
        if (threadIdx.x < s) sm[threadIdx.x] += sm[threadIdx.x + s];
        __syncthreads();
    }
    if (threadIdx.x == 0) g_f[O_RSUM + i] = sm[0];
}

__global__ void k_colsum(const float* __restrict__ adj) {
    const int j = blockIdx.x * 256 + threadIdx.x;
    float a = 0.f;
    for (int i = 0; i < 1024; i++) a += adj[(size_t)i * 1024 + j];
    g_f[O_CSUM + j] = a;
}

// adj_fwd[i][j] = adj[i][j]/rowsum[i];  adj_bwd[i][j] = adj[j][i]/colsum[i]
__global__ void k_norm(const float* __restrict__ adj) {
    const size_t idx = (size_t)blockIdx.x * 256 + threadIdx.x;
    const int i = (int)(idx >> 10), j = (int)(idx & 1023);
    g_f[O_ADJF + idx] = adj[idx] / g_f[O_RSUM + i];
    g_f[O_ADJB + idx] = adj[(size_t)j * 1024 + i] / g_f[O_CSUM + i];
}

// ---------------------------------------------------------------------------
// Encoder: xenc[t][n][b*64+h] = x[b,t,n,:] @ W_enc + b_enc[h] + emb[n][h]
// ---------------------------------------------------------------------------
__global__ void k_encoder(const float* __restrict__ x, const float* __restrict__ W,
                          const float* __restrict__ bias, const float* __restrict__ emb) {
    __shared__ float xs[16][8];
    __shared__ float Ws[8][64];
    const int n = blockIdx.x, t = blockIdx.y, tid = threadIdx.x;
    if (tid < 128) {
        const int b = tid >> 3, f = tid & 7;
        xs[b][f] = x[((size_t)(b * Tt + t) * Nn + n) * Ff + f];
    }
    {
        const int i0 = tid, i1 = tid + 256;
        Ws[i0 >> 6][i0 & 63] = W[i0];
        Ws[i1 >> 6][i1 & 63] = W[i1];
    }
    __syncthreads();
    const int h = tid & 63, bq = tid >> 6;
    const float base = bias[h] + emb[(size_t)n * 64 + h];
    float* o = g_f + O_XENC + (size_t)t * NS + (size_t)n * 1024;
#pragma unroll
    for (int i = 0; i < 4; i++) {
        const int b = bq * 4 + i;
        float acc = base;
#pragma unroll
        for (int f = 0; f < 8; f++) acc += xs[b][f] * Ws[f][h];
        o[b * 64 + h] = acc;
    }
}

// ---------------------------------------------------------------------------
// Dense hop GEMM: C(z) = A(z) @ X(z); A,X,C all [1024,1024] fp32 in g_f.
// Tile 128(m) x 64(n), BK=16, 256 threads, 8x4 accum per thread.
// selA: if set, z odd picks oA1 (fwd/bwd support pairs).
// ---------------------------------------------------------------------------
__global__ void __launch_bounds__(256) k_gemm(size_t oA0, size_t oA1, size_t oX,
                                              size_t xstr, size_t oC, size_t cstr, int selA) {
    __shared__ float As[16][128];
    __shared__ float Bs[16][64];
    const int z = blockIdx.z;
    const float* __restrict__ A = g_f + ((selA && (z & 1)) ? oA1 : oA0);
    const float* __restrict__ X = g_f + oX + (size_t)z * xstr;
    float* __restrict__ C       = g_f + oC + (size_t)z * cstr;
    const int m0 = blockIdx.y * 128, n0 = blockIdx.x * 64;
    const int tid = threadIdx.x;
    const int tx = tid & 15, ty = tid >> 4;
    const int ar = tid >> 1, ak = (tid & 1) * 8;
    const int br = tid >> 4, bc = (tid & 15) * 4;
    float acc[8][4] = {};
    const float* Arow = A + (size_t)(m0 + ar) * 1024;
    for (int k0 = 0; k0 < 1024; k0 += 16) {
        const float4 a0 = *(const float4*)(Arow + k0 + ak);
        const float4 a1 = *(const float4*)(Arow + k0 + ak + 4);
        const float4 bv = *(const float4*)(X + (size_t)(k0 + br) * 1024 + n0 + bc);
        __syncthreads();
        As[ak + 0][ar] = a0.x; As[ak + 1][ar] = a0.y; As[ak + 2][ar] = a0.z; As[ak + 3][ar] = a0.w;
        As[ak + 4][ar] = a1.x; As[ak + 5][ar] = a1.y; As[ak + 6][ar] = a1.z; As[ak + 7][ar] = a1.w;
        *(float4*)&Bs[br][bc] = bv;
        __syncthreads();
#pragma unroll
        for (int kk = 0; kk < 16; kk++) {
            const float4 av0 = *(const float4*)&As[kk][ty * 8];
            const float4 av1 = *(const float4*)&As[kk][ty * 8 + 4];
            const float4 wv  = *(const float4*)&Bs[kk][tx * 4];
            const float aa[8] = {av0.x, av0.y, av0.z, av0.w, av1.x, av1.y, av1.z, av1.w};
            const float ww[4] = {wv.x, wv.y, wv.z, wv.w};
#pragma unroll
            for (int i = 0; i < 8; i++)
#pragma unroll
                for (int j = 0; j < 4; j++) acc[i][j] += aa[i] * ww[j];
        }
    }
#pragma unroll
    for (int i = 0; i < 8; i++) {
        const float4 o = make_float4(acc[i][0], acc[i][1], acc[i][2], acc[i][3]);
        *(float4*)(C + (size_t)(m0 + ty * 8 + i) * 1024 + n0 + tx * 4) = o;
    }
}

// ---------------------------------------------------------------------------
// Gate gather-GEMM: rows g=n*16+b (16384), feature k in [0, nch*64) read from
// chunk plane ch.o[k/64] at offset n*1024 + b*64 + (k%64). out[g][h], 64 cols.
// Optionally computes a second gate (two=1) sharing the A operand.
// act: 0=none, 1=sigmoid, 2=tanh
// ---------------------------------------------------------------------------
struct COffs { size_t o[8]; };

__device__ __forceinline__ float act_fn(float v, int act) {
    if (act == 1) return 1.0f / (1.0f + expf(-v));
    if (act == 2) return tanhf(v);
    return v;
}

__global__ void __launch_bounds__(256) k_gate(COffs ch, int nch,
        const float* __restrict__ W0, const float* __restrict__ b0,
        const float* __restrict__ W1, const float* __restrict__ b1,
        size_t oOut0, size_t oOut1, int act, int two) {
    __shared__ float As[64][17];
    __shared__ float Ws0[16][68];
    __shared__ float Ws1[16][68];
    const int tid = threadIdx.x;
    const int g0 = blockIdx.x * 64;
    const int tx = tid & 15, ty = tid >> 4;
    const int ar = tid >> 2, kq = (tid & 3) * 4;
    const int g = g0 + ar;
    const size_t abase = (size_t)(g >> 4) * 1024 + (size_t)(g & 15) * 64;
    const int wr = tid >> 4, wc = (tid & 15) * 4;
    float acc0[4][4] = {};
    float acc1[4][4] = {};
    const int K = nch * 64;
    for (int k0 = 0; k0 < K; k0 += 16) {
        const float4 av = *(const float4*)(g_f + ch.o[k0 >> 6] + abase + (k0 & 63) + kq);
        const float4 w0 = *(const float4*)(W0 + (size_t)(k0 + wr) * 64 + wc);
        float4 w1 = make_float4(0.f, 0.f, 0.f, 0.f);
        if (two) w1 = *(const float4*)(W1 + (size_t)(k0 + wr) * 64 + wc);
        __syncthreads();
        As[ar][kq + 0] = av.x; As[ar][kq + 1] = av.y; As[ar][kq + 2] = av.z; As[ar][kq + 3] = av.w;
        *(float4*)&Ws0[wr][wc] = w0;
        if (two) *(float4*)&Ws1[wr][wc] = w1;
        __syncthreads();
#pragma unroll
        for (int kk = 0; kk < 16; kk++) {
            float a[4];
#pragma unroll
            for (int i = 0; i < 4; i++) a[i] = As[ty * 4 + i][kk];
            const float4 v0 = *(const float4*)&Ws0[kk][tx * 4];
            const float w0a[4] = {v0.x, v0.y, v0.z, v0.w};
#pragma unroll
            for (int i = 0; i < 4; i++)
#pragma unroll
                for (int j = 0; j < 4; j++) acc0[i][j] += a[i] * w0a[j];
            if (two) {
                const float4 v1 = *(const float4*)&Ws1[kk][tx * 4];
                const float w1a[4] = {v1.x, v1.y, v1.z, v1.w};
#pragma unroll
                for (int i = 0; i < 4; i++)
#pragma unroll
                    for (int j = 0; j < 4; j++) acc1[i][j] += a[i] * w1a[j];
            }
        }
    }
#pragma unroll
    for (int i = 0; i < 4; i++) {
        const int row = g0 + ty * 4 + i;
        float4 o0;
        float* p0 = (float*)&o0;
#pragma unroll
        for (int j = 0; j < 4; j++) p0[j] = act_fn(acc0[i][j] + b0[tx * 4 + j], act);
        *(float4*)(g_f + oOut0 + (size_t)row * 64 + tx * 4) = o0;
        if (two) {
            float4 o1;
            float* p1 = (float*)&o1;
#pragma unroll
            for (int j = 0; j < 4; j++) p1[j] = act_fn(acc1[i][j] + b1[tx * 4 + j], act);
            *(float4*)(g_f + oOut1 + (size_t)row * 64 + tx * 4) = o1;
        }
    }
}

// ---------------------------------------------------------------------------
// Elementwise
// ---------------------------------------------------------------------------
__global__ void k_zero(size_t o) {
    g_f[o + (size_t)blockIdx.x * 256 + threadIdx.x] = 0.f;
}
__global__ void k_mul(size_t oA, size_t oB, size_t oOut) {
    const size_t i = (size_t)blockIdx.x * 256 + threadIdx.x;
    g_f[oOut + i] = g_f[oA + i] * g_f[oB + i];
}
__global__ void k_hup() {
    const size_t i = (size_t)blockIdx.x * 256 + threadIdx.x;
    const float u = g_f[O_U + i], h = g_f[O_H + i], c = g_f[O_C + i];
    g_f[O_H + i] = u * h + (1.f - u) * c;
}

// ---------------------------------------------------------------------------
// Sparse DiffConv: deg normalization + deterministic per-node gather
// ---------------------------------------------------------------------------
__global__ void k_deg(const int* __restrict__ sel, const float* __restrict__ w, size_t oInv) {
    const int n = blockIdx.x, tid = threadIdx.x;
    __shared__ float sm[256];
    float a = 0.f;
    for (int e = tid; e < Ee; e += 256) if (sel[e] == n) a += w[e];
    sm[tid] = a; __syncthreads();
    for (int s = 128; s > 0; s >>= 1) {
        if (tid < s) sm[tid] += sm[tid + s];
        __syncthreads();
    }
    if (tid == 0) { const float d = sm[0]; g_f[oInv + n] = d > 0.f ? 1.f / d : 0.f; }
}

// out[n][:] = inv[n] * sum_{e: sel[e]==n} in[oth[e]][:] * w[e]   (deterministic order)
__global__ void __launch_bounds__(256) k_gather(const int* __restrict__ sel,
        const int* __restrict__ oth, const float* __restrict__ w,
        size_t oInv, size_t oIn, size_t oOut) {
    const int n = blockIdx.x, tid = threadIdx.x;
    __shared__ int   cnts[257];
    __shared__ int   s_o[2048];
    __shared__ float s_w[2048];
    int c0 = 0;
    for (int e = tid; e < Ee; e += 256) c0 += (sel[e] == n);
    cnts[tid + 1] = c0;
    if (tid == 0) cnts[0] = 0;
    __syncthreads();
    if (tid == 0) { int a = 0; for (int i = 1; i <= 256; i++) { a += cnts[i]; cnts[i] = a; } }
    __syncthreads();
    int off = cnts[tid];
    for (int e = tid; e < Ee; e += 256)
        if (sel[e] == n) { if (off < 2048) { s_o[off] = oth[e]; s_w[off] = w[e]; } off++; }
    __syncthreads();
    int M = cnts[256]; if (M > 2048) M = 2048;
    const float inv = g_f[oInv + n];
    const float4* in4 = (const float4*)(g_f + oIn);
    float4 acc = make_float4(0.f, 0.f, 0.f, 0.f);
    for (int m = 0; m < M; m++) {
        const float wm = s_w[m];
        const float4 v = in4[(size_t)s_o[m] * 256 + tid];
        acc.x += v.x * wm; acc.y += v.y * wm; acc.z += v.z * wm; acc.w += v.w * wm;
    }
    acc.x *= inv; acc.y *= inv; acc.z *= inv; acc.w *= inv;
    ((float4*)(g_f + oOut + (size_t)n * 1024))[tid] = acc;
}

// ---------------------------------------------------------------------------
// Decoder: out[b,t,n,f] = z[g=n*16+b][:] @ W_dec[:, t*8+f] + b_dec
// ---------------------------------------------------------------------------
__global__ void k_dec(const float* __restrict__ Wd, const float* __restrict__ bd,
                      float* __restrict__ out) {
    __shared__ float zs[64];
    const int g = blockIdx.x, c = threadIdx.x;   // 96 threads
    if (c < 64) zs[c] = g_f[O_Z + (size_t)g * 64 + c];
    __syncthreads();
    float a = bd[c];
#pragma unroll
    for (int h = 0; h < 64; h++) a += zs[h] * Wd[h * 96 + c];
    const int b = g & 15, n = g >> 4, t = c >> 3, f = c & 7;
    out[(((size_t)b * 12 + t) * 1024 + n) * 8 + f] = a;
}

// ---------------------------------------------------------------------------
// Launcher
// ---------------------------------------------------------------------------
extern "C" void kernel_launch(void* const* d_in, const int* in_sizes, int n_in,
                              void* d_out, int out_size) {
    const float* x      = (const float*)d_in[0];
    const int*   ei     = (const int*)d_in[1];
    const float* ew     = (const float*)d_in[2];
    const float* adj    = (const float*)d_in[3];
    const float* W_enc  = (const float*)d_in[4];
    const float* b_enc  = (const float*)d_in[5];
    const float* emb    = (const float*)d_in[6];
    const float* W_r    = (const float*)d_in[7];
    const float* b_r    = (const float*)d_in[8];
    const float* W_u    = (const float*)d_in[9];
    const float* b_u    = (const float*)d_in[10];
    const float* W_c    = (const float*)d_in[11];
    const float* b_c    = (const float*)d_in[12];
    const float* W_diff = (const float*)d_in[13];
    const float* b_diff = (const float*)d_in[14];
    const float* W_dec  = (const float*)d_in[15];
    const float* b_dec  = (const float*)d_in[16];
    float* out = (float*)d_out;
    const int* src = ei;
    const int* dst = ei + Ee;

    // supports + encoder
    k_rowsum<<<1024, 256>>>(adj);
    k_colsum<<<4, 256>>>(adj);
    k_norm<<<4096, 256>>>(adj);
    k_encoder<<<dim3(1024, 12), 256>>>(x, W_enc, b_enc, emb);

    // precompute xt hops for all t (batched z=12)
    const dim3 g12(16, 8, 12);
    k_gemm<<<g12, 256>>>(O_ADJF, O_ADJF, O_XENC, NS, O_XF1, NS, 0);
    k_gemm<<<g12, 256>>>(O_ADJB, O_ADJB, O_XENC, NS, O_XB1, NS, 0);
    k_gemm<<<g12, 256>>>(O_ADJF, O_ADJF, O_XF1, NS, O_XF2, NS, 0);
    k_gemm<<<g12, 256>>>(O_ADJB, O_ADJB, O_XB1, NS, O_XB2, NS, 0);

    // GRU scan
    k_zero<<<4096, 256>>>(O_H);
    const dim3 g2(16, 8, 2);
    for (int t = 0; t < 12; t++) {
        // h hops: hop1 -> [HF1, HB1], hop2 -> [HF2, HB2]
        k_gemm<<<g2, 256>>>(O_ADJF, O_ADJB, O_H, 0, O_HHOP, 2 * NS, 1);
        k_gemm<<<g2, 256>>>(O_ADJF, O_ADJB, O_HHOP, 2 * NS, O_HHOP + NS, 2 * NS, 1);
        COffs cg;
        cg.o[0] = O_XF1 + (size_t)t * NS; cg.o[1] = O_HHOP;
        cg.o[2] = O_XF2 + (size_t)t * NS; cg.o[3] = O_HHOP + NS;
        cg.o[4] = O_XB1 + (size_t)t * NS; cg.o[5] = O_HHOP + 2 * NS;
        cg.o[6] = O_XB2 + (size_t)t * NS; cg.o[7] = O_HHOP + 3 * NS;
        k_gate<<<256, 256>>>(cg, 8, W_r, b_r, W_u, b_u, O_R, O_U, 1, 1);
        k_mul<<<4096, 256>>>(O_R, O_H, O_RH);
        k_gemm<<<g2, 256>>>(O_ADJF, O_ADJB, O_RH, 0, O_RHHOP, 2 * NS, 1);
        k_gemm<<<g2, 256>>>(O_ADJF, O_ADJB, O_RHHOP, 2 * NS, O_RHHOP + NS, 2 * NS, 1);
        COffs cc = cg;
        cc.o[1] = O_RHHOP;          cc.o[3] = O_RHHOP + NS;
        cc.o[5] = O_RHHOP + 2 * NS; cc.o[7] = O_RHHOP + 3 * NS;
        k_gate<<<256, 256>>>(cc, 8, W_c, b_c, W_c, b_c, O_C, O_C, 2, 0);
        k_hup<<<4096, 256>>>();
    }

    // sparse DiffConv readout
    k_deg<<<1024, 256>>>(dst, ew, O_INVF);
    k_deg<<<1024, 256>>>(src, ew, O_INVB);
    k_gather<<<1024, 256>>>(dst, src, ew, O_INVF, O_H, O_F1);
    k_gather<<<1024, 256>>>(dst, src, ew, O_INVF, O_F1, O_F2);
    k_gather<<<1024, 256>>>(src, dst, ew, O_INVB, O_H, O_B1);
    k_gather<<<1024, 256>>>(src, dst, ew, O_INVB, O_B1, O_B2);
    COffs cz;
    cz.o[0] = O_H; cz.o[1] = O_F1; cz.o[2] = O_F2; cz.o[3] = O_B1; cz.o[4] = O_B2;
    cz.o[5] = cz.o[6] = cz.o[7] = O_H;
    k_gate<<<256, 256>>>(cz, 5, W_diff, b_diff, W_diff, b_diff, O_Z, O_Z, 0, 0);

    // decoder
    k_dec<<<16384, 96>>>(W_dec, b_dec, out);
}

// round 9
// speedup vs baseline: 1.0117x; 1.0117x over previous
#include <cuda_runtime.h>
#include <math.h>

typedef unsigned long long u64;

// ---------------------------------------------------------------------------
// Problem constants
// ---------------------------------------------------------------------------
constexpr int    Nn = 1024;
constexpr int    Bb = 16;
constexpr int    Tt = 12;
constexpr int    Ff = 8;
constexpr int    Ee = 32768;
constexpr size_t NS = (size_t)Nn * (Bb * 64);   // 1M floats per plane

// ---------------------------------------------------------------------------
// Scratch arena (static device memory, no allocations anywhere)
// ---------------------------------------------------------------------------
constexpr size_t O_ADJF  = 0;
constexpr size_t O_ADJB  = 1 * NS;
constexpr size_t O_XENC  = 2 * NS;    // 12 planes
constexpr size_t O_XF1   = 14 * NS;   // 12
constexpr size_t O_XF2   = 26 * NS;   // 12
constexpr size_t O_XB1   = 38 * NS;   // 12
constexpr size_t O_XB2   = 50 * NS;   // 12
constexpr size_t O_H     = 62 * NS;
constexpr size_t O_HHOP  = 63 * NS;   // 4: [HF1, HF2, HB1, HB2]
constexpr size_t O_RH    = 67 * NS;
constexpr size_t O_RHHOP = 68 * NS;   // 4
constexpr size_t O_U     = 72 * NS;
constexpr size_t O_F1    = 73 * NS;
constexpr size_t O_F2    = 74 * NS;
constexpr size_t O_B1    = 75 * NS;
constexpr size_t O_B2    = 76 * NS;
constexpr size_t O_Z     = 77 * NS;
constexpr size_t O_RSUM  = 78 * NS;          // 1024
constexpr size_t O_CSUM  = 78 * NS + 1024;   // 1024
constexpr size_t F_TOT   = 78 * NS + 2048;

__device__ float g_f[F_TOT];

// ---------------------------------------------------------------------------
// f32x2 helpers (SASS FFMA2 — 2x fp32 FMA per instruction, exact fp32 numerics)
// ---------------------------------------------------------------------------
__device__ __forceinline__ u64 pack2(float x) {
    u64 r;
    asm("mov.b64 %0, {%1, %1};" : "=l"(r) : "r"(__float_as_uint(x)));
    return r;
}
__device__ __forceinline__ void ffma2(u64& c, u64 a, u64 b) {
    asm("fma.rn.f32x2 %0, %1, %2, %0;" : "+l"(c) : "l"(a), "l"(b));
}
__device__ __forceinline__ float2 up2(u64 v) {
    float2 f;
    unsigned lo, hi;
    asm("mov.b64 {%0, %1}, %2;" : "=r"(lo), "=r"(hi) : "l"(v));
    f.x = __uint_as_float(lo); f.y = __uint_as_float(hi);
    return f;
}

// ---------------------------------------------------------------------------
// Adjacency normalization
// ---------------------------------------------------------------------------
__global__ void k_rowsum(const float* __restrict__ adj) {
    const int i = blockIdx.x;
    __shared__ float sm[256];
    float a = 0.f;
    for (int j = threadIdx.x; j < 1024; j += 256) a += adj[(size_t)i * 1024 + j];
    sm[threadIdx.x] = a; __syncthreads();
    for (int s = 128; s > 0; s >>= 1) {
        if (threadIdx.x < s) sm[threadIdx.x] += sm[threadIdx.x + s];
        __syncthreads();
    }
    if (threadIdx.x == 0) g_f[O_RSUM + i] = sm[0];
}

__global__ void k_colsum(const float* __restrict__ adj) {
    const int j = blockIdx.x * 256 + threadIdx.x;
    float a = 0.f;
    for (int i = 0; i < 1024; i++) a += adj[(size_t)i * 1024 + j];
    g_f[O_CSUM + j] = a;
}

__global__ void k_norm(const float* __restrict__ adj) {
    const size_t idx = (size_t)blockIdx.x * 256 + threadIdx.x;
    const int i = (int)(idx >> 10), j = (int)(idx & 1023);
    g_f[O_ADJF + idx] = adj[idx] / g_f[O_RSUM + i];
    g_f[O_ADJB + idx] = adj[(size_t)j * 1024 + i] / g_f[O_CSUM + i];
}

// ---------------------------------------------------------------------------
// Encoder: xenc[t][n][b*64+h] = x[b,t,n,:] @ W_enc + b_enc[h] + emb[n][h]
// ---------------------------------------------------------------------------
__global__ void k_encoder(const float* __restrict__ x, const float* __restrict__ W,
                          const float* __restrict__ bias, const float* __restrict__ emb) {
    __shared__ float xs[16][8];
    __shared__ float Ws[8][64];
    const int n = blockIdx.x, t = blockIdx.y, tid = threadIdx.x;
    if (tid < 128) {
        const int b = tid >> 3, f = tid & 7;
        xs[b][f] = x[((size_t)(b * Tt + t) * Nn + n) * Ff + f];
    }
    {
        const int i0 = tid, i1 = tid + 256;
        Ws[i0 >> 6][i0 & 63] = W[i0];
        Ws[i1 >> 6][i1 & 63] = W[i1];
    }
    __syncthreads();
    const int h = tid & 63, bq = tid >> 6;
    const float base = bias[h] + emb[(size_t)n * 64 + h];
    float* o = g_f + O_XENC + (size_t)t * NS + (size_t)n * 1024;
#pragma unroll
    for (int i = 0; i < 4; i++) {
        const int b = bq * 4 + i;
        float acc = base;
#pragma unroll
        for (int f = 0; f < 8; f++) acc += xs[b][f] * Ws[f][h];
        o[b * 64 + h] = acc;
    }
}

// ---------------------------------------------------------------------------
// Dense hop GEMM (FFMA2): C(z) = A(z) @ X(z); all [1024,1024] fp32 in g_f.
// Tile 128(m) x 128(n), BK=16, 256 threads, 8x8 per thread (4 m-pairs x 8 n).
// selA: z odd picks oA1 (fwd/bwd support pairs).
// ---------------------------------------------------------------------------
__global__ void __launch_bounds__(256, 2) k_gemm(size_t oA0, size_t oA1, size_t oX,
                                                 size_t xstr, size_t oC, size_t cstr, int selA) {
    __shared__ float As[16][132];    // transposed: As[k][m]
    __shared__ float Bs[16][128];
    const int z = blockIdx.z;
    const float* __restrict__ A = g_f + ((selA && (z & 1)) ? oA1 : oA0);
    const float* __restrict__ X = g_f + oX + (size_t)z * xstr;
    float* __restrict__ C       = g_f + oC + (size_t)z * cstr;
    const int m0 = blockIdx.y * 128, n0 = blockIdx.x * 128;
    const int tid = threadIdx.x;
    const int tx = tid & 15, ty = tid >> 4;
    const int ar = tid >> 1, ak = (tid & 1) * 8;      // A: row, k-offset (2x float4)
    const int br = tid >> 4, bc = (tid & 15) * 4;     // B: k-row, col (2 float4: bc, bc+64)
    u64 acc[4][8];
#pragma unroll
    for (int i = 0; i < 4; i++)
#pragma unroll
        for (int j = 0; j < 8; j++) acc[i][j] = 0ULL;
    const float* Arow = A + (size_t)(m0 + ar) * 1024;
    for (int k0 = 0; k0 < 1024; k0 += 16) {
        const float4 a0 = *(const float4*)(Arow + k0 + ak);
        const float4 a1 = *(const float4*)(Arow + k0 + ak + 4);
        const float4 b0 = *(const float4*)(X + (size_t)(k0 + br) * 1024 + n0 + bc);
        const float4 b1 = *(const float4*)(X + (size_t)(k0 + br) * 1024 + n0 + bc + 64);
        __syncthreads();
        As[ak + 0][ar] = a0.x; As[ak + 1][ar] = a0.y; As[ak + 2][ar] = a0.z; As[ak + 3][ar] = a0.w;
        As[ak + 4][ar] = a1.x; As[ak + 5][ar] = a1.y; As[ak + 6][ar] = a1.z; As[ak + 7][ar] = a1.w;
        *(float4*)&Bs[br][bc] = b0;
        *(float4*)&Bs[br][bc + 64] = b1;
        __syncthreads();
#pragma unroll
        for (int kk = 0; kk < 16; kk++) {
            const float4 av0 = *(const float4*)&As[kk][ty * 8];
            const float4 av1 = *(const float4*)&As[kk][ty * 8 + 4];
            const float4 bv0 = *(const float4*)&Bs[kk][tx * 8];
            const float4 bv1 = *(const float4*)&Bs[kk][tx * 8 + 4];
            u64 ap[4];
            ap[0] = ((const u64*)&av0)[0]; ap[1] = ((const u64*)&av0)[1];
            ap[2] = ((const u64*)&av1)[0]; ap[3] = ((const u64*)&av1)[1];
            u64 bb[8];
            bb[0] = pack2(bv0.x); bb[1] = pack2(bv0.y); bb[2] = pack2(bv0.z); bb[3] = pack2(bv0.w);
            bb[4] = pack2(bv1.x); bb[5] = pack2(bv1.y); bb[6] = pack2(bv1.z); bb[7] = pack2(bv1.w);
#pragma unroll
            for (int i = 0; i < 4; i++)
#pragma unroll
                for (int j = 0; j < 8; j++) ffma2(acc[i][j], ap[i], bb[j]);
        }
    }
#pragma unroll
    for (int i = 0; i < 4; i++) {
        float r0[8], r1[8];
#pragma unroll
        for (int j = 0; j < 8; j++) { const float2 v = up2(acc[i][j]); r0[j] = v.x; r1[j] = v.y; }
        const int row0 = m0 + ty * 8 + 2 * i;
        float* p0 = C + (size_t)row0 * 1024 + n0 + tx * 8;
        float* p1 = p0 + 1024;
        *(float4*)p0       = make_float4(r0[0], r0[1], r0[2], r0[3]);
        *(float4*)(p0 + 4) = make_float4(r0[4], r0[5], r0[6], r0[7]);
        *(float4*)p1       = make_float4(r1[0], r1[1], r1[2], r1[3]);
        *(float4*)(p1 + 4) = make_float4(r1[4], r1[5], r1[6], r1[7]);
    }
}

// ---------------------------------------------------------------------------
// Gate gather-GEMM (FFMA2) + fused epilogues.
// Rows g = n*16+b (16384); feature k in [0, nch*64) read from chunk plane
// ch.o[k/64] at offset g*64 + (k%64). Planes are [16384, 64] row-major.
// mode 0: out0 = pre0 + b0                          (DiffConv readout)
// mode 1: r=sig(pre0), u=sig(pre1): out0=r*h, out1=u  (fused k_mul)
// mode 2: c=tanh(pre0): h = u*h + (1-u)*c in place    (fused k_hup)
// ---------------------------------------------------------------------------
struct COffs { size_t o[8]; };

__global__ void __launch_bounds__(256) k_gate(COffs ch, int nch,
        const float* __restrict__ W0, const float* __restrict__ b0,
        const float* __restrict__ W1, const float* __restrict__ b1,
        size_t oOut0, size_t oOut1, int mode, int two) {
    __shared__ float As[64][17];
    __shared__ float Ws0[16][68];
    __shared__ float Ws1[16][68];
    const int tid = threadIdx.x;
    const int g0 = blockIdx.x * 64;
    const int tx = tid & 15, ty = tid >> 4;
    const int ar = tid >> 2, kq = (tid & 3) * 4;
    const size_t abase = (size_t)(g0 + ar) * 64;
    const int wr = tid >> 4, wc = (tid & 15) * 4;
    u64 acc0[4][2], acc1[4][2];
#pragma unroll
    for (int i = 0; i < 4; i++) { acc0[i][0] = acc0[i][1] = 0ULL; acc1[i][0] = acc1[i][1] = 0ULL; }
    const int K = nch * 64;
    for (int k0 = 0; k0 < K; k0 += 16) {
        const float4 av = *(const float4*)(g_f + ch.o[k0 >> 6] + abase + (k0 & 63) + kq);
        const float4 w0 = *(const float4*)(W0 + (size_t)(k0 + wr) * 64 + wc);
        float4 w1 = make_float4(0.f, 0.f, 0.f, 0.f);
        if (two) w1 = *(const float4*)(W1 + (size_t)(k0 + wr) * 64 + wc);
        __syncthreads();
        As[ar][kq + 0] = av.x; As[ar][kq + 1] = av.y; As[ar][kq + 2] = av.z; As[ar][kq + 3] = av.w;
        *(float4*)&Ws0[wr][wc] = w0;
        if (two) *(float4*)&Ws1[wr][wc] = w1;
        __syncthreads();
#pragma unroll
        for (int kk = 0; kk < 16; kk++) {
            u64 ap[4];
#pragma unroll
            for (int i = 0; i < 4; i++) ap[i] = pack2(As[ty * 4 + i][kk]);
            const float4 v0 = *(const float4*)&Ws0[kk][tx * 4];
            const u64 wp0 = ((const u64*)&v0)[0], wp1 = ((const u64*)&v0)[1];
#pragma unroll
            for (int i = 0; i < 4; i++) { ffma2(acc0[i][0], ap[i], wp0); ffma2(acc0[i][1], ap[i], wp1); }
            if (two) {
                const float4 v1 = *(const float4*)&Ws1[kk][tx * 4];
                const u64 xp0 = ((const u64*)&v1)[0], xp1 = ((const u64*)&v1)[1];
#pragma unroll
                for (int i = 0; i < 4; i++) { ffma2(acc1[i][0], ap[i], xp0); ffma2(acc1[i][1], ap[i], xp1); }
            }
        }
    }
    const float4 bias0 = *(const float4*)(b0 + tx * 4);
    float4 bias1 = bias0;
    if (two) bias1 = *(const float4*)(b1 + tx * 4);
#pragma unroll
    for (int i = 0; i < 4; i++) {
        const int row = g0 + ty * 4 + i;
        const size_t eo = (size_t)row * 64 + tx * 4;
        float pre0[4], pre1[4];
        { const float2 a = up2(acc0[i][0]), b = up2(acc0[i][1]);
          pre0[0] = a.x + bias0.x; pre0[1] = a.y + bias0.y; pre0[2] = b.x + bias0.z; pre0[3] = b.y + bias0.w; }
        { const float2 a = up2(acc1[i][0]), b = up2(acc1[i][1]);
          pre1[0] = a.x + bias1.x; pre1[1] = a.y + bias1.y; pre1[2] = b.x + bias1.z; pre1[3] = b.y + bias1.w; }
        if (mode == 1) {
            const float4 hv = *(const float4*)(g_f + O_H + eo);
            const float h[4] = {hv.x, hv.y, hv.z, hv.w};
            float4 rh, uo;
            float* prh = (float*)&rh; float* puo = (float*)&uo;
#pragma unroll
            for (int j = 0; j < 4; j++) {
                const float r = 1.0f / (1.0f + expf(-pre0[j]));
                const float u = 1.0f / (1.0f + expf(-pre1[j]));
                prh[j] = r * h[j]; puo[j] = u;
            }
            *(float4*)(g_f + oOut0 + eo) = rh;
            *(float4*)(g_f + oOut1 + eo) = uo;
        } else if (mode == 2) {
            const float4 hv = *(const float4*)(g_f + O_H + eo);
            const float4 uv = *(const float4*)(g_f + O_U + eo);
            const float h[4] = {hv.x, hv.y, hv.z, hv.w};
            const float u[4] = {uv.x, uv.y, uv.z, uv.w};
            float4 hn; float* phn = (float*)&hn;
#pragma unroll
            for (int j = 0; j < 4; j++) {
                const float c = tanhf(pre0[j]);
                phn[j] = u[j] * h[j] + (1.0f - u[j]) * c;
            }
            *(float4*)(g_f + O_H + eo) = hn;
        } else {
            *(float4*)(g_f + oOut0 + eo) = make_float4(pre0[0], pre0[1], pre0[2], pre0[3]);
        }
    }
}

// ---------------------------------------------------------------------------
// Misc elementwise
// ---------------------------------------------------------------------------
__global__ void k_zero(size_t o) {
    g_f[o + (size_t)blockIdx.x * 256 + threadIdx.x] = 0.f;
}

// ---------------------------------------------------------------------------
// Sparse DiffConv hop (deterministic): one block per node n.
// out[n][:] = inv_deg(n) * sum_{e: sel[e]==n} in[oth[e]][:] * w[e]
// ---------------------------------------------------------------------------
__global__ void __launch_bounds__(256) k_gather(const int* __restrict__ sel,
        const int* __restrict__ oth, const float* __restrict__ w,
        size_t oIn, size_t oOut) {
    const int n = blockIdx.x, tid = threadIdx.x;
    __shared__ int   cnts[257];
    __shared__ int   s_o[2048];
    __shared__ float s_w[2048];
    __shared__ float red[256];
    __shared__ float s_inv;
    int c0 = 0;
    for (int e = tid; e < Ee; e += 256) c0 += (sel[e] == n);
    cnts[tid + 1] = c0;
    if (tid == 0) cnts[0] = 0;
    __syncthreads();
    if (tid == 0) { int a = 0; for (int i = 1; i <= 256; i++) { a += cnts[i]; cnts[i] = a; } }
    __syncthreads();
    int off = cnts[tid];
    for (int e = tid; e < Ee; e += 256)
        if (sel[e] == n) { if (off < 2048) { s_o[off] = oth[e]; s_w[off] = w[e]; } off++; }
    __syncthreads();
    int M = cnts[256]; if (M > 2048) M = 2048;
    // degree normalization (sum over all matched weights)
    float dacc = 0.f;
    for (int m = tid; m < M; m += 256) dacc += s_w[m];
    red[tid] = dacc; __syncthreads();
    for (int s = 128; s > 0; s >>= 1) {
        if (tid < s) red[tid] += red[tid + s];
        __syncthreads();
    }
    if (tid == 0) s_inv = red[0] > 0.f ? 1.f / red[0] : 0.f;
    __syncthreads();
    const float inv = s_inv;
    const float4* in4 = (const float4*)(g_f + oIn);
    float4 acc = make_float4(0.f, 0.f, 0.f, 0.f);
    for (int m = 0; m < M; m++) {
        const float wm = s_w[m];
        const float4 v = in4[(size_t)s_o[m] * 256 + tid];
        acc.x += v.x * wm; acc.y += v.y * wm; acc.z += v.z * wm; acc.w += v.w * wm;
    }
    acc.x *= inv; acc.y *= inv; acc.z *= inv; acc.w *= inv;
    ((float4*)(g_f + oOut + (size_t)n * 1024))[tid] = acc;
}

// ---------------------------------------------------------------------------
// Decoder: out[b,t,n,f] = z[g=n*16+b][:] @ W_dec[:, t*8+f] + b_dec
// ---------------------------------------------------------------------------
__global__ void k_dec(const float* __restrict__ Wd, const float* __restrict__ bd,
                      float* __restrict__ out) {
    __shared__ float zs[64];
    const int g = blockIdx.x, c = threadIdx.x;   // 96 threads
    if (c < 64) zs[c] = g_f[O_Z + (size_t)g * 64 + c];
    __syncthreads();
    float a = bd[c];
#pragma unroll
    for (int h = 0; h < 64; h++) a += zs[h] * Wd[h * 96 + c];
    const int b = g & 15, n = g >> 4, t = c >> 3, f = c & 7;
    out[(((size_t)b * 12 + t) * 1024 + n) * 8 + f] = a;
}

// ---------------------------------------------------------------------------
// Launcher
// ---------------------------------------------------------------------------
extern "C" void kernel_launch(void* const* d_in, const int* in_sizes, int n_in,
                              void* d_out, int out_size) {
    const float* x      = (const float*)d_in[0];
    const int*   ei     = (const int*)d_in[1];
    const float* ew     = (const float*)d_in[2];
    const float* adj    = (const float*)d_in[3];
    const float* W_enc  = (const float*)d_in[4];
    const float* b_enc  = (const float*)d_in[5];
    const float* emb    = (const float*)d_in[6];
    const float* W_r    = (const float*)d_in[7];
    const float* b_r    = (const float*)d_in[8];
    const float* W_u    = (const float*)d_in[9];
    const float* b_u    = (const float*)d_in[10];
    const float* W_c    = (const float*)d_in[11];
    const float* b_c    = (const float*)d_in[12];
    const float* W_diff = (const float*)d_in[13];
    const float* b_diff = (const float*)d_in[14];
    const float* W_dec  = (const float*)d_in[15];
    const float* b_dec  = (const float*)d_in[16];
    float* out = (float*)d_out;
    const int* src = ei;
    const int* dst = ei + Ee;

    // supports + encoder
    k_rowsum<<<1024, 256>>>(adj);
    k_colsum<<<4, 256>>>(adj);
    k_norm<<<4096, 256>>>(adj);
    k_encoder<<<dim3(1024, 12), 256>>>(x, W_enc, b_enc, emb);

    // precompute xt hops for all t (batched z=12)
    const dim3 g12(8, 8, 12);
    k_gemm<<<g12, 256>>>(O_ADJF, O_ADJF, O_XENC, NS, O_XF1, NS, 0);
    k_gemm<<<g12, 256>>>(O_ADJB, O_ADJB, O_XENC, NS, O_XB1, NS, 0);
    k_gemm<<<g12, 256>>>(O_ADJF, O_ADJF, O_XF1, NS, O_XF2, NS, 0);
    k_gemm<<<g12, 256>>>(O_ADJB, O_ADJB, O_XB1, NS, O_XB2, NS, 0);

    // GRU scan
    k_zero<<<4096, 256>>>(O_H);
    const dim3 g2(8, 8, 2);
    for (int t = 0; t < 12; t++) {
        k_gemm<<<g2, 256>>>(O_ADJF, O_ADJB, O_H, 0, O_HHOP, 2 * NS, 1);
        k_gemm<<<g2, 256>>>(O_ADJF, O_ADJB, O_HHOP, 2 * NS, O_HHOP + NS, 2 * NS, 1);
        COffs cg;
        cg.o[0] = O_XF1 + (size_t)t * NS; cg.o[1] = O_HHOP;
        cg.o[2] = O_XF2 + (size_t)t * NS; cg.o[3] = O_HHOP + NS;
        cg.o[4] = O_XB1 + (size_t)t * NS; cg.o[5] = O_HHOP + 2 * NS;
        cg.o[6] = O_XB2 + (size_t)t * NS; cg.o[7] = O_HHOP + 3 * NS;
        k_gate<<<256, 256>>>(cg, 8, W_r, b_r, W_u, b_u, O_RH, O_U, 1, 1);
        k_gemm<<<g2, 256>>>(O_ADJF, O_ADJB, O_RH, 0, O_RHHOP, 2 * NS, 1);
        k_gemm<<<g2, 256>>>(O_ADJF, O_ADJB, O_RHHOP, 2 * NS, O_RHHOP + NS, 2 * NS, 1);
        COffs cc = cg;
        cc.o[1] = O_RHHOP;          cc.o[3] = O_RHHOP + NS;
        cc.o[5] = O_RHHOP + 2 * NS; cc.o[7] = O_RHHOP + 3 * NS;
        k_gate<<<256, 256>>>(cc, 8, W_c, b_c, W_c, b_c, O_H, O_H, 2, 0);
    }

    // sparse DiffConv readout (deg normalization fused into gathers)
    k_gather<<<1024, 256>>>(dst, src, ew, O_H, O_F1);
    k_gather<<<1024, 256>>>(dst, src, ew, O_F1, O_F2);
    k_gather<<<1024, 256>>>(src, dst, ew, O_H, O_B1);
    k_gather<<<1024, 256>>>(src, dst, ew, O_B1, O_B2);
    COffs cz;
    cz.o[0] = O_H; cz.o[1] = O_F1; cz.o[2] = O_F2; cz.o[3] = O_B1; cz.o[4] = O_B2;
    cz.o[5] = cz.o[6] = cz.o[7] = O_H;
    k_gate<<<256, 256>>>(cz, 5, W_diff, b_diff, W_diff, b_diff, O_Z, O_Z, 0, 0);

    // decoder
    k_dec<<<16384, 96>>>(W_dec, b_dec, out);
}

// round 12
// speedup vs baseline: 1.2884x; 1.2735x over previous
#include <cuda_runtime.h>
#include <cuda_bf16.h>
#include <math.h>
#include <stdint.h>

typedef unsigned long long u64;

// ---------------------------------------------------------------------------
// Problem constants
// ---------------------------------------------------------------------------
constexpr int    Nn = 1024;
constexpr int    Tt = 12;
constexpr int    Ff = 8;
constexpr int    Ee = 32768;
constexpr size_t NS = (size_t)Nn * 1024;   // 1M floats per plane [node][b*64+h]

// ---------------------------------------------------------------------------
// fp32 scratch arena
// ---------------------------------------------------------------------------
constexpr size_t O_ADJF  = 0;
constexpr size_t O_ADJB  = 1 * NS;
constexpr size_t O_XENC  = 2 * NS;    // 12 planes
constexpr size_t O_XF1   = 14 * NS;   // 12
constexpr size_t O_XF2   = 26 * NS;   // 12
constexpr size_t O_XB1   = 38 * NS;   // 12
constexpr size_t O_XB2   = 50 * NS;   // 12
constexpr size_t O_H     = 62 * NS;
constexpr size_t O_HHOP  = 63 * NS;   // 4: [HF1, HF2, HB1, HB2]
constexpr size_t O_RH    = 67 * NS;
constexpr size_t O_RHHOP = 68 * NS;   // 4
constexpr size_t O_U     = 72 * NS;
constexpr size_t O_F1    = 73 * NS;
constexpr size_t O_F2    = 74 * NS;
constexpr size_t O_B1    = 75 * NS;
constexpr size_t O_B2    = 76 * NS;
constexpr size_t O_Z     = 77 * NS;
constexpr size_t O_RSUM  = 78 * NS;
constexpr size_t O_CSUM  = 78 * NS + 1024;
constexpr size_t F_TOT   = 78 * NS + 2048;

__device__ float g_f[F_TOT];

// ---------------------------------------------------------------------------
// bf16 plane arena (hi/lo split pairs; "T" planes are transposed [col][node])
// ---------------------------------------------------------------------------
constexpr int PB_AF = 0, PB_AB = 2, PB_XET = 4, PB_XF1T = 28, PB_XB1T = 52;
constexpr int PB_HT = 76, PB_HF1T = 78, PB_RHT = 82, PB_RHF1T = 84;
constexpr int PB_NUM = 88;

__device__ __align__(256) __nv_bfloat16 g_b[(size_t)PB_NUM * NS];

// ---------------------------------------------------------------------------
// helpers
// ---------------------------------------------------------------------------
__device__ __forceinline__ uint32_t smem_u32(const void* p) {
    uint32_t a;
    asm("{ .reg .u64 t; cvta.to.shared.u64 t, %1; cvt.u32.u64 %0, t; }" : "=r"(a) : "l"(p));
    return a;
}

__device__ __forceinline__ void mma16816(float* c, const uint32_t* a, uint32_t b0, uint32_t b1) {
    asm volatile("mma.sync.aligned.m16n8k16.row.col.f32.bf16.bf16.f32 "
        "{%0,%1,%2,%3}, {%4,%5,%6,%7}, {%8,%9}, {%0,%1,%2,%3};"
        : "+f"(c[0]), "+f"(c[1]), "+f"(c[2]), "+f"(c[3])
        : "r"(a[0]), "r"(a[1]), "r"(a[2]), "r"(a[3]), "r"(b0), "r"(b1));
}

// ---------------------------------------------------------------------------
// Adjacency normalization
// ---------------------------------------------------------------------------
__global__ void k_rowsum(const float* __restrict__ adj) {
    const int i = blockIdx.x;
    __shared__ float sm[256];
    float a = 0.f;
    for (int j = threadIdx.x; j < 1024; j += 256) a += adj[(size_t)i * 1024 + j];
    sm[threadIdx.x] = a; __syncthreads();
    for (int s = 128; s > 0; s >>= 1) {
        if (threadIdx.x < s) sm[threadIdx.x] += sm[threadIdx.x + s];
        __syncthreads();
    }
    if (threadIdx.x == 0) g_f[O_RSUM + i] = sm[0];
}

__global__ void k_colsum(const float* __restrict__ adj) {
    const int j = blockIdx.x * 256 + threadIdx.x;
    float a = 0.f;
    for (int i = 0; i < 1024; i++) a += adj[(size_t)i * 1024 + j];
    g_f[O_CSUM + j] = a;
}

__global__ void k_norm(const float* __restrict__ adj) {
    const size_t idx = (size_t)blockIdx.x * 256 + threadIdx.x;
    const int i = (int)(idx >> 10), j = (int)(idx & 1023);
    g_f[O_ADJF + idx] = adj[idx] / g_f[O_RSUM + i];
    g_f[O_ADJB + idx] = adj[(size_t)j * 1024 + i] / g_f[O_CSUM + i];
}

// adj fp32 -> bf16 hi/lo (non-transposed; A operand is m-major rows)
__global__ void k_cvtAdj() {
    const size_t idx = (size_t)blockIdx.x * 256 + threadIdx.x;
    const int z = blockIdx.y;
    const float v = g_f[(z ? O_ADJB : O_ADJF) + idx];
    const __nv_bfloat16 h = __float2bfloat16(v);
    g_b[(size_t)(z * 2) * NS + idx] = h;
    g_b[(size_t)(z * 2 + 1) * NS + idx] = __float2bfloat16(v - __bfloat162float(h));
}

// fp32 plane [k][n] -> transposed bf16 hi/lo planes [n][k]
__global__ void k_cvtT(size_t inOff, size_t inStr, int outBase, int outStr) {
    const int z = blockIdx.z;
    const float* __restrict__ in = g_f + inOff + (size_t)z * inStr;
    __nv_bfloat16* hi = g_b + (size_t)(outBase + z * outStr) * NS;
    __nv_bfloat16* lo = hi + NS;
    __shared__ float t[32][33];
    const int bx = blockIdx.x * 32, by = blockIdx.y * 32;
    const int tx = threadIdx.x, ty = threadIdx.y;
#pragma unroll
    for (int i = 0; i < 4; i++)
        t[ty + i * 8][tx] = in[(size_t)(by + ty + i * 8) * 1024 + bx + tx];
    __syncthreads();
#pragma unroll
    for (int i = 0; i < 4; i++) {
        const int n = bx + ty + i * 8, k = by + tx;
        const float v = t[tx][ty + i * 8];
        const __nv_bfloat16 h = __float2bfloat16(v);
        hi[(size_t)n * 1024 + k] = h;
        lo[(size_t)n * 1024 + k] = __float2bfloat16(v - __bfloat162float(h));
    }
}

// ---------------------------------------------------------------------------
// Encoder
// ---------------------------------------------------------------------------
__global__ void k_encoder(const float* __restrict__ x, const float* __restrict__ W,
                          const float* __restrict__ bias, const float* __restrict__ emb) {
    __shared__ float xs[16][8];
    __shared__ float Ws[8][64];
    const int n = blockIdx.x, t = blockIdx.y, tid = threadIdx.x;
    if (tid < 128) {
        const int b = tid >> 3, f = tid & 7;
        xs[b][f] = x[((size_t)(b * Tt + t) * Nn + n) * Ff + f];
    }
    {
        const int i0 = tid, i1 = tid + 256;
        Ws[i0 >> 6][i0 & 63] = W[i0];
        Ws[i1 >> 6][i1 & 63] = W[i1];
    }
    __syncthreads();
    const int h = tid & 63, bq = tid >> 6;
    const float base = bias[h] + emb[(size_t)n * 64 + h];
    float* o = g_f + O_XENC + (size_t)t * NS + (size_t)n * 1024;
#pragma unroll
    for (int i = 0; i < 4; i++) {
        const int b = bq * 4 + i;
        float acc = base;
#pragma unroll
        for (int f = 0; f < 8; f++) acc += xs[b][f] * Ws[f][h];
        o[b * 64 + h] = acc;
    }
}

// ---------------------------------------------------------------------------
// Tensor-core hop GEMM via mma.sync (legacy HMMA, base sm_103 target):
// C(z) = A(z) @ X(z), 3-term bf16 split, fp32 accumulators.
// A planes m-major [m][k]; X-T planes [n][k]. 128x128 tile per CTA,
// 8 warps (2m x 4n), each warp 64x32 via m16n8k16. BK=32, K=3x1024.
// Smem rows padded to 40 bf16 (80B pitch) -> conflict-free ldmatrix.
// ---------------------------------------------------------------------------
__global__ void __launch_bounds__(256) k_tc(int aP0, int aP1, int aSel,
                                            int xBase, int xStr,
                                            size_t cOff, size_t cStr) {
    __shared__ __align__(16) __nv_bfloat16 sA[128 * 40];
    __shared__ __align__(16) __nv_bfloat16 sB[128 * 40];
    const int tid = threadIdx.x, wid = tid >> 5, lane = tid & 31;
    const int z = blockIdx.z;
    const int m0 = blockIdx.y * 128, n0 = blockIdx.x * 128;
    const int aP = (aSel && (z & 1)) ? aP1 : aP0;
    const __nv_bfloat16* __restrict__ Ahi = g_b + (size_t)aP * NS;
    const __nv_bfloat16* __restrict__ Alo = Ahi + NS;
    const __nv_bfloat16* __restrict__ Xhi = g_b + (size_t)(xBase + xStr * z) * NS;
    const __nv_bfloat16* __restrict__ Xlo = Xhi + NS;
    float* __restrict__ C = g_f + cOff + (size_t)z * cStr;

    const int wm = (wid & 1) * 64, wn = (wid >> 1) * 32;
    const uint32_t aBase = smem_u32(sA), bBase = smem_u32(sB);
    // ldmatrix lane addressing: row = frag_row + (lane&15), k += (lane>>4)*8
    const int lrow = lane & 15, lkh = (lane >> 4) * 8;

    float acc[4][4][4];
#pragma unroll
    for (int mi = 0; mi < 4; mi++)
#pragma unroll
        for (int ni = 0; ni < 4; ni++)
#pragma unroll
            for (int q = 0; q < 4; q++) acc[mi][ni][q] = 0.f;

    const int lrowA = tid >> 2, lcol = (tid & 3) * 8;   // global->smem copy map

#pragma unroll 1
    for (int s = 0; s < 3; s++) {
        const __nv_bfloat16* __restrict__ Ap = (s < 2) ? Ahi : Alo;
        const __nv_bfloat16* __restrict__ Xp = (s == 1) ? Xlo : Xhi;
#pragma unroll 1
        for (int kc = 0; kc < 1024; kc += 32) {
            __syncthreads();
#pragma unroll
            for (int it = 0; it < 2; it++) {
                const int row = lrowA + it * 64;
                const uint4 va = *(const uint4*)(Ap + (size_t)(m0 + row) * 1024 + kc + lcol);
                const uint4 vb = *(const uint4*)(Xp + (size_t)(n0 + row) * 1024 + kc + lcol);
                *(uint4*)(sA + row * 40 + lcol) = va;
                *(uint4*)(sB + row * 40 + lcol) = vb;
            }
            __syncthreads();
#pragma unroll
            for (int ks = 0; ks < 2; ks++) {
                const int kb = ks * 16 + lkh;
                uint32_t a[4][4], b[2][4];
#pragma unroll
                for (int mi = 0; mi < 4; mi++) {
                    const uint32_t ad = aBase + (uint32_t)(((wm + mi * 16 + lrow) * 40 + kb) * 2);
                    asm volatile("ldmatrix.sync.aligned.m8n8.x4.shared.b16 {%0,%1,%2,%3}, [%4];"
                        : "=r"(a[mi][0]), "=r"(a[mi][1]), "=r"(a[mi][2]), "=r"(a[mi][3]) : "r"(ad));
                }
#pragma unroll
                for (int nb = 0; nb < 2; nb++) {
                    const uint32_t bd = bBase + (uint32_t)(((wn + nb * 16 + lrow) * 40 + kb) * 2);
                    asm volatile("ldmatrix.sync.aligned.m8n8.x4.shared.b16 {%0,%1,%2,%3}, [%4];"
                        : "=r"(b[nb][0]), "=r"(b[nb][1]), "=r"(b[nb][2]), "=r"(b[nb][3]) : "r"(bd));
                }
#pragma unroll
                for (int mi = 0; mi < 4; mi++)
#pragma unroll
                    for (int ni = 0; ni < 4; ni++) {
                        const int nb = ni >> 1, hl = ni & 1;
                        mma16816(acc[mi][ni], a[mi], b[nb][hl], b[nb][2 + hl]);
                    }
            }
        }
    }
    // epilogue: c0,c1 -> row t/4, cols 2(t%4); c2,c3 -> row t/4+8
    const int er = lane >> 2, ec = (lane & 3) * 2;
#pragma unroll
    for (int mi = 0; mi < 4; mi++)
#pragma unroll
        for (int ni = 0; ni < 4; ni++) {
            const int row = m0 + wm + mi * 16 + er;
            const int col = n0 + wn + ni * 8 + ec;
            *(float2*)(C + (size_t)row * 1024 + col) = make_float2(acc[mi][ni][0], acc[mi][ni][1]);
            *(float2*)(C + (size_t)(row + 8) * 1024 + col) = make_float2(acc[mi][ni][2], acc[mi][ni][3]);
        }
}

// ---------------------------------------------------------------------------
// Gate gather-GEMM (FFMA2) + fused epilogues (unchanged from R9, passing)
// ---------------------------------------------------------------------------
struct COffs { size_t o[8]; };

__device__ __forceinline__ u64 pack2(float x) {
    u64 r;
    asm("mov.b64 %0, {%1, %1};" : "=l"(r) : "r"(__float_as_uint(x)));
    return r;
}
__device__ __forceinline__ void ffma2(u64& c, u64 a, u64 b) {
    asm("fma.rn.f32x2 %0, %1, %2, %0;" : "+l"(c) : "l"(a), "l"(b));
}
__device__ __forceinline__ float2 up2(u64 v) {
    float2 f;
    unsigned lo, hi;
    asm("mov.b64 {%0, %1}, %2;" : "=r"(lo), "=r"(hi) : "l"(v));
    f.x = __uint_as_float(lo); f.y = __uint_as_float(hi);
    return f;
}

__global__ void __launch_bounds__(256) k_gate(COffs ch, int nch,
        const float* __restrict__ W0, const float* __restrict__ b0,
        const float* __restrict__ W1, const float* __restrict__ b1,
        size_t oOut0, size_t oOut1, int mode, int two) {
    __shared__ float As[64][17];
    __shared__ float Ws0[16][68];
    __shared__ float Ws1[16][68];
    const int tid = threadIdx.x;
    const int g0 = blockIdx.x * 64;
    const int tx = tid & 15, ty = tid >> 4;
    const int ar = tid >> 2, kq = (tid & 3) * 4;
    const size_t abase = (size_t)(g0 + ar) * 64;
    const int wr = tid >> 4, wc = (tid & 15) * 4;
    u64 acc0[4][2], acc1[4][2];
#pragma unroll
    for (int i = 0; i < 4; i++) { acc0[i][0] = acc0[i][1] = 0ULL; acc1[i][0] = acc1[i][1] = 0ULL; }
    const int K = nch * 64;
    for (int k0 = 0; k0 < K; k0 += 16) {
        const float4 av = *(const float4*)(g_f + ch.o[k0 >> 6] + abase + (k0 & 63) + kq);
        const float4 w0 = *(const float4*)(W0 + (size_t)(k0 + wr) * 64 + wc);
        float4 w1 = make_float4(0.f, 0.f, 0.f, 0.f);
        if (two) w1 = *(const float4*)(W1 + (size_t)(k0 + wr) * 64 + wc);
        __syncthreads();
        As[ar][kq + 0] = av.x; As[ar][kq + 1] = av.y; As[ar][kq + 2] = av.z; As[ar][kq + 3] = av.w;
        *(float4*)&Ws0[wr][wc] = w0;
        if (two) *(float4*)&Ws1[wr][wc] = w1;
        __syncthreads();
#pragma unroll
        for (int kk = 0; kk < 16; kk++) {
            u64 ap[4];
#pragma unroll
            for (int i = 0; i < 4; i++) ap[i] = pack2(As[ty * 4 + i][kk]);
            const float4 v0 = *(const float4*)&Ws0[kk][tx * 4];
            const u64 wp0 = ((const u64*)&v0)[0], wp1 = ((const u64*)&v0)[1];
#pragma unroll
            for (int i = 0; i < 4; i++) { ffma2(acc0[i][0], ap[i], wp0); ffma2(acc0[i][1], ap[i], wp1); }
            if (two) {
                const float4 v1 = *(const float4*)&Ws1[kk][tx * 4];
                const u64 xp0 = ((const u64*)&v1)[0], xp1 = ((const u64*)&v1)[1];
#pragma unroll
                for (int i = 0; i < 4; i++) { ffma2(acc1[i][0], ap[i], xp0); ffma2(acc1[i][1], ap[i], xp1); }
            }
        }
    }
    const float4 bias0 = *(const float4*)(b0 + tx * 4);
    float4 bias1 = bias0;
    if (two) bias1 = *(const float4*)(b1 + tx * 4);
#pragma unroll
    for (int i = 0; i < 4; i++) {
        const int row = g0 + ty * 4 + i;
        const size_t eo = (size_t)row * 64 + tx * 4;
        float pre0[4], pre1[4];
        { const float2 a = up2(acc0[i][0]), b = up2(acc0[i][1]);
          pre0[0] = a.x + bias0.x; pre0[1] = a.y + bias0.y; pre0[2] = b.x + bias0.z; pre0[3] = b.y + bias0.w; }
        { const float2 a = up2(acc1[i][0]), b = up2(acc1[i][1]);
          pre1[0] = a.x + bias1.x; pre1[1] = a.y + bias1.y; pre1[2] = b.x + bias1.z; pre1[3] = b.y + bias1.w; }
        if (mode == 1) {
            const float4 hv = *(const float4*)(g_f + O_H + eo);
            const float h[4] = {hv.x, hv.y, hv.z, hv.w};
            float4 rh, uo;
            float* prh = (float*)&rh; float* puo = (float*)&uo;
#pragma unroll
            for (int j = 0; j < 4; j++) {
                const float r = 1.0f / (1.0f + expf(-pre0[j]));
                const float u = 1.0f / (1.0f + expf(-pre1[j]));
                prh[j] = r * h[j]; puo[j] = u;
            }
            *(float4*)(g_f + oOut0 + eo) = rh;
            *(float4*)(g_f + oOut1 + eo) = uo;
        } else if (mode == 2) {
            const float4 hv = *(const float4*)(g_f + O_H + eo);
            const float4 uv = *(const float4*)(g_f + O_U + eo);
            const float h[4] = {hv.x, hv.y, hv.z, hv.w};
            const float u[4] = {uv.x, uv.y, uv.z, uv.w};
            float4 hn; float* phn = (float*)&hn;
#pragma unroll
            for (int j = 0; j < 4; j++) {
                const float c = tanhf(pre0[j]);
                phn[j] = u[j] * h[j] + (1.0f - u[j]) * c;
            }
            *(float4*)(g_f + O_H + eo) = hn;
        } else {
            *(float4*)(g_f + oOut0 + eo) = make_float4(pre0[0], pre0[1], pre0[2], pre0[3]);
        }
    }
}

__global__ void k_zero(size_t o) {
    g_f[o + (size_t)blockIdx.x * 256 + threadIdx.x] = 0.f;
}

// ---------------------------------------------------------------------------
// Sparse DiffConv hop (deterministic): one block per node n.
// ---------------------------------------------------------------------------
__global__ void __launch_bounds__(256) k_gather(const int* __restrict__ sel,
        const int* __restrict__ oth, const float* __restrict__ w,
        size_t oIn, size_t oOut) {
    const int n = blockIdx.x, tid = threadIdx.x;
    __shared__ int   cnts[257];
    __shared__ int   s_o[2048];
    __shared__ float s_w[2048];
    __shared__ float red[256];
    __shared__ float s_inv;
    int c0 = 0;
    for (int e = tid; e < Ee; e += 256) c0 += (sel[e] == n);
    cnts[tid + 1] = c0;
    if (tid == 0) cnts[0] = 0;
    __syncthreads();
    if (tid == 0) { int a = 0; for (int i = 1; i <= 256; i++) { a += cnts[i]; cnts[i] = a; } }
    __syncthreads();
    int off = cnts[tid];
    for (int e = tid; e < Ee; e += 256)
        if (sel[e] == n) { if (off < 2048) { s_o[off] = oth[e]; s_w[off] = w[e]; } off++; }
    __syncthreads();
    int M = cnts[256]; if (M > 2048) M = 2048;
    float dacc = 0.f;
    for (int m = tid; m < M; m += 256) dacc += s_w[m];
    red[tid] = dacc; __syncthreads();
    for (int s = 128; s > 0; s >>= 1) {
        if (tid < s) red[tid] += red[tid + s];
        __syncthreads();
    }
    if (tid == 0) s_inv = red[0] > 0.f ? 1.f / red[0] : 0.f;
    __syncthreads();
    const float inv = s_inv;
    const float4* in4 = (const float4*)(g_f + oIn);
    float4 acc = make_float4(0.f, 0.f, 0.f, 0.f);
    for (int m = 0; m < M; m++) {
        const float wm = s_w[m];
        const float4 v = in4[(size_t)s_o[m] * 256 + tid];
        acc.x += v.x * wm; acc.y += v.y * wm; acc.z += v.z * wm; acc.w += v.w * wm;
    }
    acc.x *= inv; acc.y *= inv; acc.z *= inv; acc.w *= inv;
    ((float4*)(g_f + oOut + (size_t)n * 1024))[tid] = acc;
}

// ---------------------------------------------------------------------------
// Decoder
// ---------------------------------------------------------------------------
__global__ void k_dec(const float* __restrict__ Wd, const float* __restrict__ bd,
                      float* __restrict__ out) {
    __shared__ float zs[64];
    const int g = blockIdx.x, c = threadIdx.x;   // 96 threads
    if (c < 64) zs[c] = g_f[O_Z + (size_t)g * 64 + c];
    __syncthreads();
    float a = bd[c];
#pragma unroll
    for (int h = 0; h < 64; h++) a += zs[h] * Wd[h * 96 + c];
    const int b = g & 15, n = g >> 4, t = c >> 3, f = c & 7;
    out[(((size_t)b * 12 + t) * 1024 + n) * 8 + f] = a;
}

// ---------------------------------------------------------------------------
// Launcher
// ---------------------------------------------------------------------------
extern "C" void kernel_launch(void* const* d_in, const int* in_sizes, int n_in,
                              void* d_out, int out_size) {
    const float* x      = (const float*)d_in[0];
    const int*   ei     = (const int*)d_in[1];
    const float* ew     = (const float*)d_in[2];
    const float* adj    = (const float*)d_in[3];
    const float* W_enc  = (const float*)d_in[4];
    const float* b_enc  = (const float*)d_in[5];
    const float* emb    = (const float*)d_in[6];
    const float* W_r    = (const float*)d_in[7];
    const float* b_r    = (const float*)d_in[8];
    const float* W_u    = (const float*)d_in[9];
    const float* b_u    = (const float*)d_in[10];
    const float* W_c    = (const float*)d_in[11];
    const float* b_c    = (const float*)d_in[12];
    const float* W_diff = (const float*)d_in[13];
    const float* b_diff = (const float*)d_in[14];
    const float* W_dec  = (const float*)d_in[15];
    const float* b_dec  = (const float*)d_in[16];
    float* out = (float*)d_out;
    const int* src = ei;
    const int* dst = ei + Ee;

    const dim3 cvtB(32, 8);

    // supports + encoder + bf16 conversions
    k_rowsum<<<1024, 256>>>(adj);
    k_colsum<<<4, 256>>>(adj);
    k_norm<<<4096, 256>>>(adj);
    k_encoder<<<dim3(1024, 12), 256>>>(x, W_enc, b_enc, emb);
    k_cvtAdj<<<dim3(4096, 2), 256>>>();
    k_cvtT<<<dim3(32, 32, 12), cvtB>>>(O_XENC, NS, PB_XET, 2);

    // x-side hops for all t, batched (tensor cores)
    const dim3 gt12(8, 8, 12);
    k_tc<<<gt12, 256>>>(PB_AF, PB_AF, 0, PB_XET, 2, O_XF1, NS);
    k_tc<<<gt12, 256>>>(PB_AB, PB_AB, 0, PB_XET, 2, O_XB1, NS);
    k_cvtT<<<dim3(32, 32, 12), cvtB>>>(O_XF1, NS, PB_XF1T, 2);
    k_cvtT<<<dim3(32, 32, 12), cvtB>>>(O_XB1, NS, PB_XB1T, 2);
    k_tc<<<gt12, 256>>>(PB_AF, PB_AF, 0, PB_XF1T, 2, O_XF2, NS);
    k_tc<<<gt12, 256>>>(PB_AB, PB_AB, 0, PB_XB1T, 2, O_XB2, NS);

    // GRU scan
    k_zero<<<4096, 256>>>(O_H);
    const dim3 gt2(8, 8, 2);
    for (int t = 0; t < 12; t++) {
        k_cvtT<<<dim3(32, 32, 1), cvtB>>>(O_H, 0, PB_HT, 0);
        k_tc<<<gt2, 256>>>(PB_AF, PB_AB, 1, PB_HT, 0, O_HHOP, 2 * NS);
        k_cvtT<<<dim3(32, 32, 2), cvtB>>>(O_HHOP, 2 * NS, PB_HF1T, 2);
        k_tc<<<gt2, 256>>>(PB_AF, PB_AB, 1, PB_HF1T, 2, O_HHOP + NS, 2 * NS);
        COffs cg;
        cg.o[0] = O_XF1 + (size_t)t * NS; cg.o[1] = O_HHOP;
        cg.o[2] = O_XF2 + (size_t)t * NS; cg.o[3] = O_HHOP + NS;
        cg.o[4] = O_XB1 + (size_t)t * NS; cg.o[5] = O_HHOP + 2 * NS;
        cg.o[6] = O_XB2 + (size_t)t * NS; cg.o[7] = O_HHOP + 3 * NS;
        k_gate<<<256, 256>>>(cg, 8, W_r, b_r, W_u, b_u, O_RH, O_U, 1, 1);
        k_cvtT<<<dim3(32, 32, 1), cvtB>>>(O_RH, 0, PB_RHT, 0);
        k_tc<<<gt2, 256>>>(PB_AF, PB_AB, 1, PB_RHT, 0, O_RHHOP, 2 * NS);
        k_cvtT<<<dim3(32, 32, 2), cvtB>>>(O_RHHOP, 2 * NS, PB_RHF1T, 2);
        k_tc<<<gt2, 256>>>(PB_AF, PB_AB, 1, PB_RHF1T, 2, O_RHHOP + NS, 2 * NS);
        COffs cc = cg;
        cc.o[1] = O_RHHOP;          cc.o[3] = O_RHHOP + NS;
        cc.o[5] = O_RHHOP + 2 * NS; cc.o[7] = O_RHHOP + 3 * NS;
        k_gate<<<256, 256>>>(cc, 8, W_c, b_c, W_c, b_c, O_H, O_H, 2, 0);
    }

    // sparse DiffConv readout
    k_gather<<<1024, 256>>>(dst, src, ew, O_H, O_F1);
    k_gather<<<1024, 256>>>(dst, src, ew, O_F1, O_F2);
    k_gather<<<1024, 256>>>(src, dst, ew, O_H, O_B1);
    k_gather<<<1024, 256>>>(src, dst, ew, O_B1, O_B2);
    COffs cz;
    cz.o[0] = O_H; cz.o[1] = O_F1; cz.o[2] = O_F2; cz.o[3] = O_B1; cz.o[4] = O_B2;
    cz.o[5] = cz.o[6] = cz.o[7] = O_H;
    k_gate<<<256, 256>>>(cz, 5, W_diff, b_diff, W_diff, b_diff, O_Z, O_Z, 0, 0);

    // decoder
    k_dec<<<16384, 96>>>(W_dec, b_dec, out);
}

// round 14
// speedup vs baseline: 1.5046x; 1.1678x over previous
#include <cuda_runtime.h>
#include <cuda_bf16.h>
#include <math.h>
#include <stdint.h>

typedef unsigned long long u64;

// ---------------------------------------------------------------------------
// Problem constants
// ---------------------------------------------------------------------------
constexpr int    Nn = 1024;
constexpr int    Tt = 12;
constexpr int    Ff = 8;
constexpr int    Ee = 32768;
constexpr size_t NS = (size_t)Nn * 1024;   // 1M floats per plane [node][b*64+h]

// ---------------------------------------------------------------------------
// fp32 scratch arena
// ---------------------------------------------------------------------------
constexpr size_t O_ADJF  = 0;
constexpr size_t O_ADJB  = 1 * NS;
constexpr size_t O_XENC  = 2 * NS;    // 12 planes
constexpr size_t O_XF1   = 14 * NS;   // 12
constexpr size_t O_XF2   = 26 * NS;   // 12
constexpr size_t O_XB1   = 38 * NS;   // 12
constexpr size_t O_XB2   = 50 * NS;   // 12
constexpr size_t O_H     = 62 * NS;
constexpr size_t O_HHOP  = 63 * NS;   // 4: [HF1, HF2, HB1, HB2]
constexpr size_t O_RH    = 67 * NS;
constexpr size_t O_RHHOP = 68 * NS;   // 4
constexpr size_t O_U     = 72 * NS;
constexpr size_t O_F1    = 73 * NS;
constexpr size_t O_F2    = 74 * NS;
constexpr size_t O_B1    = 75 * NS;
constexpr size_t O_B2    = 76 * NS;
constexpr size_t O_Z     = 77 * NS;
constexpr size_t O_RSUM  = 78 * NS;
constexpr size_t O_CSUM  = 78 * NS + 1024;
constexpr size_t F_TOT   = 78 * NS + 2048;

__device__ float g_f[F_TOT];

// ---------------------------------------------------------------------------
// bf16 plane arena (hi/lo split pairs; "T" planes are transposed [bh][node])
// ---------------------------------------------------------------------------
constexpr int PB_AF = 0, PB_AB = 2, PB_XET = 4, PB_XF1T = 28, PB_XB1T = 52;
constexpr int PB_HT = 76, PB_HF1T = 78, PB_RHT = 82, PB_RHF1T = 84;
constexpr int PB_NUM = 88;

__device__ __align__(256) __nv_bfloat16 g_b[(size_t)PB_NUM * NS];

// ---------------------------------------------------------------------------
// helpers
// ---------------------------------------------------------------------------
__device__ __forceinline__ uint32_t smem_u32(const void* p) {
    uint32_t a;
    asm("{ .reg .u64 t; cvta.to.shared.u64 t, %1; cvt.u32.u64 %0, t; }" : "=r"(a) : "l"(p));
    return a;
}
__device__ __forceinline__ void mma16816(float* c, const uint32_t* a, uint32_t b0, uint32_t b1) {
    asm volatile("mma.sync.aligned.m16n8k16.row.col.f32.bf16.bf16.f32 "
        "{%0,%1,%2,%3}, {%4,%5,%6,%7}, {%8,%9}, {%0,%1,%2,%3};"
        : "+f"(c[0]), "+f"(c[1]), "+f"(c[2]), "+f"(c[3])
        : "r"(a[0]), "r"(a[1]), "r"(a[2]), "r"(a[3]), "r"(b0), "r"(b1));
}
__device__ __forceinline__ void cp16(uint32_t dst, const void* src) {
    asm volatile("cp.async.cg.shared.global [%0], [%1], 16;" :: "r"(dst), "l"(src));
}
__device__ __forceinline__ unsigned short bfbits(__nv_bfloat16 h) {
    return *(unsigned short*)&h;
}

// ---------------------------------------------------------------------------
// Adjacency normalization
// ---------------------------------------------------------------------------
__global__ void k_rowsum(const float* __restrict__ adj) {
    const int i = blockIdx.x;
    __shared__ float sm[256];
    float a = 0.f;
    for (int j = threadIdx.x; j < 1024; j += 256) a += adj[(size_t)i * 1024 + j];
    sm[threadIdx.x] = a; __syncthreads();
    for (int s = 128; s > 0; s >>= 1) {
        if (threadIdx.x < s) sm[threadIdx.x] += sm[threadIdx.x + s];
        __syncthreads();
    }
    if (threadIdx.x == 0) g_f[O_RSUM + i] = sm[0];
}

__global__ void k_colsum(const float* __restrict__ adj) {
    const int j = blockIdx.x * 256 + threadIdx.x;
    float a = 0.f;
    for (int i = 0; i < 1024; i++) a += adj[(size_t)i * 1024 + j];
    g_f[O_CSUM + j] = a;
}

__global__ void k_norm(const float* __restrict__ adj) {
    const size_t idx = (size_t)blockIdx.x * 256 + threadIdx.x;
    const int i = (int)(idx >> 10), j = (int)(idx & 1023);
    g_f[O_ADJF + idx] = adj[idx] / g_f[O_RSUM + i];
    g_f[O_ADJB + idx] = adj[(size_t)j * 1024 + i] / g_f[O_CSUM + i];
}

// adj fp32 -> bf16 hi/lo (non-transposed; A operand is m-major rows)
__global__ void k_cvtAdj() {
    const size_t idx = (size_t)blockIdx.x * 256 + threadIdx.x;
    const int z = blockIdx.y;
    const float v = g_f[(z ? O_ADJB : O_ADJF) + idx];
    const __nv_bfloat16 h = __float2bfloat16(v);
    g_b[(size_t)(z * 2) * NS + idx] = h;
    g_b[(size_t)(z * 2 + 1) * NS + idx] = __float2bfloat16(v - __bfloat162float(h));
}

// fp32 plane [k][n] -> transposed bf16 hi/lo planes [n][k]
__global__ void k_cvtT(size_t inOff, size_t inStr, int outBase, int outStr) {
    const int z = blockIdx.z;
    const float* __restrict__ in = g_f + inOff + (size_t)z * inStr;
    __nv_bfloat16* hi = g_b + (size_t)(outBase + z * outStr) * NS;
    __nv_bfloat16* lo = hi + NS;
    __shared__ float t[32][33];
    const int bx = blockIdx.x * 32, by = blockIdx.y * 32;
    const int tx = threadIdx.x, ty = threadIdx.y;
#pragma unroll
    for (int i = 0; i < 4; i++)
        t[ty + i * 8][tx] = in[(size_t)(by + ty + i * 8) * 1024 + bx + tx];
    __syncthreads();
#pragma unroll
    for (int i = 0; i < 4; i++) {
        const int n = bx + ty + i * 8, k = by + tx;
        const float v = t[tx][ty + i * 8];
        const __nv_bfloat16 h = __float2bfloat16(v);
        hi[(size_t)n * 1024 + k] = h;
        lo[(size_t)n * 1024 + k] = __float2bfloat16(v - __bfloat162float(h));
    }
}

// ---------------------------------------------------------------------------
// Encoder
// ---------------------------------------------------------------------------
__global__ void k_encoder(const float* __restrict__ x, const float* __restrict__ W,
                          const float* __restrict__ bias, const float* __restrict__ emb) {
    __shared__ float xs[16][8];
    __shared__ float Ws[8][64];
    const int n = blockIdx.x, t = blockIdx.y, tid = threadIdx.x;
    if (tid < 128) {
        const int b = tid >> 3, f = tid & 7;
        xs[b][f] = x[((size_t)(b * Tt + t) * Nn + n) * Ff + f];
    }
    {
        const int i0 = tid, i1 = tid + 256;
        Ws[i0 >> 6][i0 & 63] = W[i0];
        Ws[i1 >> 6][i1 & 63] = W[i1];
    }
    __syncthreads();
    const int h = tid & 63, bq = tid >> 6;
    const float base = bias[h] + emb[(size_t)n * 64 + h];
    float* o = g_f + O_XENC + (size_t)t * NS + (size_t)n * 1024;
#pragma unroll
    for (int i = 0; i < 4; i++) {
        const int b = bq * 4 + i;
        float acc = base;
#pragma unroll
        for (int f = 0; f < 8; f++) acc += xs[b][f] * Ws[f][h];
        o[b * 64 + h] = acc;
    }
}

// ---------------------------------------------------------------------------
// Tensor-core hop GEMM (mma.sync bf16, cp.async double-buffered):
// C(z) = A(z) @ X(z), 3-term bf16 split, fp32 accum. 128x128 tile/CTA,
// 8 warps (2m x 4n), BK=32, 96 chunks. Smem rows 40 bf16 (80B pitch).
// tBase >= 0: epilogue also emits transposed bf16 hi/lo planes of C
// (plane [bh][node]) at tBase + z*tStr — fuses k_cvtT for hop-1 outputs.
// ---------------------------------------------------------------------------
__global__ void __launch_bounds__(256) k_tc(int aP0, int aP1, int aSel,
                                            int xBase, int xStr,
                                            size_t cOff, size_t cStr,
                                            int tBase, int tStr) {
    // union: 2 pipeline stages (2 x 20480B: A tile + B tile) | transpose stage (33792B)
    __shared__ __align__(16) char sm[41984];
    const int tid = threadIdx.x, wid = tid >> 5, lane = tid & 31;
    const int z = blockIdx.z;
    const int m0 = blockIdx.y * 128, n0 = blockIdx.x * 128;
    const int aP = (aSel && (z & 1)) ? aP1 : aP0;
    const __nv_bfloat16* __restrict__ Ahi = g_b + (size_t)aP * NS;
    const __nv_bfloat16* __restrict__ Alo = Ahi + NS;
    const __nv_bfloat16* __restrict__ Xhi = g_b + (size_t)(xBase + xStr * z) * NS;
    const __nv_bfloat16* __restrict__ Xlo = Xhi + NS;
    float* __restrict__ C = g_f + cOff + (size_t)z * cStr;

    const int wm = (wid & 1) * 64, wn = (wid >> 1) * 32;
    const uint32_t smBase = smem_u32(sm);
    const int lrow = lane & 15, lkh = (lane >> 4) * 8;

    float acc[4][4][4];
#pragma unroll
    for (int mi = 0; mi < 4; mi++)
#pragma unroll
        for (int ni = 0; ni < 4; ni++)
#pragma unroll
            for (int q = 0; q < 4; q++) acc[mi][ni][q] = 0.f;

    const int crow = tid >> 2, cEl = (tid & 3) * 8;
    const uint32_t cBy = (tid & 3) * 16;

    // issue one BK=32 chunk (A + B tiles) into pipeline stage `buf`
    auto issue_chunk = [&](int c, int buf) {
        const int s = c >> 5;
        const int kc = (c & 31) * 32;
        const __nv_bfloat16* Ap = (s < 2) ? Ahi : Alo;
        const __nv_bfloat16* Xp = (s == 1) ? Xlo : Xhi;
        const uint32_t stage = smBase + buf * 20480;
#pragma unroll
        for (int it = 0; it < 2; it++) {
            const int row = crow + it * 64;
            cp16(stage + row * 80 + cBy, Ap + (size_t)(m0 + row) * 1024 + kc + cEl);
            cp16(stage + 10240 + row * 80 + cBy, Xp + (size_t)(n0 + row) * 1024 + kc + cEl);
        }
        asm volatile("cp.async.commit_group;");
    };

    issue_chunk(0, 0);
#pragma unroll 1
    for (int c = 0; c < 96; c++) {
        if (c + 1 < 96) {
            issue_chunk(c + 1, (c + 1) & 1);
            asm volatile("cp.async.wait_group 1;");
        } else {
            asm volatile("cp.async.wait_group 0;");
        }
        __syncthreads();
        const uint32_t aB = smBase + (c & 1) * 20480;
        const uint32_t bB = aB + 10240;
#pragma unroll
        for (int ks = 0; ks < 2; ks++) {
            const int kb = ks * 16 + lkh;
            uint32_t a[4][4], b[2][4];
#pragma unroll
            for (int mi = 0; mi < 4; mi++) {
                const uint32_t ad = aB + (uint32_t)((wm + mi * 16 + lrow) * 80 + kb * 2);
                asm volatile("ldmatrix.sync.aligned.m8n8.x4.shared.b16 {%0,%1,%2,%3}, [%4];"
                    : "=r"(a[mi][0]), "=r"(a[mi][1]), "=r"(a[mi][2]), "=r"(a[mi][3]) : "r"(ad));
            }
#pragma unroll
            for (int nb = 0; nb < 2; nb++) {
                const uint32_t bd = bB + (uint32_t)((wn + nb * 16 + lrow) * 80 + kb * 2);
                asm volatile("ldmatrix.sync.aligned.m8n8.x4.shared.b16 {%0,%1,%2,%3}, [%4];"
                    : "=r"(b[nb][0]), "=r"(b[nb][1]), "=r"(b[nb][2]), "=r"(b[nb][3]) : "r"(bd));
            }
#pragma unroll
            for (int mi = 0; mi < 4; mi++)
#pragma unroll
                for (int ni = 0; ni < 4; ni++) {
                    const int nb = ni >> 1, hl = ni & 1;
                    mma16816(acc[mi][ni], a[mi], b[nb][hl], b[nb][2 + hl]);
                }
        }
        __syncthreads();
    }

    // fp32 epilogue
    const int er = lane >> 2, ec = (lane & 3) * 2;
#pragma unroll
    for (int mi = 0; mi < 4; mi++)
#pragma unroll
        for (int ni = 0; ni < 4; ni++) {
            const int row = m0 + wm + mi * 16 + er;
            const int col = n0 + wn + ni * 8 + ec;
            *(float2*)(C + (size_t)row * 1024 + col) = make_float2(acc[mi][ni][0], acc[mi][ni][1]);
            *(float2*)(C + (size_t)(row + 8) * 1024 + col) = make_float2(acc[mi][ni][2], acc[mi][ni][3]);
        }

    // fused transpose + bf16 hi/lo emit (replaces k_cvtT for this output)
    if (tBase >= 0) {
        float* sT = (float*)sm;   // [64 cols][132 rows]
        __nv_bfloat16* hiP = g_b + (size_t)(tBase + z * tStr) * NS;
        __nv_bfloat16* loP = hiP + NS;
#pragma unroll 1
        for (int half = 0; half < 2; half++) {
            __syncthreads();
            if ((wn >> 6) == half) {
                const int cb = wn & 63;
#pragma unroll
                for (int mi = 0; mi < 4; mi++)
#pragma unroll
                    for (int ni = 0; ni < 4; ni++) {
                        const int cl = cb + ni * 8 + ec;
                        const int r = wm + mi * 16 + er;
                        sT[cl * 132 + r]           = acc[mi][ni][0];
                        sT[(cl + 1) * 132 + r]     = acc[mi][ni][1];
                        sT[cl * 132 + r + 8]       = acc[mi][ni][2];
                        sT[(cl + 1) * 132 + r + 8] = acc[mi][ni][3];
                    }
            }
            __syncthreads();
#pragma unroll
            for (int j = 0; j < 8; j++) {
                const int cl = wid * 8 + j;
                const float4 v = *(const float4*)&sT[cl * 132 + lane * 4];
                __nv_bfloat16 h0 = __float2bfloat16(v.x), h1 = __float2bfloat16(v.y);
                __nv_bfloat16 h2 = __float2bfloat16(v.z), h3 = __float2bfloat16(v.w);
                __nv_bfloat16 l0 = __float2bfloat16(v.x - __bfloat162float(h0));
                __nv_bfloat16 l1 = __float2bfloat16(v.y - __bfloat162float(h1));
                __nv_bfloat16 l2 = __float2bfloat16(v.z - __bfloat162float(h2));
                __nv_bfloat16 l3 = __float2bfloat16(v.w - __bfloat162float(h3));
                ushort4 hv = make_ushort4(bfbits(h0), bfbits(h1), bfbits(h2), bfbits(h3));
                ushort4 lv = make_ushort4(bfbits(l0), bfbits(l1), bfbits(l2), bfbits(l3));
                const size_t go = (size_t)(n0 + half * 64 + cl) * 1024 + m0 + lane * 4;
                *(uint2*)(hiP + go) = *(uint2*)&hv;
                *(uint2*)(loP + go) = *(uint2*)&lv;
            }
        }
    }
}

// ---------------------------------------------------------------------------
// Gate gather-GEMM (FFMA2) + fused epilogues (unchanged, passing)
// ---------------------------------------------------------------------------
struct COffs { size_t o[8]; };

__device__ __forceinline__ u64 pack2(float x) {
    u64 r;
    asm("mov.b64 %0, {%1, %1};" : "=l"(r) : "r"(__float_as_uint(x)));
    return r;
}
__device__ __forceinline__ void ffma2(u64& c, u64 a, u64 b) {
    asm("fma.rn.f32x2 %0, %1, %2, %0;" : "+l"(c) : "l"(a), "l"(b));
}
__device__ __forceinline__ float2 up2(u64 v) {
    float2 f;
    unsigned lo, hi;
    asm("mov.b64 {%0, %1}, %2;" : "=r"(lo), "=r"(hi) : "l"(v));
    f.x = __uint_as_float(lo); f.y = __uint_as_float(hi);
    return f;
}

__global__ void __launch_bounds__(256) k_gate(COffs ch, int nch,
        const float* __restrict__ W0, const float* __restrict__ b0,
        const float* __restrict__ W1, const float* __restrict__ b1,
        size_t oOut0, size_t oOut1, int mode, int two) {
    __shared__ float As[64][17];
    __shared__ float Ws0[16][68];
    __shared__ float Ws1[16][68];
    const int tid = threadIdx.x;
    const int g0 = blockIdx.x * 64;
    const int tx = tid & 15, ty = tid >> 4;
    const int ar = tid >> 2, kq = (tid & 3) * 4;
    const size_t abase = (size_t)(g0 + ar) * 64;
    const int wr = tid >> 4, wc = (tid & 15) * 4;
    u64 acc0[4][2], acc1[4][2];
#pragma unroll
    for (int i = 0; i < 4; i++) { acc0[i][0] = acc0[i][1] = 0ULL; acc1[i][0] = acc1[i][1] = 0ULL; }
    const int K = nch * 64;
    for (int k0 = 0; k0 < K; k0 += 16) {
        const float4 av = *(const float4*)(g_f + ch.o[k0 >> 6] + abase + (k0 & 63) + kq);
        const float4 w0 = *(const float4*)(W0 + (size_t)(k0 + wr) * 64 + wc);
        float4 w1 = make_float4(0.f, 0.f, 0.f, 0.f);
        if (two) w1 = *(const float4*)(W1 + (size_t)(k0 + wr) * 64 + wc);
        __syncthreads();
        As[ar][kq + 0] = av.x; As[ar][kq + 1] = av.y; As[ar][kq + 2] = av.z; As[ar][kq + 3] = av.w;
        *(float4*)&Ws0[wr][wc] = w0;
        if (two) *(float4*)&Ws1[wr][wc] = w1;
        __syncthreads();
#pragma unroll
        for (int kk = 0; kk < 16; kk++) {
            u64 ap[4];
#pragma unroll
            for (int i = 0; i < 4; i++) ap[i] = pack2(As[ty * 4 + i][kk]);
            const float4 v0 = *(const float4*)&Ws0[kk][tx * 4];
            const u64 wp0 = ((const u64*)&v0)[0], wp1 = ((const u64*)&v0)[1];
#pragma unroll
            for (int i = 0; i < 4; i++) { ffma2(acc0[i][0], ap[i], wp0); ffma2(acc0[i][1], ap[i], wp1); }
            if (two) {
                const float4 v1 = *(const float4*)&Ws1[kk][tx * 4];
                const u64 xp0 = ((const u64*)&v1)[0], xp1 = ((const u64*)&v1)[1];
#pragma unroll
                for (int i = 0; i < 4; i++) { ffma2(acc1[i][0], ap[i], xp0); ffma2(acc1[i][1], ap[i], xp1); }
            }
        }
    }
    const float4 bias0 = *(const float4*)(b0 + tx * 4);
    float4 bias1 = bias0;
    if (two) bias1 = *(const float4*)(b1 + tx * 4);
#pragma unroll
    for (int i = 0; i < 4; i++) {
        const int row = g0 + ty * 4 + i;
        const size_t eo = (size_t)row * 64 + tx * 4;
        float pre0[4], pre1[4];
        { const float2 a = up2(acc0[i][0]), b = up2(acc0[i][1]);
          pre0[0] = a.x + bias0.x; pre0[1] = a.y + bias0.y; pre0[2] = b.x + bias0.z; pre0[3] = b.y + bias0.w; }
        { const float2 a = up2(acc1[i][0]), b = up2(acc1[i][1]);
          pre1[0] = a.x + bias1.x; pre1[1] = a.y + bias1.y; pre1[2] = b.x + bias1.z; pre1[3] = b.y + bias1.w; }
        if (mode == 1) {
            const float4 hv = *(const float4*)(g_f + O_H + eo);
            const float h[4] = {hv.x, hv.y, hv.z, hv.w};
            float4 rh, uo;
            float* prh = (float*)&rh; float* puo = (float*)&uo;
#pragma unroll
            for (int j = 0; j < 4; j++) {
                const float r = 1.0f / (1.0f + expf(-pre0[j]));
                const float u = 1.0f / (1.0f + expf(-pre1[j]));
                prh[j] = r * h[j]; puo[j] = u;
            }
            *(float4*)(g_f + oOut0 + eo) = rh;
            *(float4*)(g_f + oOut1 + eo) = uo;
        } else if (mode == 2) {
            const float4 hv = *(const float4*)(g_f + O_H + eo);
            const float4 uv = *(const float4*)(g_f + O_U + eo);
            const float h[4] = {hv.x, hv.y, hv.z, hv.w};
            const float u[4] = {uv.x, uv.y, uv.z, uv.w};
            float4 hn; float* phn = (float*)&hn;
#pragma unroll
            for (int j = 0; j < 4; j++) {
                const float c = tanhf(pre0[j]);
                phn[j] = u[j] * h[j] + (1.0f - u[j]) * c;
            }
            *(float4*)(g_f + O_H + eo) = hn;
        } else {
            *(float4*)(g_f + oOut0 + eo) = make_float4(pre0[0], pre0[1], pre0[2], pre0[3]);
        }
    }
}

__global__ void k_zero(size_t o) {
    g_f[o + (size_t)blockIdx.x * 256 + threadIdx.x] = 0.f;
}

// ---------------------------------------------------------------------------
// Sparse DiffConv hop (deterministic): one block per node n.
// ---------------------------------------------------------------------------
__global__ void __launch_bounds__(256) k_gather(const int* __restrict__ sel,
        const int* __restrict__ oth, const float* __restrict__ w,
        size_t oIn, size_t oOut) {
    const int n = blockIdx.x, tid = threadIdx.x;
    __shared__ int   cnts[257];
    __shared__ int   s_o[2048];
    __shared__ float s_w[2048];
    __shared__ float red[256];
    __shared__ float s_inv;
    int c0 = 0;
    for (int e = tid; e < Ee; e += 256) c0 += (sel[e] == n);
    cnts[tid + 1] = c0;
    if (tid == 0) cnts[0] = 0;
    __syncthreads();
    if (tid == 0) { int a = 0; for (int i = 1; i <= 256; i++) { a += cnts[i]; cnts[i] = a; } }
    __syncthreads();
    int off = cnts[tid];
    for (int e = tid; e < Ee; e += 256)
        if (sel[e] == n) { if (off < 2048) { s_o[off] = oth[e]; s_w[off] = w[e]; } off++; }
    __syncthreads();
    int M = cnts[256]; if (M > 2048) M = 2048;
    float dacc = 0.f;
    for (int m = tid; m < M; m += 256) dacc += s_w[m];
    red[tid] = dacc; __syncthreads();
    for (int s = 128; s > 0; s >>= 1) {
        if (tid < s) red[tid] += red[tid + s];
        __syncthreads();
    }
    if (tid == 0) s_inv = red[0] > 0.f ? 1.f / red[0] : 0.f;
    __syncthreads();
    const float inv = s_inv;
    const float4* in4 = (const float4*)(g_f + oIn);
    float4 acc = make_float4(0.f, 0.f, 0.f, 0.f);
    for (int m = 0; m < M; m++) {
        const float wm = s_w[m];
        const float4 v = in4[(size_t)s_o[m] * 256 + tid];
        acc.x += v.x * wm; acc.y += v.y * wm; acc.z += v.z * wm; acc.w += v.w * wm;
    }
    acc.x *= inv; acc.y *= inv; acc.z *= inv; acc.w *= inv;
    ((float4*)(g_f + oOut + (size_t)n * 1024))[tid] = acc;
}

// ---------------------------------------------------------------------------
// Decoder
// ---------------------------------------------------------------------------
__global__ void k_dec(const float* __restrict__ Wd, const float* __restrict__ bd,
                      float* __restrict__ out) {
    __shared__ float zs[64];
    const int g = blockIdx.x, c = threadIdx.x;   // 96 threads
    if (c < 64) zs[c] = g_f[O_Z + (size_t)g * 64 + c];
    __syncthreads();
    float a = bd[c];
#pragma unroll
    for (int h = 0; h < 64; h++) a += zs[h] * Wd[h * 96 + c];
    const int b = g & 15, n = g >> 4, t = c >> 3, f = c & 7;
    out[(((size_t)b * 12 + t) * 1024 + n) * 8 + f] = a;
}

// ---------------------------------------------------------------------------
// Launcher
// ---------------------------------------------------------------------------
extern "C" void kernel_launch(void* const* d_in, const int* in_sizes, int n_in,
                              void* d_out, int out_size) {
    const float* x      = (const float*)d_in[0];
    const int*   ei     = (const int*)d_in[1];
    const float* ew     = (const float*)d_in[2];
    const float* adj    = (const float*)d_in[3];
    const float* W_enc  = (const float*)d_in[4];
    const float* b_enc  = (const float*)d_in[5];
    const float* emb    = (const float*)d_in[6];
    const float* W_r    = (const float*)d_in[7];
    const float* b_r    = (const float*)d_in[8];
    const float* W_u    = (const float*)d_in[9];
    const float* b_u    = (const float*)d_in[10];
    const float* W_c    = (const float*)d_in[11];
    const float* b_c    = (const float*)d_in[12];
    const float* W_diff = (const float*)d_in[13];
    const float* b_diff = (const float*)d_in[14];
    const float* W_dec  = (const float*)d_in[15];
    const float* b_dec  = (const float*)d_in[16];
    float* out = (float*)d_out;
    const int* src = ei;
    const int* dst = ei + Ee;

    const dim3 cvtB(32, 8);

    // supports + encoder + bf16 conversions
    k_rowsum<<<1024, 256>>>(adj);
    k_colsum<<<4, 256>>>(adj);
    k_norm<<<4096, 256>>>(adj);
    k_encoder<<<dim3(1024, 12), 256>>>(x, W_enc, b_enc, emb);
    k_cvtAdj<<<dim3(4096, 2), 256>>>();
    k_cvtT<<<dim3(32, 32, 12), cvtB>>>(O_XENC, NS, PB_XET, 2);

    // x-side hops for all t, batched (tensor cores; hop1 emits T planes)
    const dim3 gt12(8, 8, 12);
    k_tc<<<gt12, 256>>>(PB_AF, PB_AF, 0, PB_XET, 2, O_XF1, NS, PB_XF1T, 2);
    k_tc<<<gt12, 256>>>(PB_AB, PB_AB, 0, PB_XET, 2, O_XB1, NS, PB_XB1T, 2);
    k_tc<<<gt12, 256>>>(PB_AF, PB_AF, 0, PB_XF1T, 2, O_XF2, NS, -1, 0);
    k_tc<<<gt12, 256>>>(PB_AB, PB_AB, 0, PB_XB1T, 2, O_XB2, NS, -1, 0);

    // GRU scan
    k_zero<<<4096, 256>>>(O_H);
    const dim3 gt2(8, 8, 2);
    for (int t = 0; t < 12; t++) {
        k_cvtT<<<dim3(32, 32, 1), cvtB>>>(O_H, 0, PB_HT, 0);
        k_tc<<<gt2, 256>>>(PB_AF, PB_AB, 1, PB_HT, 0, O_HHOP, 2 * NS, PB_HF1T, 2);
        k_tc<<<gt2, 256>>>(PB_AF, PB_AB, 1, PB_HF1T, 2, O_HHOP + NS, 2 * NS, -1, 0);
        COffs cg;
        cg.o[0] = O_XF1 + (size_t)t * NS; cg.o[1] = O_HHOP;
        cg.o[2] = O_XF2 + (size_t)t * NS; cg.o[3] = O_HHOP + NS;
        cg.o[4] = O_XB1 + (size_t)t * NS; cg.o[5] = O_HHOP + 2 * NS;
        cg.o[6] = O_XB2 + (size_t)t * NS; cg.o[7] = O_HHOP + 3 * NS;
        k_gate<<<256, 256>>>(cg, 8, W_r, b_r, W_u, b_u, O_RH, O_U, 1, 1);
        k_cvtT<<<dim3(32, 32, 1), cvtB>>>(O_RH, 0, PB_RHT, 0);
        k_tc<<<gt2, 256>>>(PB_AF, PB_AB, 1, PB_RHT, 0, O_RHHOP, 2 * NS, PB_RHF1T, 2);
        k_tc<<<gt2, 256>>>(PB_AF, PB_AB, 1, PB_RHF1T, 2, O_RHHOP + NS, 2 * NS, -1, 0);
        COffs cc = cg;
        cc.o[1] = O_RHHOP;          cc.o[3] = O_RHHOP + NS;
        cc.o[5] = O_RHHOP + 2 * NS; cc.o[7] = O_RHHOP + 3 * NS;
        k_gate<<<256, 256>>>(cc, 8, W_c, b_c, W_c, b_c, O_H, O_H, 2, 0);
    }

    // sparse DiffConv readout
    k_gather<<<1024, 256>>>(dst, src, ew, O_H, O_F1);
    k_gather<<<1024, 256>>>(dst, src, ew, O_F1, O_F2);
    k_gather<<<1024, 256>>>(src, dst, ew, O_H, O_B1);
    k_gather<<<1024, 256>>>(src, dst, ew, O_B1, O_B2);
    COffs cz;
    cz.o[0] = O_H; cz.o[1] = O_F1; cz.o[2] = O_F2; cz.o[3] = O_B1; cz.o[4] = O_B2;
    cz.o[5] = cz.o[6] = cz.o[7] = O_H;
    k_gate<<<256, 256>>>(cz, 5, W_diff, b_diff, W_diff, b_diff, O_Z, O_Z, 0, 0);

    // decoder
    k_dec<<<16384, 96>>>(W_dec, b_dec, out);
}

// round 15
// speedup vs baseline: 1.7062x; 1.1340x over previous
#include <cuda_runtime.h>
#include <cuda_bf16.h>
#include <math.h>
#include <stdint.h>

typedef unsigned long long u64;

// ---------------------------------------------------------------------------
// Problem constants
// ---------------------------------------------------------------------------
constexpr int    Nn = 1024;
constexpr int    Tt = 12;
constexpr int    Ff = 8;
constexpr int    Ee = 32768;
constexpr size_t NS = (size_t)Nn * 1024;   // 1M floats per plane [node][b*64+h]

// ---------------------------------------------------------------------------
// fp32 scratch arena
// ---------------------------------------------------------------------------
constexpr size_t O_ADJF  = 0;
constexpr size_t O_ADJB  = 1 * NS;
constexpr size_t O_XENC  = 2 * NS;    // 12 planes
constexpr size_t O_XF1   = 14 * NS;   // 12
constexpr size_t O_XF2   = 26 * NS;   // 12
constexpr size_t O_XB1   = 38 * NS;   // 12
constexpr size_t O_XB2   = 50 * NS;   // 12
constexpr size_t O_H     = 62 * NS;
constexpr size_t O_HHOP  = 63 * NS;   // 4: [HF1, HF2, HB1, HB2]
constexpr size_t O_RH    = 67 * NS;
constexpr size_t O_RHHOP = 68 * NS;   // 4
constexpr size_t O_U     = 72 * NS;
constexpr size_t O_F1    = 73 * NS;
constexpr size_t O_F2    = 74 * NS;
constexpr size_t O_B1    = 75 * NS;
constexpr size_t O_B2    = 76 * NS;
constexpr size_t O_Z     = 77 * NS;
constexpr size_t O_RSUM  = 78 * NS;
constexpr size_t O_CSUM  = 78 * NS + 1024;
constexpr size_t F_TOT   = 78 * NS + 2048;

__device__ float g_f[F_TOT];

// ---------------------------------------------------------------------------
// bf16 plane arena (hi/lo split pairs; "T" planes are transposed [bh][node])
// ---------------------------------------------------------------------------
constexpr int PB_AF = 0, PB_AB = 2, PB_XET = 4, PB_XF1T = 28, PB_XB1T = 52;
constexpr int PB_HT = 76, PB_HF1T = 78, PB_RHT = 82, PB_RHF1T = 84;
constexpr int PB_NUM = 88;

__device__ __align__(256) __nv_bfloat16 g_b[(size_t)PB_NUM * NS];

// ---------------------------------------------------------------------------
// helpers
// ---------------------------------------------------------------------------
__device__ __forceinline__ uint32_t smem_u32(const void* p) {
    uint32_t a;
    asm("{ .reg .u64 t; cvta.to.shared.u64 t, %1; cvt.u32.u64 %0, t; }" : "=r"(a) : "l"(p));
    return a;
}
__device__ __forceinline__ void mma16816(float* c, const uint32_t* a, uint32_t b0, uint32_t b1) {
    asm volatile("mma.sync.aligned.m16n8k16.row.col.f32.bf16.bf16.f32 "
        "{%0,%1,%2,%3}, {%4,%5,%6,%7}, {%8,%9}, {%0,%1,%2,%3};"
        : "+f"(c[0]), "+f"(c[1]), "+f"(c[2]), "+f"(c[3])
        : "r"(a[0]), "r"(a[1]), "r"(a[2]), "r"(a[3]), "r"(b0), "r"(b1));
}
__device__ __forceinline__ void cp16(uint32_t dst, const void* src) {
    asm volatile("cp.async.cg.shared.global [%0], [%1], 16;" :: "r"(dst), "l"(src));
}
__device__ __forceinline__ void ldm4(uint32_t* r, uint32_t addr) {
    asm volatile("ldmatrix.sync.aligned.m8n8.x4.shared.b16 {%0,%1,%2,%3}, [%4];"
        : "=r"(r[0]), "=r"(r[1]), "=r"(r[2]), "=r"(r[3]) : "r"(addr));
}
__device__ __forceinline__ unsigned short bfbits(__nv_bfloat16 h) {
    return *(unsigned short*)&h;
}

// ---------------------------------------------------------------------------
// Adjacency normalization
// ---------------------------------------------------------------------------
__global__ void k_rowsum(const float* __restrict__ adj) {
    const int i = blockIdx.x;
    __shared__ float sm[256];
    float a = 0.f;
    for (int j = threadIdx.x; j < 1024; j += 256) a += adj[(size_t)i * 1024 + j];
    sm[threadIdx.x] = a; __syncthreads();
    for (int s = 128; s > 0; s >>= 1) {
        if (threadIdx.x < s) sm[threadIdx.x] += sm[threadIdx.x + s];
        __syncthreads();
    }
    if (threadIdx.x == 0) g_f[O_RSUM + i] = sm[0];
}

__global__ void k_colsum(const float* __restrict__ adj) {
    const int j = blockIdx.x * 256 + threadIdx.x;
    float a = 0.f;
    for (int i = 0; i < 1024; i++) a += adj[(size_t)i * 1024 + j];
    g_f[O_CSUM + j] = a;
}

__global__ void k_norm(const float* __restrict__ adj) {
    const size_t idx = (size_t)blockIdx.x * 256 + threadIdx.x;
    const int i = (int)(idx >> 10), j = (int)(idx & 1023);
    g_f[O_ADJF + idx] = adj[idx] / g_f[O_RSUM + i];
    g_f[O_ADJB + idx] = adj[(size_t)j * 1024 + i] / g_f[O_CSUM + i];
}

// adj fp32 -> bf16 hi/lo (non-transposed; A operand is m-major rows)
__global__ void k_cvtAdj() {
    const size_t idx = (size_t)blockIdx.x * 256 + threadIdx.x;
    const int z = blockIdx.y;
    const float v = g_f[(z ? O_ADJB : O_ADJF) + idx];
    const __nv_bfloat16 h = __float2bfloat16(v);
    g_b[(size_t)(z * 2) * NS + idx] = h;
    g_b[(size_t)(z * 2 + 1) * NS + idx] = __float2bfloat16(v - __bfloat162float(h));
}

// fp32 plane [k][n] -> transposed bf16 hi/lo planes [n][k]
__global__ void k_cvtT(size_t inOff, size_t inStr, int outBase, int outStr) {
    const int z = blockIdx.z;
    const float* __restrict__ in = g_f + inOff + (size_t)z * inStr;
    __nv_bfloat16* hi = g_b + (size_t)(outBase + z * outStr) * NS;
    __nv_bfloat16* lo = hi + NS;
    __shared__ float t[32][33];
    const int bx = blockIdx.x * 32, by = blockIdx.y * 32;
    const int tx = threadIdx.x, ty = threadIdx.y;
#pragma unroll
    for (int i = 0; i < 4; i++)
        t[ty + i * 8][tx] = in[(size_t)(by + ty + i * 8) * 1024 + bx + tx];
    __syncthreads();
#pragma unroll
    for (int i = 0; i < 4; i++) {
        const int n = bx + ty + i * 8, k = by + tx;
        const float v = t[tx][ty + i * 8];
        const __nv_bfloat16 h = __float2bfloat16(v);
        hi[(size_t)n * 1024 + k] = h;
        lo[(size_t)n * 1024 + k] = __float2bfloat16(v - __bfloat162float(h));
    }
}

// zero two consecutive bf16 planes starting at `plane`
__global__ void k_zerob(int plane) {
    ((uint4*)(g_b + (size_t)plane * NS))[(size_t)blockIdx.x * 256 + threadIdx.x] =
        make_uint4(0, 0, 0, 0);
}

// ---------------------------------------------------------------------------
// Encoder
// ---------------------------------------------------------------------------
__global__ void k_encoder(const float* __restrict__ x, const float* __restrict__ W,
                          const float* __restrict__ bias, const float* __restrict__ emb) {
    __shared__ float xs[16][8];
    __shared__ float Ws[8][64];
    const int n = blockIdx.x, t = blockIdx.y, tid = threadIdx.x;
    if (tid < 128) {
        const int b = tid >> 3, f = tid & 7;
        xs[b][f] = x[((size_t)(b * Tt + t) * Nn + n) * Ff + f];
    }
    {
        const int i0 = tid, i1 = tid + 256;
        Ws[i0 >> 6][i0 & 63] = W[i0];
        Ws[i1 >> 6][i1 & 63] = W[i1];
    }
    __syncthreads();
    const int h = tid & 63, bq = tid >> 6;
    const float base = bias[h] + emb[(size_t)n * 64 + h];
    float* o = g_f + O_XENC + (size_t)t * NS + (size_t)n * 1024;
#pragma unroll
    for (int i = 0; i < 4; i++) {
        const int b = bq * 4 + i;
        float acc = base;
#pragma unroll
        for (int f = 0; f < 8; f++) acc += xs[b][f] * Ws[f][h];
        o[b * 64 + h] = acc;
    }
}

// ---------------------------------------------------------------------------
// Tensor-core hop GEMM v2 (mma.sync bf16, cp.async 2-stage, 4-tile chunks):
// C(z) = A(z)@X(z) = Ahi·Xhi + Ahi·Xlo + Alo·Xhi, fp32 accum.
// Each BK=32 chunk loads {Ahi,Alo,Xhi,Xlo} once (40KB stage) and runs all 3
// split passes reusing fragments. 128x128 tile/CTA, 8 warps (2m x 4n).
// Dynamic smem 81920B (2 stages). tBase >= 0: epilogue also emits transposed
// bf16 hi/lo planes of C ([bh][node]) at tBase + z*tStr.
// ---------------------------------------------------------------------------
__global__ void __launch_bounds__(256) k_tc(int aP0, int aP1, int aSel,
                                            int xBase, int xStr,
                                            size_t cOff, size_t cStr,
                                            int tBase, int tStr) {
    extern __shared__ __align__(16) char sm[];
    const int tid = threadIdx.x, wid = tid >> 5, lane = tid & 31;
    const int z = blockIdx.z;
    const int m0 = blockIdx.y * 128, n0 = blockIdx.x * 128;
    const int aP = (aSel && (z & 1)) ? aP1 : aP0;
    const __nv_bfloat16* __restrict__ Ahi = g_b + (size_t)aP * NS;
    const __nv_bfloat16* __restrict__ Alo = Ahi + NS;
    const __nv_bfloat16* __restrict__ Xhi = g_b + (size_t)(xBase + xStr * z) * NS;
    const __nv_bfloat16* __restrict__ Xlo = Xhi + NS;
    float* __restrict__ C = g_f + cOff + (size_t)z * cStr;

    const int wm = (wid & 1) * 64, wn = (wid >> 1) * 32;
    const uint32_t smBase = smem_u32(sm);
    const int lrow = lane & 15, lkh = (lane >> 4) * 8;

    float acc[4][4][4];
#pragma unroll
    for (int mi = 0; mi < 4; mi++)
#pragma unroll
        for (int ni = 0; ni < 4; ni++)
#pragma unroll
            for (int q = 0; q < 4; q++) acc[mi][ni][q] = 0.f;

    const int crow = tid >> 2, cEl = (tid & 3) * 8;
    const uint32_t cBy = (tid & 3) * 16;

    // one BK=32 chunk: 4 tiles {Ahi, Alo, Xhi, Xlo}, 80B row pitch
    auto issue_chunk = [&](int kc, int buf) {
        const uint32_t st = smBase + buf * 40960;
#pragma unroll
        for (int it = 0; it < 2; it++) {
            const int row = crow + it * 64;
            const size_t ga = (size_t)(m0 + row) * 1024 + kc + cEl;
            const size_t gx = (size_t)(n0 + row) * 1024 + kc + cEl;
            const uint32_t so = row * 80 + cBy;
            cp16(st + so,         Ahi + ga);
            cp16(st + 10240 + so, Alo + ga);
            cp16(st + 20480 + so, Xhi + gx);
            cp16(st + 30720 + so, Xlo + gx);
        }
        asm volatile("cp.async.commit_group;");
    };

    issue_chunk(0, 0);
#pragma unroll 1
    for (int c = 0; c < 32; c++) {
        if (c + 1 < 32) {
            issue_chunk((c + 1) * 32, (c + 1) & 1);
            asm volatile("cp.async.wait_group 1;");
        } else {
            asm volatile("cp.async.wait_group 0;");
        }
        __syncthreads();
        const uint32_t st = smBase + (c & 1) * 40960;
#pragma unroll
        for (int ks = 0; ks < 2; ks++) {
            const uint32_t kb = (uint32_t)((ks * 16 + lkh) * 2);
            uint32_t ah[4][4], al[4][4], bh[2][4], bl[2][4];
#pragma unroll
            for (int mi = 0; mi < 4; mi++)
                ldm4(ah[mi], st + (wm + mi * 16 + lrow) * 80 + kb);
#pragma unroll
            for (int nb = 0; nb < 2; nb++)
                ldm4(bh[nb], st + 20480 + (wn + nb * 16 + lrow) * 80 + kb);
#pragma unroll
            for (int mi = 0; mi < 4; mi++)
#pragma unroll
                for (int ni = 0; ni < 4; ni++) {
                    const int nb = ni >> 1, hl = ni & 1;
                    mma16816(acc[mi][ni], ah[mi], bh[nb][hl], bh[nb][2 + hl]);
                }
#pragma unroll
            for (int nb = 0; nb < 2; nb++)
                ldm4(bl[nb], st + 30720 + (wn + nb * 16 + lrow) * 80 + kb);
#pragma unroll
            for (int mi = 0; mi < 4; mi++)
#pragma unroll
                for (int ni = 0; ni < 4; ni++) {
                    const int nb = ni >> 1, hl = ni & 1;
                    mma16816(acc[mi][ni], ah[mi], bl[nb][hl], bl[nb][2 + hl]);
                }
#pragma unroll
            for (int mi = 0; mi < 4; mi++)
                ldm4(al[mi], st + 10240 + (wm + mi * 16 + lrow) * 80 + kb);
#pragma unroll
            for (int mi = 0; mi < 4; mi++)
#pragma unroll
                for (int ni = 0; ni < 4; ni++) {
                    const int nb = ni >> 1, hl = ni & 1;
                    mma16816(acc[mi][ni], al[mi], bh[nb][hl], bh[nb][2 + hl]);
                }
        }
        __syncthreads();
    }

    // fp32 epilogue
    const int er = lane >> 2, ec = (lane & 3) * 2;
#pragma unroll
    for (int mi = 0; mi < 4; mi++)
#pragma unroll
        for (int ni = 0; ni < 4; ni++) {
            const int row = m0 + wm + mi * 16 + er;
            const int col = n0 + wn + ni * 8 + ec;
            *(float2*)(C + (size_t)row * 1024 + col) = make_float2(acc[mi][ni][0], acc[mi][ni][1]);
            *(float2*)(C + (size_t)(row + 8) * 1024 + col) = make_float2(acc[mi][ni][2], acc[mi][ni][3]);
        }

    // fused transpose + bf16 hi/lo emit
    if (tBase >= 0) {
        float* sT = (float*)sm;   // [64 cols][132 rows]
        __nv_bfloat16* hiP = g_b + (size_t)(tBase + z * tStr) * NS;
        __nv_bfloat16* loP = hiP + NS;
#pragma unroll 1
        for (int half = 0; half < 2; half++) {
            __syncthreads();
            if ((wn >> 6) == half) {
                const int cb = wn & 63;
#pragma unroll
                for (int mi = 0; mi < 4; mi++)
#pragma unroll
                    for (int ni = 0; ni < 4; ni++) {
                        const int cl = cb + ni * 8 + ec;
                        const int r = wm + mi * 16 + er;
                        sT[cl * 132 + r]           = acc[mi][ni][0];
                        sT[(cl + 1) * 132 + r]     = acc[mi][ni][1];
                        sT[cl * 132 + r + 8]       = acc[mi][ni][2];
                        sT[(cl + 1) * 132 + r + 8] = acc[mi][ni][3];
                    }
            }
            __syncthreads();
#pragma unroll
            for (int j = 0; j < 8; j++) {
                const int cl = wid * 8 + j;
                const float4 v = *(const float4*)&sT[cl * 132 + lane * 4];
                __nv_bfloat16 h0 = __float2bfloat16(v.x), h1 = __float2bfloat16(v.y);
                __nv_bfloat16 h2 = __float2bfloat16(v.z), h3 = __float2bfloat16(v.w);
                __nv_bfloat16 l0 = __float2bfloat16(v.x - __bfloat162float(h0));
                __nv_bfloat16 l1 = __float2bfloat16(v.y - __bfloat162float(h1));
                __nv_bfloat16 l2 = __float2bfloat16(v.z - __bfloat162float(h2));
                __nv_bfloat16 l3 = __float2bfloat16(v.w - __bfloat162float(h3));
                ushort4 hv = make_ushort4(bfbits(h0), bfbits(h1), bfbits(h2), bfbits(h3));
                ushort4 lv = make_ushort4(bfbits(l0), bfbits(l1), bfbits(l2), bfbits(l3));
                const size_t go = (size_t)(n0 + half * 64 + cl) * 1024 + m0 + lane * 4;
                *(uint2*)(hiP + go) = *(uint2*)&hv;
                *(uint2*)(loP + go) = *(uint2*)&lv;
            }
        }
    }
}

// ---------------------------------------------------------------------------
// Gate gather-GEMM (FFMA2) + fused epilogues.
// mode 0: out0 = pre0 + b0
// mode 1: r=sig(pre0), u=sig(pre1): out0=r*h, out1=u; tEmit: RH-T planes
// mode 2: c=tanh(pre0): h = u*h + (1-u)*c in place;   tEmit: H-T planes
// ---------------------------------------------------------------------------
struct COffs { size_t o[8]; };

__device__ __forceinline__ u64 pack2(float x) {
    u64 r;
    asm("mov.b64 %0, {%1, %1};" : "=l"(r) : "r"(__float_as_uint(x)));
    return r;
}
__device__ __forceinline__ void ffma2(u64& c, u64 a, u64 b) {
    asm("fma.rn.f32x2 %0, %1, %2, %0;" : "+l"(c) : "l"(a), "l"(b));
}
__device__ __forceinline__ float2 up2(u64 v) {
    float2 f;
    unsigned lo, hi;
    asm("mov.b64 {%0, %1}, %2;" : "=r"(lo), "=r"(hi) : "l"(v));
    f.x = __uint_as_float(lo); f.y = __uint_as_float(hi);
    return f;
}
__device__ __forceinline__ void emitT(int tEmit, int bh, int n, float v) {
    const __nv_bfloat16 h = __float2bfloat16(v);
    g_b[(size_t)tEmit * NS + (size_t)bh * 1024 + n] = h;
    g_b[(size_t)(tEmit + 1) * NS + (size_t)bh * 1024 + n] =
        __float2bfloat16(v - __bfloat162float(h));
}

__global__ void __launch_bounds__(256) k_gate(COffs ch, int nch,
        const float* __restrict__ W0, const float* __restrict__ b0,
        const float* __restrict__ W1, const float* __restrict__ b1,
        size_t oOut0, size_t oOut1, int mode, int two, int tEmit) {
    __shared__ float As[64][17];
    __shared__ float Ws0[16][68];
    __shared__ float Ws1[16][68];
    const int tid = threadIdx.x;
    const int g0 = blockIdx.x * 64;
    const int tx = tid & 15, ty = tid >> 4;
    const int ar = tid >> 2, kq = (tid & 3) * 4;
    const size_t abase = (size_t)(g0 + ar) * 64;
    const int wr = tid >> 4, wc = (tid & 15) * 4;
    u64 acc0[4][2], acc1[4][2];
#pragma unroll
    for (int i = 0; i < 4; i++) { acc0[i][0] = acc0[i][1] = 0ULL; acc1[i][0] = acc1[i][1] = 0ULL; }
    const int K = nch * 64;
    for (int k0 = 0; k0 < K; k0 += 16) {
        const float4 av = *(const float4*)(g_f + ch.o[k0 >> 6] + abase + (k0 & 63) + kq);
        const float4 w0 = *(const float4*)(W0 + (size_t)(k0 + wr) * 64 + wc);
        float4 w1 = make_float4(0.f, 0.f, 0.f, 0.f);
        if (two) w1 = *(const float4*)(W1 + (size_t)(k0 + wr) * 64 + wc);
        __syncthreads();
        As[ar][kq + 0] = av.x; As[ar][kq + 1] = av.y; As[ar][kq + 2] = av.z; As[ar][kq + 3] = av.w;
        *(float4*)&Ws0[wr][wc] = w0;
        if (two) *(float4*)&Ws1[wr][wc] = w1;
        __syncthreads();
#pragma unroll
        for (int kk = 0; kk < 16; kk++) {
            u64 ap[4];
#pragma unroll
            for (int i = 0; i < 4; i++) ap[i] = pack2(As[ty * 4 + i][kk]);
            const float4 v0 = *(const float4*)&Ws0[kk][tx * 4];
            const u64 wp0 = ((const u64*)&v0)[0], wp1 = ((const u64*)&v0)[1];
#pragma unroll
            for (int i = 0; i < 4; i++) { ffma2(acc0[i][0], ap[i], wp0); ffma2(acc0[i][1], ap[i], wp1); }
            if (two) {
                const float4 v1 = *(const float4*)&Ws1[kk][tx * 4];
                const u64 xp0 = ((const u64*)&v1)[0], xp1 = ((const u64*)&v1)[1];
#pragma unroll
                for (int i = 0; i < 4; i++) { ffma2(acc1[i][0], ap[i], xp0); ffma2(acc1[i][1], ap[i], xp1); }
            }
        }
    }
    const float4 bias0 = *(const float4*)(b0 + tx * 4);
    float4 bias1 = bias0;
    if (two) bias1 = *(const float4*)(b1 + tx * 4);
#pragma unroll
    for (int i = 0; i < 4; i++) {
        const int row = g0 + ty * 4 + i;
        const int nb = row >> 4, bb = (row & 15) * 64 + tx * 4;
        const size_t eo = (size_t)row * 64 + tx * 4;
        float pre0[4], pre1[4];
        { const float2 a = up2(acc0[i][0]), b = up2(acc0[i][1]);
          pre0[0] = a.x + bias0.x; pre0[1] = a.y + bias0.y; pre0[2] = b.x + bias0.z; pre0[3] = b.y + bias0.w; }
        { const float2 a = up2(acc1[i][0]), b = up2(acc1[i][1]);
          pre1[0] = a.x + bias1.x; pre1[1] = a.y + bias1.y; pre1[2] = b.x + bias1.z; pre1[3] = b.y + bias1.w; }
        if (mode == 1) {
            const float4 hv = *(const float4*)(g_f + O_H + eo);
            const float h[4] = {hv.x, hv.y, hv.z, hv.w};
            float4 rh, uo;
            float* prh = (float*)&rh; float* puo = (float*)&uo;
#pragma unroll
            for (int j = 0; j < 4; j++) {
                const float r = 1.0f / (1.0f + expf(-pre0[j]));
                const float u = 1.0f / (1.0f + expf(-pre1[j]));
                prh[j] = r * h[j]; puo[j] = u;
            }
            *(float4*)(g_f + oOut0 + eo) = rh;
            *(float4*)(g_f + oOut1 + eo) = uo;
            if (tEmit >= 0) {
#pragma unroll
                for (int j = 0; j < 4; j++) emitT(tEmit, bb + j, nb, prh[j]);
            }
        } else if (mode == 2) {
            const float4 hv = *(const float4*)(g_f + O_H + eo);
            const float4 uv = *(const float4*)(g_f + O_U + eo);
            const float h[4] = {hv.x, hv.y, hv.z, hv.w};
            const float u[4] = {uv.x, uv.y, uv.z, uv.w};
            float4 hn; float* phn = (float*)&hn;
#pragma unroll
            for (int j = 0; j < 4; j++) {
                const float c = tanhf(pre0[j]);
                phn[j] = u[j] * h[j] + (1.0f - u[j]) * c;
            }
            *(float4*)(g_f + O_H + eo) = hn;
            if (tEmit >= 0) {
#pragma unroll
                for (int j = 0; j < 4; j++) emitT(tEmit, bb + j, nb, phn[j]);
            }
        } else {
            *(float4*)(g_f + oOut0 + eo) = make_float4(pre0[0], pre0[1], pre0[2], pre0[3]);
        }
    }
}

__global__ void k_zero(size_t o) {
    g_f[o + (size_t)blockIdx.x * 256 + threadIdx.x] = 0.f;
}

// ---------------------------------------------------------------------------
// Sparse DiffConv hop (deterministic): one block per node n.
// ---------------------------------------------------------------------------
__global__ void __launch_bounds__(256) k_gather(const int* __restrict__ sel,
        const int* __restrict__ oth, const float* __restrict__ w,
        size_t oIn, size_t oOut) {
    const int n = blockIdx.x, tid = threadIdx.x;
    __shared__ int   cnts[257];
    __shared__ int   s_o[2048];
    __shared__ float s_w[2048];
    __shared__ float red[256];
    __shared__ float s_inv;
    int c0 = 0;
    for (int e = tid; e < Ee; e += 256) c0 += (sel[e] == n);
    cnts[tid + 1] = c0;
    if (tid == 0) cnts[0] = 0;
    __syncthreads();
    if (tid == 0) { int a = 0; for (int i = 1; i <= 256; i++) { a += cnts[i]; cnts[i] = a; } }
    __syncthreads();
    int off = cnts[tid];
    for (int e = tid; e < Ee; e += 256)
        if (sel[e] == n) { if (off < 2048) { s_o[off] = oth[e]; s_w[off] = w[e]; } off++; }
    __syncthreads();
    int M = cnts[256]; if (M > 2048) M = 2048;
    float dacc = 0.f;
    for (int m = tid; m < M; m += 256) dacc += s_w[m];
    red[tid] = dacc; __syncthreads();
    for (int s = 128; s > 0; s >>= 1) {
        if (tid < s) red[tid] += red[tid + s];
        __syncthreads();
    }
    if (tid == 0) s_inv = red[0] > 0.f ? 1.f / red[0] : 0.f;
    __syncthreads();
    const float inv = s_inv;
    const float4* in4 = (const float4*)(g_f + oIn);
    float4 acc = make_float4(0.f, 0.f, 0.f, 0.f);
    for (int m = 0; m < M; m++) {
        const float wm = s_w[m];
        const float4 v = in4[(size_t)s_o[m] * 256 + tid];
        acc.x += v.x * wm; acc.y += v.y * wm; acc.z += v.z * wm; acc.w += v.w * wm;
    }
    acc.x *= inv; acc.y *= inv; acc.z *= inv; acc.w *= inv;
    ((float4*)(g_f + oOut + (size_t)n * 1024))[tid] = acc;
}

// ---------------------------------------------------------------------------
// Decoder
// ---------------------------------------------------------------------------
__global__ void k_dec(const float* __restrict__ Wd, const float* __restrict__ bd,
                      float* __restrict__ out) {
    __shared__ float zs[64];
    const int g = blockIdx.x, c = threadIdx.x;   // 96 threads
    if (c < 64) zs[c] = g_f[O_Z + (size_t)g * 64 + c];
    __syncthreads();
    float a = bd[c];
#pragma unroll
    for (int h = 0; h < 64; h++) a += zs[h] * Wd[h * 96 + c];
    const int b = g & 15, n = g >> 4, t = c >> 3, f = c & 7;
    out[(((size_t)b * 12 + t) * 1024 + n) * 8 + f] = a;
}

// ---------------------------------------------------------------------------
// Launcher
// ---------------------------------------------------------------------------
extern "C" void kernel_launch(void* const* d_in, const int* in_sizes, int n_in,
                              void* d_out, int out_size) {
    const float* x      = (const float*)d_in[0];
    const int*   ei     = (const int*)d_in[1];
    const float* ew     = (const float*)d_in[2];
    const float* adj    = (const float*)d_in[3];
    const float* W_enc  = (const float*)d_in[4];
    const float* b_enc  = (const float*)d_in[5];
    const float* emb    = (const float*)d_in[6];
    const float* W_r    = (const float*)d_in[7];
    const float* b_r    = (const float*)d_in[8];
    const float* W_u    = (const float*)d_in[9];
    const float* b_u    = (const float*)d_in[10];
    const float* W_c    = (const float*)d_in[11];
    const float* b_c    = (const float*)d_in[12];
    const float* W_diff = (const float*)d_in[13];
    const float* b_diff = (const float*)d_in[14];
    const float* W_dec  = (const float*)d_in[15];
    const float* b_dec  = (const float*)d_in[16];
    float* out = (float*)d_out;
    const int* src = ei;
    const int* dst = ei + Ee;

    const dim3 cvtB(32, 8);
    const int TC_SMEM = 81920;
    cudaFuncSetAttribute((const void*)k_tc,
                         cudaFuncAttributeMaxDynamicSharedMemorySize, TC_SMEM);

    // supports + encoder + bf16 conversions
    k_rowsum<<<1024, 256>>>(adj);
    k_colsum<<<4, 256>>>(adj);
    k_norm<<<4096, 256>>>(adj);
    k_encoder<<<dim3(1024, 12), 256>>>(x, W_enc, b_enc, emb);
    k_cvtAdj<<<dim3(4096, 2), 256>>>();
    k_cvtT<<<dim3(32, 32, 12), cvtB>>>(O_XENC, NS, PB_XET, 2);

    // x-side hops for all t, batched (hop1 emits T planes)
    const dim3 gt12(8, 8, 12);
    k_tc<<<gt12, 256, TC_SMEM>>>(PB_AF, PB_AF, 0, PB_XET, 2, O_XF1, NS, PB_XF1T, 2);
    k_tc<<<gt12, 256, TC_SMEM>>>(PB_AB, PB_AB, 0, PB_XET, 2, O_XB1, NS, PB_XB1T, 2);
    k_tc<<<gt12, 256, TC_SMEM>>>(PB_AF, PB_AF, 0, PB_XF1T, 2, O_XF2, NS, -1, 0);
    k_tc<<<gt12, 256, TC_SMEM>>>(PB_AB, PB_AB, 0, PB_XB1T, 2, O_XB2, NS, -1, 0);

    // GRU scan
    k_zero<<<4096, 256>>>(O_H);
    k_zerob<<<1024, 256>>>(PB_HT);
    const dim3 gt2(8, 8, 2);
    for (int t = 0; t < 12; t++) {
        k_tc<<<gt2, 256, TC_SMEM>>>(PB_AF, PB_AB, 1, PB_HT, 0, O_HHOP, 2 * NS, PB_HF1T, 2);
        k_tc<<<gt2, 256, TC_SMEM>>>(PB_AF, PB_AB, 1, PB_HF1T, 2, O_HHOP + NS, 2 * NS, -1, 0);
        COffs cg;
        cg.o[0] = O_XF1 + (size_t)t * NS; cg.o[1] = O_HHOP;
        cg.o[2] = O_XF2 + (size_t)t * NS; cg.o[3] = O_HHOP + NS;
        cg.o[4] = O_XB1 + (size_t)t * NS; cg.o[5] = O_HHOP + 2 * NS;
        cg.o[6] = O_XB2 + (size_t)t * NS; cg.o[7] = O_HHOP + 3 * NS;
        k_gate<<<256, 256>>>(cg, 8, W_r, b_r, W_u, b_u, O_RH, O_U, 1, 1, PB_RHT);
        k_tc<<<gt2, 256, TC_SMEM>>>(PB_AF, PB_AB, 1, PB_RHT, 0, O_RHHOP, 2 * NS, PB_RHF1T, 2);
        k_tc<<<gt2, 256, TC_SMEM>>>(PB_AF, PB_AB, 1, PB_RHF1T, 2, O_RHHOP + NS, 2 * NS, -1, 0);
        COffs cc = cg;
        cc.o[1] = O_RHHOP;          cc.o[3] = O_RHHOP + NS;
        cc.o[5] = O_RHHOP + 2 * NS; cc.o[7] = O_RHHOP + 3 * NS;
        k_gate<<<256, 256>>>(cc, 8, W_c, b_c, W_c, b_c, O_H, O_H, 2, 0, PB_HT);
    }

    // sparse DiffConv readout
    k_gather<<<1024, 256>>>(dst, src, ew, O_H, O_F1);
    k_gather<<<1024, 256>>>(dst, src, ew, O_F1, O_F2);
    k_gather<<<1024, 256>>>(src, dst, ew, O_H, O_B1);
    k_gather<<<1024, 256>>>(src, dst, ew, O_B1, O_B2);
    COffs cz;
    cz.o[0] = O_H; cz.o[1] = O_F1; cz.o[2] = O_F2; cz.o[3] = O_B1; cz.o[4] = O_B2;
    cz.o[5] = cz.o[6] = cz.o[7] = O_H;
    k_gate<<<256, 256>>>(cz, 5, W_diff, b_diff, W_diff, b_diff, O_Z, O_Z, 0, 0, -1);

    // decoder
    k_dec<<<16384, 96>>>(W_dec, b_dec, out);
}

// round 16
// speedup vs baseline: 1.8352x; 1.0756x over previous
#include <cuda_runtime.h>
#include <cuda_bf16.h>
#include <math.h>
#include <stdint.h>

typedef unsigned long long u64;

// ---------------------------------------------------------------------------
// Problem constants
// ---------------------------------------------------------------------------
constexpr int    Nn = 1024;
constexpr int    Tt = 12;
constexpr int    Ff = 8;
constexpr int    Ee = 32768;
constexpr size_t NS = (size_t)Nn * 1024;   // 1M floats per plane [node][b*64+h]

// ---------------------------------------------------------------------------
// fp32 scratch arena
// ---------------------------------------------------------------------------
constexpr size_t O_ADJF  = 0;
constexpr size_t O_ADJB  = 1 * NS;
constexpr size_t O_XENC  = 2 * NS;    // 12 planes
constexpr size_t O_XF1   = 14 * NS;   // 12
constexpr size_t O_XF2   = 26 * NS;   // 12
constexpr size_t O_XB1   = 38 * NS;   // 12
constexpr size_t O_XB2   = 50 * NS;   // 12
constexpr size_t O_H     = 62 * NS;
constexpr size_t O_HHOP  = 63 * NS;   // 4: [HF1, HF2, HB1, HB2]
constexpr size_t O_RH    = 67 * NS;
constexpr size_t O_RHHOP = 68 * NS;   // 4
constexpr size_t O_U     = 72 * NS;
constexpr size_t O_F1    = 73 * NS;
constexpr size_t O_F2    = 74 * NS;
constexpr size_t O_B1    = 75 * NS;
constexpr size_t O_B2    = 76 * NS;
constexpr size_t O_Z     = 77 * NS;
constexpr size_t O_RSUM  = 78 * NS;
constexpr size_t O_CSUM  = 78 * NS + 1024;
constexpr size_t F_TOT   = 78 * NS + 2048;

__device__ float g_f[F_TOT];

// ---------------------------------------------------------------------------
// bf16 plane arena (hi/lo pairs; "T" planes transposed [bh|k][node])
// 0..3: AF,AB (m-major) | 4..27: XENC-T ×12 | 28..31: AF-T, AB-T
// 32..35: AF2, AB2 (m-major) | 36,37: H-T | 38,39: RH-T
// ---------------------------------------------------------------------------
constexpr int PB_AF = 0, PB_AB = 2, PB_XET = 4, PB_AFT = 28, PB_AF2 = 32;
constexpr int PB_HT = 36, PB_RHT = 38;
constexpr int PB_NUM = 40;

__device__ __align__(256) __nv_bfloat16 g_b[(size_t)PB_NUM * NS];

// ---------------------------------------------------------------------------
// helpers
// ---------------------------------------------------------------------------
__device__ __forceinline__ uint32_t smem_u32(const void* p) {
    uint32_t a;
    asm("{ .reg .u64 t; cvta.to.shared.u64 t, %1; cvt.u32.u64 %0, t; }" : "=r"(a) : "l"(p));
    return a;
}
__device__ __forceinline__ void mma16816(float* c, const uint32_t* a, uint32_t b0, uint32_t b1) {
    asm volatile("mma.sync.aligned.m16n8k16.row.col.f32.bf16.bf16.f32 "
        "{%0,%1,%2,%3}, {%4,%5,%6,%7}, {%8,%9}, {%0,%1,%2,%3};"
        : "+f"(c[0]), "+f"(c[1]), "+f"(c[2]), "+f"(c[3])
        : "r"(a[0]), "r"(a[1]), "r"(a[2]), "r"(a[3]), "r"(b0), "r"(b1));
}
__device__ __forceinline__ void cp16(uint32_t dst, const void* src) {
    asm volatile("cp.async.cg.shared.global [%0], [%1], 16;" :: "r"(dst), "l"(src));
}
__device__ __forceinline__ void ldm4(uint32_t* r, uint32_t addr) {
    asm volatile("ldmatrix.sync.aligned.m8n8.x4.shared.b16 {%0,%1,%2,%3}, [%4];"
        : "=r"(r[0]), "=r"(r[1]), "=r"(r[2]), "=r"(r[3]) : "r"(addr));
}

// ---------------------------------------------------------------------------
// Adjacency normalization
// ---------------------------------------------------------------------------
__global__ void k_rowsum(const float* __restrict__ adj) {
    const int i = blockIdx.x;
    __shared__ float sm[256];
    float a = 0.f;
    for (int j = threadIdx.x; j < 1024; j += 256) a += adj[(size_t)i * 1024 + j];
    sm[threadIdx.x] = a; __syncthreads();
    for (int s = 128; s > 0; s >>= 1) {
        if (threadIdx.x < s) sm[threadIdx.x] += sm[threadIdx.x + s];
        __syncthreads();
    }
    if (threadIdx.x == 0) g_f[O_RSUM + i] = sm[0];
}

__global__ void k_colsum(const float* __restrict__ adj) {
    const int j = blockIdx.x * 256 + threadIdx.x;
    float a = 0.f;
    for (int i = 0; i < 1024; i++) a += adj[(size_t)i * 1024 + j];
    g_f[O_CSUM + j] = a;
}

__global__ void k_norm(const float* __restrict__ adj) {
    const size_t idx = (size_t)blockIdx.x * 256 + threadIdx.x;
    const int i = (int)(idx >> 10), j = (int)(idx & 1023);
    g_f[O_ADJF + idx] = adj[idx] / g_f[O_RSUM + i];
    g_f[O_ADJB + idx] = adj[(size_t)j * 1024 + i] / g_f[O_CSUM + i];
}

// fp32 plane pair at inOff (+z*NS) -> bf16 hi/lo plane pairs (m-major)
__global__ void k_cvtA(size_t inOff, int outPlane) {
    const size_t idx = (size_t)blockIdx.x * 256 + threadIdx.x;
    const int z = blockIdx.y;
    const float v = g_f[inOff + (size_t)z * NS + idx];
    const __nv_bfloat16 h = __float2bfloat16(v);
    g_b[(size_t)(outPlane + z * 2) * NS + idx] = h;
    g_b[(size_t)(outPlane + z * 2 + 1) * NS + idx] = __float2bfloat16(v - __bfloat162float(h));
}

// fp32 plane [k][n] -> transposed bf16 hi/lo planes [n][k]
__global__ void k_cvtT(size_t inOff, size_t inStr, int outBase, int outStr) {
    const int z = blockIdx.z;
    const float* __restrict__ in = g_f + inOff + (size_t)z * inStr;
    __nv_bfloat16* hi = g_b + (size_t)(outBase + z * outStr) * NS;
    __nv_bfloat16* lo = hi + NS;
    __shared__ float t[32][33];
    const int bx = blockIdx.x * 32, by = blockIdx.y * 32;
    const int tx = threadIdx.x, ty = threadIdx.y;
#pragma unroll
    for (int i = 0; i < 4; i++)
        t[ty + i * 8][tx] = in[(size_t)(by + ty + i * 8) * 1024 + bx + tx];
    __syncthreads();
#pragma unroll
    for (int i = 0; i < 4; i++) {
        const int n = bx + ty + i * 8, k = by + tx;
        const float v = t[tx][ty + i * 8];
        const __nv_bfloat16 h = __float2bfloat16(v);
        hi[(size_t)n * 1024 + k] = h;
        lo[(size_t)n * 1024 + k] = __float2bfloat16(v - __bfloat162float(h));
    }
}

// zero two consecutive bf16 planes starting at `plane`
__global__ void k_zerob(int plane) {
    ((uint4*)(g_b + (size_t)plane * NS))[(size_t)blockIdx.x * 256 + threadIdx.x] =
        make_uint4(0, 0, 0, 0);
}

// ---------------------------------------------------------------------------
// Encoder
// ---------------------------------------------------------------------------
__global__ void k_encoder(const float* __restrict__ x, const float* __restrict__ W,
                          const float* __restrict__ bias, const float* __restrict__ emb) {
    __shared__ float xs[16][8];
    __shared__ float Ws[8][64];
    const int n = blockIdx.x, t = blockIdx.y, tid = threadIdx.x;
    if (tid < 128) {
        const int b = tid >> 3, f = tid & 7;
        xs[b][f] = x[((size_t)(b * Tt + t) * Nn + n) * Ff + f];
    }
    {
        const int i0 = tid, i1 = tid + 256;
        Ws[i0 >> 6][i0 & 63] = W[i0];
        Ws[i1 >> 6][i1 & 63] = W[i1];
    }
    __syncthreads();
    const int h = tid & 63, bq = tid >> 6;
    const float base = bias[h] + emb[(size_t)n * 64 + h];
    float* o = g_f + O_XENC + (size_t)t * NS + (size_t)n * 1024;
#pragma unroll
    for (int i = 0; i < 4; i++) {
        const int b = bq * 4 + i;
        float acc = base;
#pragma unroll
        for (int f = 0; f < 8; f++) acc += xs[b][f] * Ws[f][h];
        o[b * 64 + h] = acc;
    }
}

// ---------------------------------------------------------------------------
// Tensor-core hop GEMM v3 (mma.sync bf16, cp.async 2-stage, 4-tile chunks):
// z maps to (f, t): f = z/nT selects A plane (aPl.{x,y,z,w}) and output base
// cOffs.o[f]; t = z%nT selects X plane (xBase + t*xStr + f*xFStr) and output
// offset t*cStr. C = Ahi·Xhi + Ahi·Xlo + Alo·Xhi, fp32 accum, fp32 out.
// ---------------------------------------------------------------------------
struct COffs4 { size_t o[4]; };

__global__ void __launch_bounds__(256, 2) k_tc(int4 aPl, int nT,
        int xBase, int xStr, int xFStr, COffs4 cOffs, size_t cStr) {
    extern __shared__ __align__(16) char sm[];
    const int tid = threadIdx.x, wid = tid >> 5, lane = tid & 31;
    const int z = blockIdx.z;
    const int f = z / nT, t = z - f * nT;
    const int m0 = blockIdx.y * 128, n0 = blockIdx.x * 128;
    const int aP = (f == 0) ? aPl.x : (f == 1) ? aPl.y : (f == 2) ? aPl.z : aPl.w;
    const __nv_bfloat16* __restrict__ Ahi = g_b + (size_t)aP * NS;
    const __nv_bfloat16* __restrict__ Alo = Ahi + NS;
    const __nv_bfloat16* __restrict__ Xhi = g_b + (size_t)(xBase + t * xStr + f * xFStr) * NS;
    const __nv_bfloat16* __restrict__ Xlo = Xhi + NS;
    float* __restrict__ C = g_f + cOffs.o[f] + (size_t)t * cStr;

    const int wm = (wid & 1) * 64, wn = (wid >> 1) * 32;
    const uint32_t smBase = smem_u32(sm);
    const int lrow = lane & 15, lkh = (lane >> 4) * 8;

    float acc[4][4][4];
#pragma unroll
    for (int mi = 0; mi < 4; mi++)
#pragma unroll
        for (int ni = 0; ni < 4; ni++)
#pragma unroll
            for (int q = 0; q < 4; q++) acc[mi][ni][q] = 0.f;

    const int crow = tid >> 2, cEl = (tid & 3) * 8;
    const uint32_t cBy = (tid & 3) * 16;

    // one BK=32 chunk: 4 tiles {Ahi, Alo, Xhi, Xlo}, 80B row pitch
    auto issue_chunk = [&](int kc, int buf) {
        const uint32_t st = smBase + buf * 40960;
#pragma unroll
        for (int it = 0; it < 2; it++) {
            const int row = crow + it * 64;
            const size_t ga = (size_t)(m0 + row) * 1024 + kc + cEl;
            const size_t gx = (size_t)(n0 + row) * 1024 + kc + cEl;
            const uint32_t so = row * 80 + cBy;
            cp16(st + so,         Ahi + ga);
            cp16(st + 10240 + so, Alo + ga);
            cp16(st + 20480 + so, Xhi + gx);
            cp16(st + 30720 + so, Xlo + gx);
        }
        asm volatile("cp.async.commit_group;");
    };

    issue_chunk(0, 0);
#pragma unroll 1
    for (int c = 0; c < 32; c++) {
        if (c + 1 < 32) {
            issue_chunk((c + 1) * 32, (c + 1) & 1);
            asm volatile("cp.async.wait_group 1;");
        } else {
            asm volatile("cp.async.wait_group 0;");
        }
        __syncthreads();
        const uint32_t st = smBase + (c & 1) * 40960;
#pragma unroll
        for (int ks = 0; ks < 2; ks++) {
            const uint32_t kb = (uint32_t)((ks * 16 + lkh) * 2);
            uint32_t ah[4][4], bh[2][4];
#pragma unroll
            for (int mi = 0; mi < 4; mi++)
                ldm4(ah[mi], st + (wm + mi * 16 + lrow) * 80 + kb);
#pragma unroll
            for (int nb = 0; nb < 2; nb++)
                ldm4(bh[nb], st + 20480 + (wn + nb * 16 + lrow) * 80 + kb);
#pragma unroll
            for (int mi = 0; mi < 4; mi++)
#pragma unroll
                for (int ni = 0; ni < 4; ni++) {
                    const int nb = ni >> 1, hl = ni & 1;
                    mma16816(acc[mi][ni], ah[mi], bh[nb][hl], bh[nb][2 + hl]);
                }
            {
                uint32_t bl[2][4];
#pragma unroll
                for (int nb = 0; nb < 2; nb++)
                    ldm4(bl[nb], st + 30720 + (wn + nb * 16 + lrow) * 80 + kb);
#pragma unroll
                for (int mi = 0; mi < 4; mi++)
#pragma unroll
                    for (int ni = 0; ni < 4; ni++) {
                        const int nb = ni >> 1, hl = ni & 1;
                        mma16816(acc[mi][ni], ah[mi], bl[nb][hl], bl[nb][2 + hl]);
                    }
            }
            {
                uint32_t al[4][4];
#pragma unroll
                for (int mi = 0; mi < 4; mi++)
                    ldm4(al[mi], st + 10240 + (wm + mi * 16 + lrow) * 80 + kb);
#pragma unroll
                for (int mi = 0; mi < 4; mi++)
#pragma unroll
                    for (int ni = 0; ni < 4; ni++) {
                        const int nb = ni >> 1, hl = ni & 1;
                        mma16816(acc[mi][ni], al[mi], bh[nb][hl], bh[nb][2 + hl]);
                    }
            }
        }
        __syncthreads();
    }

    // fp32 epilogue
    const int er = lane >> 2, ec = (lane & 3) * 2;
#pragma unroll
    for (int mi = 0; mi < 4; mi++)
#pragma unroll
        for (int ni = 0; ni < 4; ni++) {
            const int row = m0 + wm + mi * 16 + er;
            const int col = n0 + wn + ni * 8 + ec;
            *(float2*)(C + (size_t)row * 1024 + col) = make_float2(acc[mi][ni][0], acc[mi][ni][1]);
            *(float2*)(C + (size_t)(row + 8) * 1024 + col) = make_float2(acc[mi][ni][2], acc[mi][ni][3]);
        }
}

// ---------------------------------------------------------------------------
// Gate gather-GEMM (FFMA2) + fused epilogues.
// mode 0: out0 = pre0 + b0
// mode 1: r=sig(pre0), u=sig(pre1): out0=r*h, out1=u; tEmit: RH-T planes
// mode 2: c=tanh(pre0): h = u*h + (1-u)*c in place;   tEmit: H-T planes
// ---------------------------------------------------------------------------
struct COffs { size_t o[8]; };

__device__ __forceinline__ u64 pack2(float x) {
    u64 r;
    asm("mov.b64 %0, {%1, %1};" : "=l"(r) : "r"(__float_as_uint(x)));
    return r;
}
__device__ __forceinline__ void ffma2(u64& c, u64 a, u64 b) {
    asm("fma.rn.f32x2 %0, %1, %2, %0;" : "+l"(c) : "l"(a), "l"(b));
}
__device__ __forceinline__ float2 up2(u64 v) {
    float2 f;
    unsigned lo, hi;
    asm("mov.b64 {%0, %1}, %2;" : "=r"(lo), "=r"(hi) : "l"(v));
    f.x = __uint_as_float(lo); f.y = __uint_as_float(hi);
    return f;
}
__device__ __forceinline__ void emitT(int tEmit, int bh, int n, float v) {
    const __nv_bfloat16 h = __float2bfloat16(v);
    g_b[(size_t)tEmit * NS + (size_t)bh * 1024 + n] = h;
    g_b[(size_t)(tEmit + 1) * NS + (size_t)bh * 1024 + n] =
        __float2bfloat16(v - __bfloat162float(h));
}

__global__ void __launch_bounds__(256) k_gate(COffs ch, int nch,
        const float* __restrict__ W0, const float* __restrict__ b0,
        const float* __restrict__ W1, const float* __restrict__ b1,
        size_t oOut0, size_t oOut1, int mode, int two, int tEmit) {
    __shared__ float As[64][17];
    __shared__ float Ws0[16][68];
    __shared__ float Ws1[16][68];
    const int tid = threadIdx.x;
    const int g0 = blockIdx.x * 64;
    const int tx = tid & 15, ty = tid >> 4;
    const int ar = tid >> 2, kq = (tid & 3) * 4;
    const size_t abase = (size_t)(g0 + ar) * 64;
    const int wr = tid >> 4, wc = (tid & 15) * 4;
    u64 acc0[4][2], acc1[4][2];
#pragma unroll
    for (int i = 0; i < 4; i++) { acc0[i][0] = acc0[i][1] = 0ULL; acc1[i][0] = acc1[i][1] = 0ULL; }
    const int K = nch * 64;
    for (int k0 = 0; k0 < K; k0 += 16) {
        const float4 av = *(const float4*)(g_f + ch.o[k0 >> 6] + abase + (k0 & 63) + kq);
        const float4 w0 = *(const float4*)(W0 + (size_t)(k0 + wr) * 64 + wc);
        float4 w1 = make_float4(0.f, 0.f, 0.f, 0.f);
        if (two) w1 = *(const float4*)(W1 + (size_t)(k0 + wr) * 64 + wc);
        __syncthreads();
        As[ar][kq + 0] = av.x; As[ar][kq + 1] = av.y; As[ar][kq + 2] = av.z; As[ar][kq + 3] = av.w;
        *(float4*)&Ws0[wr][wc] = w0;
        if (two) *(float4*)&Ws1[wr][wc] = w1;
        __syncthreads();
#pragma unroll
        for (int kk = 0; kk < 16; kk++) {
            u64 ap[4];
#pragma unroll
            for (int i = 0; i < 4; i++) ap[i] = pack2(As[ty * 4 + i][kk]);
            const float4 v0 = *(const float4*)&Ws0[kk][tx * 4];
            const u64 wp0 = ((const u64*)&v0)[0], wp1 = ((const u64*)&v0)[1];
#pragma unroll
            for (int i = 0; i < 4; i++) { ffma2(acc0[i][0], ap[i], wp0); ffma2(acc0[i][1], ap[i], wp1); }
            if (two) {
                const float4 v1 = *(const float4*)&Ws1[kk][tx * 4];
                const u64 xp0 = ((const u64*)&v1)[0], xp1 = ((const u64*)&v1)[1];
#pragma unroll
                for (int i = 0; i < 4; i++) { ffma2(acc1[i][0], ap[i], xp0); ffma2(acc1[i][1], ap[i], xp1); }
            }
        }
    }
    const float4 bias0 = *(const float4*)(b0 + tx * 4);
    float4 bias1 = bias0;
    if (two) bias1 = *(const float4*)(b1 + tx * 4);
#pragma unroll
    for (int i = 0; i < 4; i++) {
        const int row = g0 + ty * 4 + i;
        const int nb = row >> 4, bb = (row & 15) * 64 + tx * 4;
        const size_t eo = (size_t)row * 64 + tx * 4;
        float pre0[4], pre1[4];
        { const float2 a = up2(acc0[i][0]), b = up2(acc0[i][1]);
          pre0[0] = a.x + bias0.x; pre0[1] = a.y + bias0.y; pre0[2] = b.x + bias0.z; pre0[3] = b.y + bias0.w; }
        { const float2 a = up2(acc1[i][0]), b = up2(acc1[i][1]);
          pre1[0] = a.x + bias1.x; pre1[1] = a.y + bias1.y; pre1[2] = b.x + bias1.z; pre1[3] = b.y + bias1.w; }
        if (mode == 1) {
            const float4 hv = *(const float4*)(g_f + O_H + eo);
            const float h[4] = {hv.x, hv.y, hv.z, hv.w};
            float4 rh, uo;
            float* prh = (float*)&rh; float* puo = (float*)&uo;
#pragma unroll
            for (int j = 0; j < 4; j++) {
                const float r = 1.0f / (1.0f + expf(-pre0[j]));
                const float u = 1.0f / (1.0f + expf(-pre1[j]));
                prh[j] = r * h[j]; puo[j] = u;
            }
            *(float4*)(g_f + oOut0 + eo) = rh;
            *(float4*)(g_f + oOut1 + eo) = uo;
            if (tEmit >= 0) {
#pragma unroll
                for (int j = 0; j < 4; j++) emitT(tEmit, bb + j, nb, prh[j]);
            }
        } else if (mode == 2) {
            const float4 hv = *(const float4*)(g_f + O_H + eo);
            const float4 uv = *(const float4*)(g_f + O_U + eo);
            const float h[4] = {hv.x, hv.y, hv.z, hv.w};
            const float u[4] = {uv.x, uv.y, uv.z, uv.w};
            float4 hn; float* phn = (float*)&hn;
#pragma unroll
            for (int j = 0; j < 4; j++) {
                const float c = tanhf(pre0[j]);
                phn[j] = u[j] * h[j] + (1.0f - u[j]) * c;
            }
            *(float4*)(g_f + O_H + eo) = hn;
            if (tEmit >= 0) {
#pragma unroll
                for (int j = 0; j < 4; j++) emitT(tEmit, bb + j, nb, phn[j]);
            }
        } else {
            *(float4*)(g_f + oOut0 + eo) = make_float4(pre0[0], pre0[1], pre0[2], pre0[3]);
        }
    }
}

__global__ void k_zero(size_t o) {
    g_f[o + (size_t)blockIdx.x * 256 + threadIdx.x] = 0.f;
}

// ---------------------------------------------------------------------------
// Sparse DiffConv hop (deterministic): one block per node n.
// ---------------------------------------------------------------------------
__global__ void __launch_bounds__(256) k_gather(const int* __restrict__ sel,
        const int* __restrict__ oth, const float* __restrict__ w,
        size_t oIn, size_t oOut) {
    const int n = blockIdx.x, tid = threadIdx.x;
    __shared__ int   cnts[257];
    __shared__ int   s_o[2048];
    __shared__ float s_w[2048];
    __shared__ float red[256];
    __shared__ float s_inv;
    int c0 = 0;
    for (int e = tid; e < Ee; e += 256) c0 += (sel[e] == n);
    cnts[tid + 1] = c0;
    if (tid == 0) cnts[0] = 0;
    __syncthreads();
    if (tid == 0) { int a = 0; for (int i = 1; i <= 256; i++) { a += cnts[i]; cnts[i] = a; } }
    __syncthreads();
    int off = cnts[tid];
    for (int e = tid; e < Ee; e += 256)
        if (sel[e] == n) { if (off < 2048) { s_o[off] = oth[e]; s_w[off] = w[e]; } off++; }
    __syncthreads();
    int M = cnts[256]; if (M > 2048) M = 2048;
    float dacc = 0.f;
    for (int m = tid; m < M; m += 256) dacc += s_w[m];
    red[tid] = dacc; __syncthreads();
    for (int s = 128; s > 0; s >>= 1) {
        if (tid < s) red[tid] += red[tid + s];
        __syncthreads();
    }
    if (tid == 0) s_inv = red[0] > 0.f ? 1.f / red[0] : 0.f;
    __syncthreads();
    const float inv = s_inv;
    const float4* in4 = (const float4*)(g_f + oIn);
    float4 acc = make_float4(0.f, 0.f, 0.f, 0.f);
    for (int m = 0; m < M; m++) {
        const float wm = s_w[m];
        const float4 v = in4[(size_t)s_o[m] * 256 + tid];
        acc.x += v.x * wm; acc.y += v.y * wm; acc.z += v.z * wm; acc.w += v.w * wm;
    }
    acc.x *= inv; acc.y *= inv; acc.z *= inv; acc.w *= inv;
    ((float4*)(g_f + oOut + (size_t)n * 1024))[tid] = acc;
}

// ---------------------------------------------------------------------------
// Decoder
// ---------------------------------------------------------------------------
__global__ void k_dec(const float* __restrict__ Wd, const float* __restrict__ bd,
                      float* __restrict__ out) {
    __shared__ float zs[64];
    const int g = blockIdx.x, c = threadIdx.x;   // 96 threads
    if (c < 64) zs[c] = g_f[O_Z + (size_t)g * 64 + c];
    __syncthreads();
    float a = bd[c];
#pragma unroll
    for (int h = 0; h < 64; h++) a += zs[h] * Wd[h * 96 + c];
    const int b = g & 15, n = g >> 4, t = c >> 3, f = c & 7;
    out[(((size_t)b * 12 + t) * 1024 + n) * 8 + f] = a;
}

// ---------------------------------------------------------------------------
// Launcher
// ---------------------------------------------------------------------------
extern "C" void kernel_launch(void* const* d_in, const int* in_sizes, int n_in,
                              void* d_out, int out_size) {
    const float* x      = (const float*)d_in[0];
    const int*   ei     = (const int*)d_in[1];
    const float* ew     = (const float*)d_in[2];
    const float* adj    = (const float*)d_in[3];
    const float* W_enc  = (const float*)d_in[4];
    const float* b_enc  = (const float*)d_in[5];
    const float* emb    = (const float*)d_in[6];
    const float* W_r    = (const float*)d_in[7];
    const float* b_r    = (const float*)d_in[8];
    const float* W_u    = (const float*)d_in[9];
    const float* b_u    = (const float*)d_in[10];
    const float* W_c    = (const float*)d_in[11];
    const float* b_c    = (const float*)d_in[12];
    const float* W_diff = (const float*)d_in[13];
    const float* b_diff = (const float*)d_in[14];
    const float* W_dec  = (const float*)d_in[15];
    const float* b_dec  = (const float*)d_in[16];
    float* out = (float*)d_out;
    const int* src = ei;
    const int* dst = ei + Ee;

    const dim3 cvtB(32, 8);
    const int TC_SMEM = 81920;
    cudaFuncSetAttribute((const void*)k_tc,
                         cudaFuncAttributeMaxDynamicSharedMemorySize, TC_SMEM);

    const int4 aAll = make_int4(PB_AF, PB_AB, PB_AF2, PB_AF2 + 2);

    // supports + encoder + conversions
    k_rowsum<<<1024, 256>>>(adj);
    k_colsum<<<4, 256>>>(adj);
    k_norm<<<4096, 256>>>(adj);
    k_encoder<<<dim3(1024, 12), 256>>>(x, W_enc, b_enc, emb);
    k_cvtA<<<dim3(4096, 2), 256>>>(O_ADJF, PB_AF);
    k_cvtT<<<dim3(32, 32, 12), cvtB>>>(O_XENC, NS, PB_XET, 2);
    k_cvtT<<<dim3(32, 32, 2), cvtB>>>(O_ADJF, NS, PB_AFT, 2);

    // A^2 (fp32 via split GEMM), then convert to bf16 hi/lo
    {
        COffs4 c2; c2.o[0] = O_F1; c2.o[1] = O_F2; c2.o[2] = 0; c2.o[3] = 0;
        k_tc<<<dim3(8, 8, 2), 256, TC_SMEM>>>(make_int4(PB_AF, PB_AB, 0, 0),
                                              1, PB_AFT, 0, 2, c2, 0);
        k_cvtA<<<dim3(4096, 2), 256>>>(O_F1, PB_AF2);
    }

    // all 48 x-side hops in ONE launch (independent via A^2)
    {
        COffs4 cx; cx.o[0] = O_XF1; cx.o[1] = O_XB1; cx.o[2] = O_XF2; cx.o[3] = O_XB2;
        k_tc<<<dim3(8, 8, 48), 256, TC_SMEM>>>(aAll, 12, PB_XET, 2, 0, cx, NS);
    }

    // GRU scan: per step ONE z=4 hop launch + gate (x2)
    k_zero<<<4096, 256>>>(O_H);
    k_zerob<<<1024, 256>>>(PB_HT);
    COffs4 cH; cH.o[0] = O_HHOP; cH.o[1] = O_HHOP + 2 * NS;
    cH.o[2] = O_HHOP + NS; cH.o[3] = O_HHOP + 3 * NS;
    COffs4 cR; cR.o[0] = O_RHHOP; cR.o[1] = O_RHHOP + 2 * NS;
    cR.o[2] = O_RHHOP + NS; cR.o[3] = O_RHHOP + 3 * NS;
    for (int t = 0; t < 12; t++) {
        k_tc<<<dim3(8, 8, 4), 256, TC_SMEM>>>(aAll, 1, PB_HT, 0, 0, cH, 0);
        COffs cg;
        cg.o[0] = O_XF1 + (size_t)t * NS; cg.o[1] = O_HHOP;
        cg.o[2] = O_XF2 + (size_t)t * NS; cg.o[3] = O_HHOP + NS;
        cg.o[4] = O_XB1 + (size_t)t * NS; cg.o[5] = O_HHOP + 2 * NS;
        cg.o[6] = O_XB2 + (size_t)t * NS; cg.o[7] = O_HHOP + 3 * NS;
        k_gate<<<256, 256>>>(cg, 8, W_r, b_r, W_u, b_u, O_RH, O_U, 1, 1, PB_RHT);
        k_tc<<<dim3(8, 8, 4), 256, TC_SMEM>>>(aAll, 1, PB_RHT, 0, 0, cR, 0);
        COffs cc = cg;
        cc.o[1] = O_RHHOP;          cc.o[3] = O_RHHOP + NS;
        cc.o[5] = O_RHHOP + 2 * NS; cc.o[7] = O_RHHOP + 3 * NS;
        k_gate<<<256, 256>>>(cc, 8, W_c, b_c, W_c, b_c, O_H, O_H, 2, 0, PB_HT);
    }

    // sparse DiffConv readout
    k_gather<<<1024, 256>>>(dst, src, ew, O_H, O_F1);
    k_gather<<<1024, 256>>>(dst, src, ew, O_F1, O_F2);
    k_gather<<<1024, 256>>>(src, dst, ew, O_H, O_B1);
    k_gather<<<1024, 256>>>(src, dst, ew, O_B1, O_B2);
    COffs cz;
    cz.o[0] = O_H; cz.o[1] = O_F1; cz.o[2] = O_F2; cz.o[3] = O_B1; cz.o[4] = O_B2;
    cz.o[5] = cz.o[6] = cz.o[7] = O_H;
    k_gate<<<256, 256>>>(cz, 5, W_diff, b_diff, W_diff, b_diff, O_Z, O_Z, 0, 0, -1);

    // decoder
    k_dec<<<16384, 96>>>(W_dec, b_dec, out);
}

// round 17
// speedup vs baseline: 2.0212x; 1.1013x over previous
#include <cuda_runtime.h>
#include <cuda_bf16.h>
#include <math.h>
#include <stdint.h>

typedef unsigned long long u64;

// ---------------------------------------------------------------------------
// Problem constants
// ---------------------------------------------------------------------------
constexpr int    Nn = 1024;
constexpr int    Tt = 12;
constexpr int    Ff = 8;
constexpr int    Ee = 32768;
constexpr size_t NS = (size_t)Nn * 1024;   // 1M elems per plane [node][b*64+h]

// ---------------------------------------------------------------------------
// fp32 scratch arena
// ---------------------------------------------------------------------------
constexpr size_t O_ADJF  = 0;
constexpr size_t O_ADJB  = 1 * NS;
constexpr size_t O_XENC  = 2 * NS;    // 12 planes
constexpr size_t O_H     = 14 * NS;
constexpr size_t O_U     = 15 * NS;
constexpr size_t O_F1    = 16 * NS;
constexpr size_t O_F2    = 17 * NS;
constexpr size_t O_B1    = 18 * NS;
constexpr size_t O_B2    = 19 * NS;
constexpr size_t O_Z     = 20 * NS;
constexpr size_t O_A2    = 21 * NS;   // 2 planes (AF^2, AB^2 fp32 staging)
constexpr size_t O_RSUM  = 23 * NS;
constexpr size_t O_CSUM  = 23 * NS + 1024;
constexpr size_t F_TOT   = 23 * NS + 2048;

__device__ float g_f[F_TOT];

// ---------------------------------------------------------------------------
// bf16 plane arena (hi/lo pairs). "T" planes transposed [bh|k][node].
// 0..3: AF,AB (m-major) | 4..27: XENC-T x12 | 28..31: AF-T,AB-T
// 32..35: AF2,AB2 (m-major) | 36,37: H-T | 38,39: RH-T
// 40..135: X chunks (f in {XF1,XB1,XF2,XB2}) x t: plane = 40+(f*12+t)*2
// 136..143: H-hop chunks (f: HF1,HB1,HF2,HB2) | 144..151: RH-hop chunks
// ---------------------------------------------------------------------------
constexpr int PB_AF = 0, PB_AB = 2, PB_XET = 4, PB_AFT = 28, PB_AF2 = 32;
constexpr int PB_HT = 36, PB_RHT = 38, PB_XC = 40, PB_HB = 136, PB_RB = 144;
constexpr int PB_NUM = 152;

__device__ __align__(256) __nv_bfloat16 g_b[(size_t)PB_NUM * NS];
__device__ __align__(256) __nv_bfloat16 g_w[6][64 * 512];   // WT hi/lo: r,u,c

// ---------------------------------------------------------------------------
// helpers
// ---------------------------------------------------------------------------
__device__ __forceinline__ uint32_t smem_u32(const void* p) {
    uint32_t a;
    asm("{ .reg .u64 t; cvta.to.shared.u64 t, %1; cvt.u32.u64 %0, t; }" : "=r"(a) : "l"(p));
    return a;
}
__device__ __forceinline__ void mma16816(float* c, const uint32_t* a, uint32_t b0, uint32_t b1) {
    asm volatile("mma.sync.aligned.m16n8k16.row.col.f32.bf16.bf16.f32 "
        "{%0,%1,%2,%3}, {%4,%5,%6,%7}, {%8,%9}, {%0,%1,%2,%3};"
        : "+f"(c[0]), "+f"(c[1]), "+f"(c[2]), "+f"(c[3])
        : "r"(a[0]), "r"(a[1]), "r"(a[2]), "r"(a[3]), "r"(b0), "r"(b1));
}
__device__ __forceinline__ void cp16(uint32_t dst, const void* src) {
    asm volatile("cp.async.cg.shared.global [%0], [%1], 16;" :: "r"(dst), "l"(src));
}
__device__ __forceinline__ void ldm4(uint32_t* r, uint32_t addr) {
    asm volatile("ldmatrix.sync.aligned.m8n8.x4.shared.b16 {%0,%1,%2,%3}, [%4];"
        : "=r"(r[0]), "=r"(r[1]), "=r"(r[2]), "=r"(r[3]) : "r"(addr));
}
__device__ __forceinline__ void split2(float v, __nv_bfloat16& h, __nv_bfloat16& l) {
    h = __float2bfloat16(v);
    l = __float2bfloat16(v - __bfloat162float(h));
}

// ---------------------------------------------------------------------------
// Adjacency normalization
// ---------------------------------------------------------------------------
__global__ void k_rowsum(const float* __restrict__ adj) {
    const int i = blockIdx.x;
    __shared__ float sm[256];
    float a = 0.f;
    for (int j = threadIdx.x; j < 1024; j += 256) a += adj[(size_t)i * 1024 + j];
    sm[threadIdx.x] = a; __syncthreads();
    for (int s = 128; s > 0; s >>= 1) {
        if (threadIdx.x < s) sm[threadIdx.x] += sm[threadIdx.x + s];
        __syncthreads();
    }
    if (threadIdx.x == 0) g_f[O_RSUM + i] = sm[0];
}

__global__ void k_colsum(const float* __restrict__ adj) {
    const int j = blockIdx.x * 256 + threadIdx.x;
    float a = 0.f;
    for (int i = 0; i < 1024; i++) a += adj[(size_t)i * 1024 + j];
    g_f[O_CSUM + j] = a;
}

__global__ void k_norm(const float* __restrict__ adj) {
    const size_t idx = (size_t)blockIdx.x * 256 + threadIdx.x;
    const int i = (int)(idx >> 10), j = (int)(idx & 1023);
    g_f[O_ADJF + idx] = adj[idx] / g_f[O_RSUM + i];
    g_f[O_ADJB + idx] = adj[(size_t)j * 1024 + i] / g_f[O_CSUM + i];
}

// fp32 plane pair at inOff (+z*NS) -> bf16 hi/lo plane pairs (m-major)
__global__ void k_cvtA(size_t inOff, int outPlane) {
    const size_t idx = (size_t)blockIdx.x * 256 + threadIdx.x;
    const int z = blockIdx.y;
    const float v = g_f[inOff + (size_t)z * NS + idx];
    __nv_bfloat16 h, l;
    split2(v, h, l);
    g_b[(size_t)(outPlane + z * 2) * NS + idx] = h;
    g_b[(size_t)(outPlane + z * 2 + 1) * NS + idx] = l;
}

// fp32 plane [k][n] -> transposed bf16 hi/lo planes [n][k]
__global__ void k_cvtT(size_t inOff, size_t inStr, int outBase, int outStr) {
    const int z = blockIdx.z;
    const float* __restrict__ in = g_f + inOff + (size_t)z * inStr;
    __nv_bfloat16* hi = g_b + (size_t)(outBase + z * outStr) * NS;
    __nv_bfloat16* lo = hi + NS;
    __shared__ float t[32][33];
    const int bx = blockIdx.x * 32, by = blockIdx.y * 32;
    const int tx = threadIdx.x, ty = threadIdx.y;
#pragma unroll
    for (int i = 0; i < 4; i++)
        t[ty + i * 8][tx] = in[(size_t)(by + ty + i * 8) * 1024 + bx + tx];
    __syncthreads();
#pragma unroll
    for (int i = 0; i < 4; i++) {
        const int n = bx + ty + i * 8, k = by + tx;
        __nv_bfloat16 h, l;
        split2(t[tx][ty + i * 8], h, l);
        hi[(size_t)n * 1024 + k] = h;
        lo[(size_t)n * 1024 + k] = l;
    }
}

// weight [512][64] fp32 -> WT hi/lo [64][512] bf16 (g_w slot wi)
__global__ void k_cvtW(const float* __restrict__ W, int wi) {
    const int idx = blockIdx.x * 256 + threadIdx.x;   // h*512 + k
    const int h = idx >> 9, k = idx & 511;
    __nv_bfloat16 hh, ll;
    split2(W[k * 64 + h], hh, ll);
    g_w[wi * 2][idx] = hh;
    g_w[wi * 2 + 1][idx] = ll;
}

// zero two consecutive bf16 planes starting at `plane`
__global__ void k_zerob(int plane) {
    ((uint4*)(g_b + (size_t)plane * NS))[(size_t)blockIdx.x * 256 + threadIdx.x] =
        make_uint4(0, 0, 0, 0);
}
__global__ void k_zero(size_t o) {
    g_f[o + (size_t)blockIdx.x * 256 + threadIdx.x] = 0.f;
}

// ---------------------------------------------------------------------------
// Encoder
// ---------------------------------------------------------------------------
__global__ void k_encoder(const float* __restrict__ x, const float* __restrict__ W,
                          const float* __restrict__ bias, const float* __restrict__ emb) {
    __shared__ float xs[16][8];
    __shared__ float Ws[8][64];
    const int n = blockIdx.x, t = blockIdx.y, tid = threadIdx.x;
    if (tid < 128) {
        const int b = tid >> 3, f = tid & 7;
        xs[b][f] = x[((size_t)(b * Tt + t) * Nn + n) * Ff + f];
    }
    {
        const int i0 = tid, i1 = tid + 256;
        Ws[i0 >> 6][i0 & 63] = W[i0];
        Ws[i1 >> 6][i1 & 63] = W[i1];
    }
    __syncthreads();
    const int h = tid & 63, bq = tid >> 6;
    const float base = bias[h] + emb[(size_t)n * 64 + h];
    float* o = g_f + O_XENC + (size_t)t * NS + (size_t)n * 1024;
#pragma unroll
    for (int i = 0; i < 4; i++) {
        const int b = bq * 4 + i;
        float acc = base;
#pragma unroll
        for (int f = 0; f < 8; f++) acc += xs[b][f] * Ws[f][h];
        o[b * 64 + h] = acc;
    }
}

// ---------------------------------------------------------------------------
// Tensor-core hop GEMM (mma.sync bf16, cp.async 2-stage, 4-tile chunks):
// z -> (f = z/nT, t = z%nT). A plane aPl[f]; X plane xBase + t*xStr + f*xFStr.
// C = Ahi·Xhi + Ahi·Xlo + Alo·Xhi, fp32 accum.
// outBf < 0: fp32 out at cOffs.o[f] + t*cStr.
// outBf >= 0: bf16 hi/lo out at planes outBf + (f*nT+t)*2.
// ---------------------------------------------------------------------------
struct COffs4 { size_t o[4]; };

__global__ void __launch_bounds__(256, 2) k_tc(int4 aPl, int nT,
        int xBase, int xStr, int xFStr, COffs4 cOffs, size_t cStr, int outBf) {
    extern __shared__ __align__(16) char sm[];
    const int tid = threadIdx.x, wid = tid >> 5, lane = tid & 31;
    const int z = blockIdx.z;
    const int f = z / nT, t = z - f * nT;
    const int m0 = blockIdx.y * 128, n0 = blockIdx.x * 128;
    const int aP = (f == 0) ? aPl.x : (f == 1) ? aPl.y : (f == 2) ? aPl.z : aPl.w;
    const __nv_bfloat16* __restrict__ Ahi = g_b + (size_t)aP * NS;
    const __nv_bfloat16* __restrict__ Alo = Ahi + NS;
    const __nv_bfloat16* __restrict__ Xhi = g_b + (size_t)(xBase + t * xStr + f * xFStr) * NS;
    const __nv_bfloat16* __restrict__ Xlo = Xhi + NS;

    const int wm = (wid & 1) * 64, wn = (wid >> 1) * 32;
    const uint32_t smBase = smem_u32(sm);
    const int lrow = lane & 15, lkh = (lane >> 4) * 8;

    float acc[4][4][4];
#pragma unroll
    for (int mi = 0; mi < 4; mi++)
#pragma unroll
        for (int ni = 0; ni < 4; ni++)
#pragma unroll
            for (int q = 0; q < 4; q++) acc[mi][ni][q] = 0.f;

    const int crow = tid >> 2, cEl = (tid & 3) * 8;
    const uint32_t cBy = (tid & 3) * 16;

    auto issue_chunk = [&](int kc, int buf) {
        const uint32_t st = smBase + buf * 40960;
#pragma unroll
        for (int it = 0; it < 2; it++) {
            const int row = crow + it * 64;
            const size_t ga = (size_t)(m0 + row) * 1024 + kc + cEl;
            const size_t gx = (size_t)(n0 + row) * 1024 + kc + cEl;
            const uint32_t so = row * 80 + cBy;
            cp16(st + so,         Ahi + ga);
            cp16(st + 10240 + so, Alo + ga);
            cp16(st + 20480 + so, Xhi + gx);
            cp16(st + 30720 + so, Xlo + gx);
        }
        asm volatile("cp.async.commit_group;");
    };

    issue_chunk(0, 0);
#pragma unroll 1
    for (int c = 0; c < 32; c++) {
        if (c + 1 < 32) {
            issue_chunk((c + 1) * 32, (c + 1) & 1);
            asm volatile("cp.async.wait_group 1;");
        } else {
            asm volatile("cp.async.wait_group 0;");
        }
        __syncthreads();
        const uint32_t st = smBase + (c & 1) * 40960;
#pragma unroll
        for (int ks = 0; ks < 2; ks++) {
            const uint32_t kb = (uint32_t)((ks * 16 + lkh) * 2);
            uint32_t ah[4][4], bh[2][4];
#pragma unroll
            for (int mi = 0; mi < 4; mi++)
                ldm4(ah[mi], st + (wm + mi * 16 + lrow) * 80 + kb);
#pragma unroll
            for (int nb = 0; nb < 2; nb++)
                ldm4(bh[nb], st + 20480 + (wn + nb * 16 + lrow) * 80 + kb);
#pragma unroll
            for (int mi = 0; mi < 4; mi++)
#pragma unroll
                for (int ni = 0; ni < 4; ni++) {
                    const int nb = ni >> 1, hl = ni & 1;
                    mma16816(acc[mi][ni], ah[mi], bh[nb][hl], bh[nb][2 + hl]);
                }
            {
                uint32_t bl[2][4];
#pragma unroll
                for (int nb = 0; nb < 2; nb++)
                    ldm4(bl[nb], st + 30720 + (wn + nb * 16 + lrow) * 80 + kb);
#pragma unroll
                for (int mi = 0; mi < 4; mi++)
#pragma unroll
                    for (int ni = 0; ni < 4; ni++) {
                        const int nb = ni >> 1, hl = ni & 1;
                        mma16816(acc[mi][ni], ah[mi], bl[nb][hl], bl[nb][2 + hl]);
                    }
            }
            {
                uint32_t al[4][4];
#pragma unroll
                for (int mi = 0; mi < 4; mi++)
                    ldm4(al[mi], st + 10240 + (wm + mi * 16 + lrow) * 80 + kb);
#pragma unroll
                for (int mi = 0; mi < 4; mi++)
#pragma unroll
                    for (int ni = 0; ni < 4; ni++) {
                        const int nb = ni >> 1, hl = ni & 1;
                        mma16816(acc[mi][ni], al[mi], bh[nb][hl], bh[nb][2 + hl]);
                    }
            }
        }
        __syncthreads();
    }

    const int er = lane >> 2, ec = (lane & 3) * 2;
    if (outBf < 0) {
        float* __restrict__ C = g_f + cOffs.o[f] + (size_t)t * cStr;
#pragma unroll
        for (int mi = 0; mi < 4; mi++)
#pragma unroll
            for (int ni = 0; ni < 4; ni++) {
                const int row = m0 + wm + mi * 16 + er;
                const int col = n0 + wn + ni * 8 + ec;
                *(float2*)(C + (size_t)row * 1024 + col) = make_float2(acc[mi][ni][0], acc[mi][ni][1]);
                *(float2*)(C + (size_t)(row + 8) * 1024 + col) = make_float2(acc[mi][ni][2], acc[mi][ni][3]);
            }
    } else {
        __nv_bfloat16* hiP = g_b + (size_t)(outBf + (f * nT + t) * 2) * NS;
        __nv_bfloat16* loP = hiP + NS;
#pragma unroll
        for (int mi = 0; mi < 4; mi++)
#pragma unroll
            for (int ni = 0; ni < 4; ni++) {
                const int row = m0 + wm + mi * 16 + er;
                const int col = n0 + wn + ni * 8 + ec;
                __nv_bfloat16 h0, l0, h1, l1, h2, l2, h3, l3;
                split2(acc[mi][ni][0], h0, l0); split2(acc[mi][ni][1], h1, l1);
                split2(acc[mi][ni][2], h2, l2); split2(acc[mi][ni][3], h3, l3);
                __nv_bfloat162 hv0; hv0.x = h0; hv0.y = h1;
                __nv_bfloat162 lv0; lv0.x = l0; lv0.y = l1;
                __nv_bfloat162 hv1; hv1.x = h2; hv1.y = h3;
                __nv_bfloat162 lv1; lv1.x = l2; lv1.y = l3;
                *(__nv_bfloat162*)(hiP + (size_t)row * 1024 + col) = hv0;
                *(__nv_bfloat162*)(loP + (size_t)row * 1024 + col) = lv0;
                *(__nv_bfloat162*)(hiP + (size_t)(row + 8) * 1024 + col) = hv1;
                *(__nv_bfloat162*)(loP + (size_t)(row + 8) * 1024 + col) = lv1;
            }
    }
}

// ---------------------------------------------------------------------------
// Tensor-core gate GEMM (mma.sync bf16 split), K=512 gathered from 8 bf16
// chunk-plane pairs (cp.p[ci] = hi plane; lo = +1). Rows g (128/block),
// cols h (64). 8 warps = 4m x 2n, warp 32x32.
// mode 1 (two gates W_r,W_u): r=sig, u=sig -> O_U fp32, RH-T bf16 planes
// mode 2 (one gate W_c): c=tanh -> H = u*h+(1-u)*c in place + H-T planes
// ---------------------------------------------------------------------------
struct CP8 { int p[8]; };

__device__ __forceinline__ void emitT(int tEmit, int bh, int n, float v) {
    __nv_bfloat16 h, l;
    split2(v, h, l);
    g_b[(size_t)tEmit * NS + (size_t)bh * 1024 + n] = h;
    g_b[(size_t)(tEmit + 1) * NS + (size_t)bh * 1024 + n] = l;
}

__global__ void __launch_bounds__(256) k_gateTC(CP8 cp,
        const __nv_bfloat16* __restrict__ Wt0, const float* __restrict__ b0,
        const __nv_bfloat16* __restrict__ Wt1, const float* __restrict__ b1,
        int mode, int tEmit) {
    extern __shared__ __align__(16) char sm[];
    const int tid = threadIdx.x, wid = tid >> 5, lane = tid & 31;
    const int g0 = blockIdx.x * 128;
    const int wm = (wid & 3) * 32, wn = (wid >> 2) * 32;
    const uint32_t smBase = smem_u32(sm);
    const int lrow = lane & 15, lkh = (lane >> 4) * 8;
    const int two = (mode == 1);

    float acc0[2][4][4], acc1[2][4][4];
#pragma unroll
    for (int mi = 0; mi < 2; mi++)
#pragma unroll
        for (int ni = 0; ni < 4; ni++)
#pragma unroll
            for (int q = 0; q < 4; q++) { acc0[mi][ni][q] = 0.f; acc1[mi][ni][q] = 0.f; }

    const int arow = tid >> 2;               // 0..63
    const uint32_t cBy = (tid & 3) * 16;
    const int cEl = (tid & 3) * 8;

    // one sub-chunk (BK=32): A hi/lo [128][32] + W tiles [64][32]
    auto issue_sub = [&](int ksc, int buf) {
        const int ci = ksc >> 1, half = (ksc & 1) * 32;
        const uint32_t st = smBase + buf * 40960;
        const __nv_bfloat16* Ahi = g_b + (size_t)cp.p[ci] * NS;
        const __nv_bfloat16* Alo = Ahi + NS;
#pragma unroll
        for (int it = 0; it < 2; it++) {
            const int row = arow + it * 64;
            const size_t ga = (size_t)(g0 + row) * 64 + half + cEl;
            const uint32_t so = row * 80 + cBy;
            cp16(st + so,         Ahi + ga);
            cp16(st + 10240 + so, Alo + ga);
        }
        {
            const size_t gw = (size_t)arow * 512 + ci * 64 + half + cEl;
            const uint32_t so = arow * 80 + cBy;
            cp16(st + 20480 + so, Wt0 + gw);
            cp16(st + 25600 + so, Wt0 + 32768 + gw);
            if (two) {
                cp16(st + 30720 + so, Wt1 + gw);
                cp16(st + 35840 + so, Wt1 + 32768 + gw);
            }
        }
        asm volatile("cp.async.commit_group;");
    };

    issue_sub(0, 0);
#pragma unroll 1
    for (int c = 0; c < 16; c++) {
        if (c + 1 < 16) {
            issue_sub(c + 1, (c + 1) & 1);
            asm volatile("cp.async.wait_group 1;");
        } else {
            asm volatile("cp.async.wait_group 0;");
        }
        __syncthreads();
        const uint32_t st = smBase + (c & 1) * 40960;
#pragma unroll
        for (int ks = 0; ks < 2; ks++) {
            const uint32_t kb = (uint32_t)((ks * 16 + lkh) * 2);
            uint32_t ah[2][4], b0h[2][4];
#pragma unroll
            for (int mi = 0; mi < 2; mi++)
                ldm4(ah[mi], st + (wm + mi * 16 + lrow) * 80 + kb);
#pragma unroll
            for (int nb = 0; nb < 2; nb++)
                ldm4(b0h[nb], st + 20480 + (wn + nb * 16 + lrow) * 80 + kb);
#pragma unroll
            for (int mi = 0; mi < 2; mi++)
#pragma unroll
                for (int ni = 0; ni < 4; ni++) {
                    const int nb = ni >> 1, hl = ni & 1;
                    mma16816(acc0[mi][ni], ah[mi], b0h[nb][hl], b0h[nb][2 + hl]);
                }
            {
                uint32_t b0l[2][4];
#pragma unroll
                for (int nb = 0; nb < 2; nb++)
                    ldm4(b0l[nb], st + 25600 + (wn + nb * 16 + lrow) * 80 + kb);
#pragma unroll
                for (int mi = 0; mi < 2; mi++)
#pragma unroll
                    for (int ni = 0; ni < 4; ni++) {
                        const int nb = ni >> 1, hl = ni & 1;
                        mma16816(acc0[mi][ni], ah[mi], b0l[nb][hl], b0l[nb][2 + hl]);
                    }
            }
            uint32_t b1h[2][4];
            if (two) {
#pragma unroll
                for (int nb = 0; nb < 2; nb++)
                    ldm4(b1h[nb], st + 30720 + (wn + nb * 16 + lrow) * 80 + kb);
#pragma unroll
                for (int mi = 0; mi < 2; mi++)
#pragma unroll
                    for (int ni = 0; ni < 4; ni++) {
                        const int nb = ni >> 1, hl = ni & 1;
                        mma16816(acc1[mi][ni], ah[mi], b1h[nb][hl], b1h[nb][2 + hl]);
                    }
                uint32_t b1l[2][4];
#pragma unroll
                for (int nb = 0; nb < 2; nb++)
                    ldm4(b1l[nb], st + 35840 + (wn + nb * 16 + lrow) * 80 + kb);
#pragma unroll
                for (int mi = 0; mi < 2; mi++)
#pragma unroll
                    for (int ni = 0; ni < 4; ni++) {
                        const int nb = ni >> 1, hl = ni & 1;
                        mma16816(acc1[mi][ni], ah[mi], b1l[nb][hl], b1l[nb][2 + hl]);
                    }
            }
            {
                uint32_t al[2][4];
#pragma unroll
                for (int mi = 0; mi < 2; mi++)
                    ldm4(al[mi], st + 10240 + (wm + mi * 16 + lrow) * 80 + kb);
#pragma unroll
                for (int mi = 0; mi < 2; mi++)
#pragma unroll
                    for (int ni = 0; ni < 4; ni++) {
                        const int nb = ni >> 1, hl = ni & 1;
                        mma16816(acc0[mi][ni], al[mi], b0h[nb][hl], b0h[nb][2 + hl]);
                        if (two) mma16816(acc1[mi][ni], al[mi], b1h[nb][hl], b1h[nb][2 + hl]);
                    }
            }
        }
        __syncthreads();
    }

    // epilogue
    const int er = lane >> 2, ec = (lane & 3) * 2;
#pragma unroll
    for (int mi = 0; mi < 2; mi++)
#pragma unroll
        for (int ni = 0; ni < 4; ni++) {
            const int col = wn + ni * 8 + ec;
            const float2 br = *(const float2*)(b0 + col);
            float2 bu = br;
            if (two) bu = *(const float2*)(b1 + col);
#pragma unroll
            for (int half = 0; half < 2; half++) {
                const int row = g0 + wm + mi * 16 + er + half * 8;
                const float p0 = acc0[mi][ni][half * 2 + 0] + br.x;
                const float p1 = acc0[mi][ni][half * 2 + 1] + br.y;
                const size_t eo = (size_t)row * 64 + col;
                const int nb = row >> 4, bb = (row & 15) * 64 + col;
                if (mode == 1) {
                    const float q0 = acc1[mi][ni][half * 2 + 0] + bu.x;
                    const float q1 = acc1[mi][ni][half * 2 + 1] + bu.y;
                    const float2 hv = *(const float2*)(g_f + O_H + eo);
                    const float r0 = 1.0f / (1.0f + expf(-p0));
                    const float r1 = 1.0f / (1.0f + expf(-p1));
                    const float u0 = 1.0f / (1.0f + expf(-q0));
                    const float u1 = 1.0f / (1.0f + expf(-q1));
                    *(float2*)(g_f + O_U + eo) = make_float2(u0, u1);
                    emitT(tEmit, bb, nb, r0 * hv.x);
                    emitT(tEmit, bb + 1, nb, r1 * hv.y);
                } else {
                    const float2 hv = *(const float2*)(g_f + O_H + eo);
                    const float2 uv = *(const float2*)(g_f + O_U + eo);
                    const float c0 = tanhf(p0), c1 = tanhf(p1);
                    const float n0 = uv.x * hv.x + (1.0f - uv.x) * c0;
                    const float n1 = uv.y * hv.y + (1.0f - uv.y) * c1;
                    *(float2*)(g_f + O_H + eo) = make_float2(n0, n1);
                    emitT(tEmit, bb, nb, n0);
                    emitT(tEmit, bb + 1, nb, n1);
                }
            }
        }
}

// ---------------------------------------------------------------------------
// Readout gate (FFMA2, fp32 chunk planes) — mode 0 only
// ---------------------------------------------------------------------------
struct COffs { size_t o[8]; };

__device__ __forceinline__ u64 pack2(float x) {
    u64 r;
    asm("mov.b64 %0, {%1, %1};" : "=l"(r) : "r"(__float_as_uint(x)));
    return r;
}
__device__ __forceinline__ void ffma2(u64& c, u64 a, u64 b) {
    asm("fma.rn.f32x2 %0, %1, %2, %0;" : "+l"(c) : "l"(a), "l"(b));
}
__device__ __forceinline__ float2 up2(u64 v) {
    float2 f;
    unsigned lo, hi;
    asm("mov.b64 {%0, %1}, %2;" : "=r"(lo), "=r"(hi) : "l"(v));
    f.x = __uint_as_float(lo); f.y = __uint_as_float(hi);
    return f;
}

__global__ void __launch_bounds__(256) k_gate(COffs ch, int nch,
        const float* __restrict__ W0, const float* __restrict__ b0, size_t oOut0) {
    __shared__ float As[64][17];
    __shared__ float Ws0[16][68];
    const int tid = threadIdx.x;
    const int g0 = blockIdx.x * 64;
    const int tx = tid & 15, ty = tid >> 4;
    const int ar = tid >> 2, kq = (tid & 3) * 4;
    const size_t abase = (size_t)(g0 + ar) * 64;
    const int wr = tid >> 4, wc = (tid & 15) * 4;
    u64 acc0[4][2];
#pragma unroll
    for (int i = 0; i < 4; i++) { acc0[i][0] = acc0[i][1] = 0ULL; }
    const int K = nch * 64;
    for (int k0 = 0; k0 < K; k0 += 16) {
        const float4 av = *(const float4*)(g_f + ch.o[k0 >> 6] + abase + (k0 & 63) + kq);
        const float4 w0 = *(const float4*)(W0 + (size_t)(k0 + wr) * 64 + wc);
        __syncthreads();
        As[ar][kq + 0] = av.x; As[ar][kq + 1] = av.y; As[ar][kq + 2] = av.z; As[ar][kq + 3] = av.w;
        *(float4*)&Ws0[wr][wc] = w0;
        __syncthreads();
#pragma unroll
        for (int kk = 0; kk < 16; kk++) {
            u64 ap[4];
#pragma unroll
            for (int i = 0; i < 4; i++) ap[i] = pack2(As[ty * 4 + i][kk]);
            const float4 v0 = *(const float4*)&Ws0[kk][tx * 4];
            const u64 wp0 = ((const u64*)&v0)[0], wp1 = ((const u64*)&v0)[1];
#pragma unroll
            for (int i = 0; i < 4; i++) { ffma2(acc0[i][0], ap[i], wp0); ffma2(acc0[i][1], ap[i], wp1); }
        }
    }
    const float4 bias0 = *(const float4*)(b0 + tx * 4);
#pragma unroll
    for (int i = 0; i < 4; i++) {
        const int row = g0 + ty * 4 + i;
        const size_t eo = (size_t)row * 64 + tx * 4;
        const float2 a = up2(acc0[i][0]), b = up2(acc0[i][1]);
        *(float4*)(g_f + oOut0 + eo) =
            make_float4(a.x + bias0.x, a.y + bias0.y, b.x + bias0.z, b.y + bias0.w);
    }
}

// ---------------------------------------------------------------------------
// Sparse DiffConv hop (deterministic): one block per node n.
// ---------------------------------------------------------------------------
__global__ void __launch_bounds__(256) k_gather(const int* __restrict__ sel,
        const int* __restrict__ oth, const float* __restrict__ w,
        size_t oIn, size_t oOut) {
    const int n = blockIdx.x, tid = threadIdx.x;
    __shared__ int   cnts[257];
    __shared__ int   s_o[2048];
    __shared__ float s_w[2048];
    __shared__ float red[256];
    __shared__ float s_inv;
    int c0 = 0;
    for (int e = tid; e < Ee; e += 256) c0 += (sel[e] == n);
    cnts[tid + 1] = c0;
    if (tid == 0) cnts[0] = 0;
    __syncthreads();
    if (tid == 0) { int a = 0; for (int i = 1; i <= 256; i++) { a += cnts[i]; cnts[i] = a; } }
    __syncthreads();
    int off = cnts[tid];
    for (int e = tid; e < Ee; e += 256)
        if (sel[e] == n) { if (off < 2048) { s_o[off] = oth[e]; s_w[off] = w[e]; } off++; }
    __syncthreads();
    int M = cnts[256]; if (M > 2048) M = 2048;
    float dacc = 0.f;
    for (int m = tid; m < M; m += 256) dacc += s_w[m];
    red[tid] = dacc; __syncthreads();
    for (int s = 128; s > 0; s >>= 1) {
        if (tid < s) red[tid] += red[tid + s];
        __syncthreads();
    }
    if (tid == 0) s_inv = red[0] > 0.f ? 1.f / red[0] : 0.f;
    __syncthreads();
    const float inv = s_inv;
    const float4* in4 = (const float4*)(g_f + oIn);
    float4 acc = make_float4(0.f, 0.f, 0.f, 0.f);
    for (int m = 0; m < M; m++) {
        const float wm = s_w[m];
        const float4 v = in4[(size_t)s_o[m] * 256 + tid];
        acc.x += v.x * wm; acc.y += v.y * wm; acc.z += v.z * wm; acc.w += v.w * wm;
    }
    acc.x *= inv; acc.y *= inv; acc.z *= inv; acc.w *= inv;
    ((float4*)(g_f + oOut + (size_t)n * 1024))[tid] = acc;
}

// ---------------------------------------------------------------------------
// Decoder
// ---------------------------------------------------------------------------
__global__ void k_dec(const float* __restrict__ Wd, const float* __restrict__ bd,
                      float* __restrict__ out) {
    __shared__ float zs[64];
    const int g = blockIdx.x, c = threadIdx.x;   // 96 threads
    if (c < 64) zs[c] = g_f[O_Z + (size_t)g * 64 + c];
    __syncthreads();
    float a = bd[c];
#pragma unroll
    for (int h = 0; h < 64; h++) a += zs[h] * Wd[h * 96 + c];
    const int b = g & 15, n = g >> 4, t = c >> 3, f = c & 7;
    out[(((size_t)b * 12 + t) * 1024 + n) * 8 + f] = a;
}

// ---------------------------------------------------------------------------
// Launcher
// ---------------------------------------------------------------------------
extern "C" void kernel_launch(void* const* d_in, const int* in_sizes, int n_in,
                              void* d_out, int out_size) {
    const float* x      = (const float*)d_in[0];
    const int*   ei     = (const int*)d_in[1];
    const float* ew     = (const float*)d_in[2];
    const float* adj    = (const float*)d_in[3];
    const float* W_enc  = (const float*)d_in[4];
    const float* b_enc  = (const float*)d_in[5];
    const float* emb    = (const float*)d_in[6];
    const float* W_r    = (const float*)d_in[7];
    const float* b_r    = (const float*)d_in[8];
    const float* W_u    = (const float*)d_in[9];
    const float* b_u    = (const float*)d_in[10];
    const float* W_c    = (const float*)d_in[11];
    const float* b_c    = (const float*)d_in[12];
    const float* W_diff = (const float*)d_in[13];
    const float* b_diff = (const float*)d_in[14];
    const float* W_dec  = (const float*)d_in[15];
    const float* b_dec  = (const float*)d_in[16];
    float* out = (float*)d_out;
    const int* src = ei;
    const int* dst = ei + Ee;

    const dim3 cvtB(32, 8);
    const int TC_SMEM = 81920;
    cudaFuncSetAttribute((const void*)k_tc,
                         cudaFuncAttributeMaxDynamicSharedMemorySize, TC_SMEM);
    cudaFuncSetAttribute((const void*)k_gateTC,
                         cudaFuncAttributeMaxDynamicSharedMemorySize, TC_SMEM);

    const int4 aAll = make_int4(PB_AF, PB_AB, PB_AF2, PB_AF2 + 2);
    const COffs4 cDummy = {};

    // host-side pointers into __device__ arrays
    __nv_bfloat16* wtDev = nullptr;
    cudaGetSymbolAddress((void**)&wtDev, g_w);

    // supports + encoder + conversions
    k_rowsum<<<1024, 256>>>(adj);
    k_colsum<<<4, 256>>>(adj);
    k_norm<<<4096, 256>>>(adj);
    k_encoder<<<dim3(1024, 12), 256>>>(x, W_enc, b_enc, emb);
    k_cvtA<<<dim3(4096, 2), 256>>>(O_ADJF, PB_AF);
    k_cvtT<<<dim3(32, 32, 12), cvtB>>>(O_XENC, NS, PB_XET, 2);
    k_cvtT<<<dim3(32, 32, 2), cvtB>>>(O_ADJF, NS, PB_AFT, 2);
    k_cvtW<<<128, 256>>>(W_r, 0);
    k_cvtW<<<128, 256>>>(W_u, 1);
    k_cvtW<<<128, 256>>>(W_c, 2);

    // A^2 (fp32 via split GEMM), then convert to bf16 hi/lo
    {
        COffs4 c2; c2.o[0] = O_A2; c2.o[1] = O_A2 + NS; c2.o[2] = 0; c2.o[3] = 0;
        k_tc<<<dim3(8, 8, 2), 256, TC_SMEM>>>(make_int4(PB_AF, PB_AB, 0, 0),
                                              1, PB_AFT, 0, 2, c2, 0, -1);
        k_cvtA<<<dim3(4096, 2), 256>>>(O_A2, PB_AF2);
    }

    // all 48 x-side hops in ONE launch -> bf16 chunk planes
    k_tc<<<dim3(8, 8, 48), 256, TC_SMEM>>>(aAll, 12, PB_XET, 2, 0, cDummy, 0, PB_XC);

    // GRU scan
    k_zero<<<4096, 256>>>(O_H);
    k_zerob<<<1024, 256>>>(PB_HT);
    for (int t = 0; t < 12; t++) {
        k_tc<<<dim3(8, 8, 4), 256, TC_SMEM>>>(aAll, 1, PB_HT, 0, 0, cDummy, 0, PB_HB);
        CP8 cg;
        cg.p[0] = PB_XC + t * 2;        cg.p[1] = PB_HB + 0;
        cg.p[2] = PB_XC + (24 + t) * 2; cg.p[3] = PB_HB + 4;
        cg.p[4] = PB_XC + (12 + t) * 2; cg.p[5] = PB_HB + 2;
        cg.p[6] = PB_XC + (36 + t) * 2; cg.p[7] = PB_HB + 6;
        k_gateTC<<<128, 256, TC_SMEM>>>(cg, wtDev, b_r, wtDev + 2 * 32768, b_u, 1, PB_RHT);
        k_tc<<<dim3(8, 8, 4), 256, TC_SMEM>>>(aAll, 1, PB_RHT, 0, 0, cDummy, 0, PB_RB);
        CP8 cc = cg;
        cc.p[1] = PB_RB + 0; cc.p[3] = PB_RB + 4;
        cc.p[5] = PB_RB + 2; cc.p[7] = PB_RB + 6;
        k_gateTC<<<128, 256, TC_SMEM>>>(cc, wtDev + 4 * 32768, b_c, wtDev + 4 * 32768, b_c, 2, PB_HT);
    }

    // sparse DiffConv readout (fp32 planes)
    k_gather<<<1024, 256>>>(dst, src, ew, O_H, O_F1);
    k_gather<<<1024, 256>>>(dst, src, ew, O_F1, O_F2);
    k_gather<<<1024, 256>>>(src, dst, ew, O_H, O_B1);
    k_gather<<<1024, 256>>>(src, dst, ew, O_B1, O_B2);
    COffs cz;
    cz.o[0] = O_H; cz.o[1] = O_F1; cz.o[2] = O_F2; cz.o[3] = O_B1; cz.o[4] = O_B2;
    cz.o[5] = cz.o[6] = cz.o[7] = O_H;
    k_gate<<<256, 256>>>(cz, 5, W_diff, b_diff, O_Z);

    // decoder
    k_dec<<<16384, 96>>>(W_dec, b_dec, out);
}